// round 1
// baseline (speedup 1.0000x reference)
#include <cuda_runtime.h>
#include <math.h>

// ---------------------------------------------------------------------------
// HierarchicalModelFusion: two stacked MHAs.
//   Stage A: batch=S*B=8192, L=M=4, H=1024, nh=8, dh=128, then mean over M
//   Stage B: batch=B=128,   L=S=64, H=1024, nh=8, dh=128
// All heavy lifting = 4 GEMMs of the form C = A * W^T + bias (both K-major).
// ---------------------------------------------------------------------------

#define H_DIM 1024
#define KD    1024

// Scratch (device globals; no allocation allowed in kernel_launch)
__device__ float g_qkv1[(size_t)32768 * 3072];  // stage-A qkv
__device__ float g_mean[(size_t)8192 * 1024];   // mean-over-models attn out
__device__ float g_seq [(size_t)8192 * 1024];   // [B,S,H] seq (+pos)
__device__ float g_qkv2[(size_t)8192 * 3072];   // stage-B qkv
__device__ float g_att2[(size_t)8192 * 1024];   // stage-B attn out

// ---------------------------------------------------------------------------
// SGEMM: C[n, j] = sum_k A[n,k] * B[j,k] + bias[j]   (128x128x16 tile, 8x8/thr)
// MAPA: 0 = A row-major [M,K]; 1 = gather rows from hidden[S,M,B,1,H]
// EPI : 0 = plain store at row n
//       1 = row n = s*128+b  -> store at row b*64+s, add pos_enc[s, :]
//       2 = row n = b*64+s   -> store at row s*128+b
// ---------------------------------------------------------------------------
template <int MAPA, int EPI>
__global__ void __launch_bounds__(256) sgemm_kernel(
    const float* __restrict__ A, const float* __restrict__ B,
    const float* __restrict__ bias, const float* __restrict__ pos,
    float* __restrict__ C, int N)
{
    __shared__ float As[16][132];
    __shared__ float Bs[16][132];

    const int tid = threadIdx.x;
    const int bm = blockIdx.y, bn = blockIdx.x;
    const int lr = tid >> 2;            // 0..63 row-within-tile loader
    const int lk = (tid & 3) << 2;      // 0,4,8,12 k-offset loader

    // A row offsets (with optional gather from hidden[S,M,B,1,H])
    size_t aoff0, aoff1;
    {
        int n0 = bm * 128 + lr;
        int n1 = n0 + 64;
        if (MAPA == 0) {
            aoff0 = (size_t)n0 * KD;
            aoff1 = (size_t)n1 * KD;
        } else {
            // n = (s*128 + b)*4 + m  ->  hidden offset ((s*4+m)*128 + b)*1024
            int s0 = n0 >> 9, r0 = n0 & 511, b0 = r0 >> 2, m0 = r0 & 3;
            aoff0 = ((size_t)((s0 * 4 + m0) * 128 + b0)) << 10;
            int s1 = n1 >> 9, r1 = n1 & 511, b1 = r1 >> 2, m1 = r1 & 3;
            aoff1 = ((size_t)((s1 * 4 + m1) * 128 + b1)) << 10;
        }
        aoff0 += lk;
        aoff1 += lk;
    }
    size_t boff0 = (size_t)(bn * 128 + lr) * KD + lk;
    size_t boff1 = boff0 + (size_t)64 * KD;

    float acc[8][8];
#pragma unroll
    for (int i = 0; i < 8; i++)
#pragma unroll
        for (int j = 0; j < 8; j++) acc[i][j] = 0.0f;

    const int ty = (tid >> 4) << 3;   // 0..120 step 8
    const int tx = (tid & 15) << 3;   // 0..120 step 8

    for (int k0 = 0; k0 < KD; k0 += 16) {
        float4 a0 = *(const float4*)(A + aoff0 + k0);
        float4 a1 = *(const float4*)(A + aoff1 + k0);
        float4 b0 = *(const float4*)(B + boff0 + k0);
        float4 b1 = *(const float4*)(B + boff1 + k0);

        As[lk + 0][lr] = a0.x; As[lk + 1][lr] = a0.y;
        As[lk + 2][lr] = a0.z; As[lk + 3][lr] = a0.w;
        As[lk + 0][lr + 64] = a1.x; As[lk + 1][lr + 64] = a1.y;
        As[lk + 2][lr + 64] = a1.z; As[lk + 3][lr + 64] = a1.w;
        Bs[lk + 0][lr] = b0.x; Bs[lk + 1][lr] = b0.y;
        Bs[lk + 2][lr] = b0.z; Bs[lk + 3][lr] = b0.w;
        Bs[lk + 0][lr + 64] = b1.x; Bs[lk + 1][lr + 64] = b1.y;
        Bs[lk + 2][lr + 64] = b1.z; Bs[lk + 3][lr + 64] = b1.w;
        __syncthreads();

#pragma unroll
        for (int kk = 0; kk < 16; kk++) {
            float ar[8], br[8];
            *(float4*)(ar)     = *(const float4*)&As[kk][ty];
            *(float4*)(ar + 4) = *(const float4*)&As[kk][ty + 4];
            *(float4*)(br)     = *(const float4*)&Bs[kk][tx];
            *(float4*)(br + 4) = *(const float4*)&Bs[kk][tx + 4];
#pragma unroll
            for (int i = 0; i < 8; i++)
#pragma unroll
                for (int j = 0; j < 8; j++)
                    acc[i][j] += ar[i] * br[j];
        }
        __syncthreads();
    }

    // Epilogue with bias (+ optional transpose scatter / pos_enc)
    const int gcb = bn * 128 + tx;
#pragma unroll
    for (int i = 0; i < 8; i++) {
        int gr = bm * 128 + ty + i;
        size_t coff;
        int srow = 0;
        if (EPI == 0) {
            coff = (size_t)gr * N;
        } else if (EPI == 1) {
            srow = gr >> 7;                 // s
            int b = gr & 127;               // b
            coff = (size_t)(b * 64 + srow) * N;
        } else {
            int b = gr >> 6, s = gr & 63;
            coff = (size_t)(s * 128 + b) * N;
        }
#pragma unroll
        for (int j = 0; j < 8; j++) {
            float v = acc[i][j] + bias[gcb + j];
            if (EPI == 1) v += pos[(size_t)srow * 1024 + gcb + j];
            C[coff + gcb + j] = v;
        }
    }
}

// ---------------------------------------------------------------------------
// Attention stage A: L=4, dh=128. One warp per (sb, head), fully in registers.
// Also folds the mean over the M=4 models (legal since out-proj is linear).
// ---------------------------------------------------------------------------
__global__ void __launch_bounds__(256) attn1_kernel(
    const float* __restrict__ qkv, float* __restrict__ meanout)
{
    const int sb = blockIdx.x;           // 0..8191
    const int w  = threadIdx.x >> 5;     // head 0..7
    const int l  = threadIdx.x & 31;

    const float* base = qkv + (size_t)sb * 4 * 3072 + w * 128 + l * 4;

    float4 q[4], k[4], v[4];
#pragma unroll
    for (int i = 0; i < 4; i++) {
        q[i] = *(const float4*)(base + (size_t)i * 3072);
        k[i] = *(const float4*)(base + (size_t)i * 3072 + 1024);
        v[i] = *(const float4*)(base + (size_t)i * 3072 + 2048);
    }

    float sc[4][4];
#pragma unroll
    for (int i = 0; i < 4; i++)
#pragma unroll
        for (int j = 0; j < 4; j++)
            sc[i][j] = q[i].x * k[j].x + q[i].y * k[j].y +
                       q[i].z * k[j].z + q[i].w * k[j].w;

#pragma unroll
    for (int o = 16; o > 0; o >>= 1)
#pragma unroll
        for (int i = 0; i < 4; i++)
#pragma unroll
            for (int j = 0; j < 4; j++)
                sc[i][j] += __shfl_xor_sync(0xffffffffu, sc[i][j], o);

    const float scale = 0.08838834764831845f;  // 1/sqrt(128)
    float wj[4] = {0.f, 0.f, 0.f, 0.f};
#pragma unroll
    for (int i = 0; i < 4; i++) {
        float s0 = sc[i][0] * scale, s1 = sc[i][1] * scale;
        float s2 = sc[i][2] * scale, s3 = sc[i][3] * scale;
        float m = fmaxf(fmaxf(s0, s1), fmaxf(s2, s3));
        float e0 = __expf(s0 - m), e1 = __expf(s1 - m);
        float e2 = __expf(s2 - m), e3 = __expf(s3 - m);
        float inv = 0.25f / (e0 + e1 + e2 + e3);   // 0.25 = mean over M
        wj[0] += e0 * inv; wj[1] += e1 * inv;
        wj[2] += e2 * inv; wj[3] += e3 * inv;
    }

    float4 o = {0.f, 0.f, 0.f, 0.f};
#pragma unroll
    for (int j = 0; j < 4; j++) {
        o.x += wj[j] * v[j].x; o.y += wj[j] * v[j].y;
        o.z += wj[j] * v[j].z; o.w += wj[j] * v[j].w;
    }
    *(float4*)(meanout + (size_t)sb * 1024 + w * 128 + l * 4) = o;
}

// ---------------------------------------------------------------------------
// Attention stage B: L=64, dh=128. One CTA per (b, head); q/k/v in smem.
// ---------------------------------------------------------------------------
#define A2_LD 129
#define A2_SMEM ((3 * 64 * A2_LD + 64 * 65) * 4)

__global__ void __launch_bounds__(256) attn2_kernel(
    const float* __restrict__ qkv2, float* __restrict__ out)
{
    extern __shared__ float sm[];
    float* qs = sm;
    float* ks = qs + 64 * A2_LD;
    float* vs = ks + 64 * A2_LD;
    float* ps = vs + 64 * A2_LD;     // 64 x 65 score rows

    const int b = blockIdx.x >> 3;
    const int h = blockIdx.x & 7;
    const int tid = threadIdx.x;

    // Load q,k,v [64][128] tiles
    for (int p = tid; p < 64 * 32; p += 256) {
        int r = p >> 5, c4 = (p & 31) << 2;
        const float* src = qkv2 + (size_t)(b * 64 + r) * 3072 + h * 128 + c4;
        float4 xq = *(const float4*)(src);
        float4 xk = *(const float4*)(src + 1024);
        float4 xv = *(const float4*)(src + 2048);
        float* qd = qs + r * A2_LD + c4;
        float* kd = ks + r * A2_LD + c4;
        float* vd = vs + r * A2_LD + c4;
        qd[0] = xq.x; qd[1] = xq.y; qd[2] = xq.z; qd[3] = xq.w;
        kd[0] = xk.x; kd[1] = xk.y; kd[2] = xk.z; kd[3] = xk.w;
        vd[0] = xv.x; vd[1] = xv.y; vd[2] = xv.z; vd[3] = xv.w;
    }
    __syncthreads();

    const int w = tid >> 5, l = tid & 31;
    const float scale = 0.08838834764831845f;

    // Scores: warp w owns query rows [w*8, w*8+8)
    for (int r = 0; r < 8; r++) {
        int i = w * 8 + r;
        const float* qp = qs + i * A2_LD;
        const float* k0 = ks + l * A2_LD;
        const float* k1 = ks + (l + 32) * A2_LD;
        float s0 = 0.f, s1 = 0.f;
#pragma unroll 8
        for (int d = 0; d < 128; d++) {
            float qv = qp[d];
            s0 += qv * k0[d];
            s1 += qv * k1[d];
        }
        ps[i * 65 + l]      = s0 * scale;
        ps[i * 65 + l + 32] = s1 * scale;
    }
    __syncwarp();

    // Softmax per row (same warp owns its rows)
    for (int r = 0; r < 8; r++) {
        int i = w * 8 + r;
        float a0 = ps[i * 65 + l], a1 = ps[i * 65 + l + 32];
        float m = fmaxf(a0, a1);
#pragma unroll
        for (int o = 16; o > 0; o >>= 1)
            m = fmaxf(m, __shfl_xor_sync(0xffffffffu, m, o));
        float e0 = __expf(a0 - m), e1 = __expf(a1 - m);
        float s = e0 + e1;
#pragma unroll
        for (int o = 16; o > 0; o >>= 1)
            s += __shfl_xor_sync(0xffffffffu, s, o);
        float inv = 1.0f / s;
        ps[i * 65 + l]      = e0 * inv;
        ps[i * 65 + l + 32] = e1 * inv;
    }
    __syncwarp();

    // out[i][d] = sum_j p[i][j] * v[j][d]
    for (int r = 0; r < 8; r++) {
        int i = w * 8 + r;
        const float* pr = ps + i * 65;
        float a0 = 0.f, a1 = 0.f, a2 = 0.f, a3 = 0.f;
#pragma unroll 4
        for (int j = 0; j < 64; j++) {
            float pj = pr[j];
            const float* vp = vs + j * A2_LD;
            a0 += pj * vp[l];
            a1 += pj * vp[l + 32];
            a2 += pj * vp[l + 64];
            a3 += pj * vp[l + 96];
        }
        float* op = out + (size_t)(b * 64 + i) * 1024 + h * 128;
        op[l] = a0; op[l + 32] = a1; op[l + 64] = a2; op[l + 96] = a3;
    }
}

// ---------------------------------------------------------------------------
extern "C" void kernel_launch(void* const* d_in, const int* in_sizes, int n_in,
                              void* d_out, int out_size)
{
    (void)in_sizes; (void)n_in; (void)out_size;
    const float* hid      = (const float*)d_in[0];
    const float* mf_in_w  = (const float*)d_in[1];
    const float* mf_in_b  = (const float*)d_in[2];
    const float* mf_out_w = (const float*)d_in[3];
    const float* mf_out_b = (const float*)d_in[4];
    const float* sf_in_w  = (const float*)d_in[5];
    const float* sf_in_b  = (const float*)d_in[6];
    const float* sf_out_w = (const float*)d_in[7];
    const float* sf_out_b = (const float*)d_in[8];
    const float* pos_enc  = (const float*)d_in[9];
    float* out = (float*)d_out;

    float *qkv1, *meanb, *seq, *qkv2, *att2;
    cudaGetSymbolAddress((void**)&qkv1, g_qkv1);
    cudaGetSymbolAddress((void**)&meanb, g_mean);
    cudaGetSymbolAddress((void**)&seq,  g_seq);
    cudaGetSymbolAddress((void**)&qkv2, g_qkv2);
    cudaGetSymbolAddress((void**)&att2, g_att2);

    cudaFuncSetAttribute(attn2_kernel,
                         cudaFuncAttributeMaxDynamicSharedMemorySize, A2_SMEM);

    // Stage A: qkv = gather(hidden) @ mf_in_w^T + b     [32768 x 3072]
    sgemm_kernel<1, 0><<<dim3(24, 256), 256>>>(hid, mf_in_w, mf_in_b, nullptr,
                                               qkv1, 3072);
    // Stage A attention (L=4) + mean over models        [8192 x 1024]
    attn1_kernel<<<8192, 256>>>(qkv1, meanb);
    // Stage A out-proj + transpose to [B,S,H] + pos_enc [8192 x 1024]
    sgemm_kernel<0, 1><<<dim3(8, 64), 256>>>(meanb, mf_out_w, mf_out_b, pos_enc,
                                             seq, 1024);
    // Stage B: qkv2 = seq @ sf_in_w^T + b               [8192 x 3072]
    sgemm_kernel<0, 0><<<dim3(24, 64), 256>>>(seq, sf_in_w, sf_in_b, nullptr,
                                              qkv2, 3072);
    // Stage B attention (L=64)                          [8192 x 1024]
    attn2_kernel<<<1024, 256, A2_SMEM>>>(qkv2, att2);
    // Stage B out-proj + transpose to [S,B,1,H]         -> d_out
    sgemm_kernel<0, 2><<<dim3(8, 64), 256>>>(att2, sf_out_w, sf_out_b, nullptr,
                                             out, 1024);
}

// round 3
// speedup vs baseline: 1.9614x; 1.9614x over previous
#include <cuda_runtime.h>
#include <cstdint>
#include <math.h>

// ---------------------------------------------------------------------------
// HierarchicalModelFusion — mma.sync tf32 edition (plain sm_100 target:
// tcgen05 unavailable, legacy HMMA path is).
//   4 GEMMs (C = A @ W^T + bias, K=1024) via mma.sync.m16n8k8 tf32.
//   CTA tile 128x128, K chunks of 32, double-buffered smem.
//   Attention stages in fp32 CUDA-core code (tiny fraction of FLOPs).
// ---------------------------------------------------------------------------

#define KD 1024

// Scratch (device globals; no allocation allowed)
__device__ float g_qkv1[(size_t)32768 * 3072];
__device__ float g_mean[(size_t)8192 * 1024];
__device__ float g_seq [(size_t)8192 * 1024];
__device__ float g_qkv2[(size_t)8192 * 3072];
__device__ float g_att2[(size_t)8192 * 1024];

__device__ __forceinline__ uint32_t cvt_tf32(float x) {
    uint32_t r;
    asm("cvt.rna.tf32.f32 %0, %1;" : "=r"(r) : "f"(x));
    return r;
}

__device__ __forceinline__ void mma_tf32(float* d, const uint32_t* a,
                                         const uint32_t* b) {
    asm volatile(
        "mma.sync.aligned.m16n8k8.row.col.f32.tf32.tf32.f32 "
        "{%0,%1,%2,%3}, {%4,%5,%6,%7}, {%8,%9}, {%0,%1,%2,%3};"
        : "+f"(d[0]), "+f"(d[1]), "+f"(d[2]), "+f"(d[3])
        : "r"(a[0]), "r"(a[1]), "r"(a[2]), "r"(a[3]),
          "r"(b[0]), "r"(b[1]));
}

// ---------------------------------------------------------------------------
// Tensor GEMM: C[n,j] = sum_k A[n,k]*W[j,k] + bias[j]
// Tile 128x128, K chunks of 32, double buffered. 8 warps (2x4), warp 64x32.
// Smem layout per matrix: [128 rows][36 floats]; within each k8 block the 8
// k-columns are stored in order 0,4,1,5,2,6,3,7 so that the mma fragment
// pairs (k, k+4) are contiguous -> ld.shared.v2.
// MAPA: 0 = A row-major [M,1024]; 1 = gather from hidden[S,M,B,1,H]
// EPI : 0 plain; 1 transpose to [B,S,H] + pos_enc; 2 transpose to [S,B,H]
// ---------------------------------------------------------------------------
#define RP 36                    // row pitch (floats)
#define MAT_F (128 * RP)         // floats per matrix tile
#define BUF_F (2 * MAT_F)        // floats per buffer (A + B)
#define SMEM_BYTES (2 * BUF_F * 4)

template <int MAPA, int EPI>
__global__ void __launch_bounds__(256) tgemm(
    const float* __restrict__ A, const float* __restrict__ W,
    const float* __restrict__ bias, const float* __restrict__ pos,
    float* __restrict__ C, int N)
{
    extern __shared__ float sm[];
    const int tid = threadIdx.x, wid = tid >> 5, lane = tid & 31;
    const int bm = blockIdx.y, bn = blockIdx.x;

    // ---- loader setup: 4 float4 per thread per matrix per chunk ----
    size_t arow[4], brow[4];
    int sbase[4];
#pragma unroll
    for (int i = 0; i < 4; i++) {
        int idx = tid + 256 * i;      // 0..1023
        int r = idx >> 3, k4 = idx & 7;
        size_t ro;
        int n = bm * 128 + r;
        if (MAPA == 0) ro = (size_t)n * KD;
        else {
            // n = (s*128 + b)*4 + m -> hidden offset ((s*4+m)*128 + b)*1024
            int s = n >> 9, rr = n & 511, b = rr >> 2, m = rr & 3;
            ro = ((size_t)((s * 4 + m) * 128 + b)) << 10;
        }
        arow[i] = ro + (size_t)(k4 << 2);
        brow[i] = (size_t)(bn * 128 + r) * KD + (size_t)(k4 << 2);
        // permuted store base: row*RP + k8*8 + (k4&1); elements go at +2*j
        sbase[i] = r * RP + ((k4 >> 1) << 3) + (k4 & 1);
    }

    float4 aval[4], bval[4];

    auto load_g = [&](int k0) {
#pragma unroll
        for (int i = 0; i < 4; i++) {
            aval[i] = *(const float4*)(A + arow[i] + k0);
            bval[i] = *(const float4*)(W + brow[i] + k0);
        }
    };
    auto store_s = [&](int p) {
        float* ab = sm + p * BUF_F;
        float* bb = ab + MAT_F;
#pragma unroll
        for (int i = 0; i < 4; i++) {
            int s = sbase[i];
            ab[s + 0] = __uint_as_float(cvt_tf32(aval[i].x));
            ab[s + 2] = __uint_as_float(cvt_tf32(aval[i].y));
            ab[s + 4] = __uint_as_float(cvt_tf32(aval[i].z));
            ab[s + 6] = __uint_as_float(cvt_tf32(aval[i].w));
            bb[s + 0] = __uint_as_float(cvt_tf32(bval[i].x));
            bb[s + 2] = __uint_as_float(cvt_tf32(bval[i].y));
            bb[s + 4] = __uint_as_float(cvt_tf32(bval[i].z));
            bb[s + 6] = __uint_as_float(cvt_tf32(bval[i].w));
        }
    };

    // ---- compute setup ----
    const int wm = (wid & 1) << 6;    // 0,64
    const int wn = (wid >> 1) << 3;   // 0..24 step 8 -> *4 = col base/4? no:
    const int wnc = (wid >> 1) << 5;  // warp col base: 0,32,64,96
    (void)wn;
    const int grp = lane >> 2, tig = lane & 3;

    float acc[4][4][4];
#pragma unroll
    for (int mt = 0; mt < 4; mt++)
#pragma unroll
        for (int nt = 0; nt < 4; nt++)
#pragma unroll
            for (int e = 0; e < 4; e++) acc[mt][nt][e] = 0.0f;

    auto compute = [&](int p) {
        const float* ab = sm + p * BUF_F;
        const float* bb = ab + MAT_F;
#pragma unroll
        for (int ks = 0; ks < 4; ks++) {
            uint32_t afr[4][4], bfr[4][2];
#pragma unroll
            for (int mt = 0; mt < 4; mt++) {
                int r0 = wm + mt * 16 + grp;
                float2 lo = *(const float2*)(ab + r0 * RP + ks * 8 + 2 * tig);
                float2 hi = *(const float2*)(ab + (r0 + 8) * RP + ks * 8 + 2 * tig);
                afr[mt][0] = __float_as_uint(lo.x);
                afr[mt][2] = __float_as_uint(lo.y);
                afr[mt][1] = __float_as_uint(hi.x);
                afr[mt][3] = __float_as_uint(hi.y);
            }
#pragma unroll
            for (int nt = 0; nt < 4; nt++) {
                int n0 = wnc + nt * 8 + grp;
                float2 bp = *(const float2*)(bb + n0 * RP + ks * 8 + 2 * tig);
                bfr[nt][0] = __float_as_uint(bp.x);
                bfr[nt][1] = __float_as_uint(bp.y);
            }
#pragma unroll
            for (int mt = 0; mt < 4; mt++)
#pragma unroll
                for (int nt = 0; nt < 4; nt++)
                    mma_tf32(acc[mt][nt], afr[mt], bfr[nt]);
        }
    };

    // ---- pipeline: 32 K-chunks, double buffered ----
    load_g(0);
    store_s(0);
    __syncthreads();
#pragma unroll 1
    for (int c = 0; c < 32; c++) {
        const int p = c & 1;
        if (c < 31) load_g((c + 1) << 5);
        compute(p);
        __syncthreads();
        if (c < 31) {
            store_s(p ^ 1);
            __syncthreads();
        }
    }

    // ---- epilogue: bias (+ pos_enc / transposes), float2 stores ----
#pragma unroll
    for (int mt = 0; mt < 4; mt++) {
        int gr0 = bm * 128 + wm + mt * 16 + grp;
#pragma unroll
        for (int h = 0; h < 2; h++) {
            int gr = gr0 + 8 * h;
            size_t coff;
            int srow = 0;
            if (EPI == 0) {
                coff = (size_t)gr * N;
            } else if (EPI == 1) {
                srow = gr >> 7;
                int b = gr & 127;
                coff = (size_t)(b * 64 + srow) * N;
            } else {
                int b = gr >> 6, s = gr & 63;
                coff = (size_t)(s * 128 + b) * N;
            }
#pragma unroll
            for (int nt = 0; nt < 4; nt++) {
                int gc = bn * 128 + wnc + nt * 8 + 2 * tig;
                float2 b2 = *(const float2*)(bias + gc);
                float vx = acc[mt][nt][2 * h]     + b2.x;
                float vy = acc[mt][nt][2 * h + 1] + b2.y;
                if (EPI == 1) {
                    float2 p2 = *(const float2*)(pos + (size_t)srow * 1024 + gc);
                    vx += p2.x; vy += p2.y;
                }
                float2 o; o.x = vx; o.y = vy;
                *(float2*)(C + coff + gc) = o;
            }
        }
    }
}

// ---------------------------------------------------------------------------
// Attention stage A: L=4, dh=128. One warp per (sb, head), registers only.
// Folds the mean over M=4 models (out-proj is linear).
// ---------------------------------------------------------------------------
__global__ void __launch_bounds__(256) attn1_kernel(
    const float* __restrict__ qkv, float* __restrict__ meanout)
{
    const int sb = blockIdx.x;
    const int w  = threadIdx.x >> 5;
    const int l  = threadIdx.x & 31;

    const float* base = qkv + (size_t)sb * 4 * 3072 + w * 128 + l * 4;

    float4 q[4], k[4], v[4];
#pragma unroll
    for (int i = 0; i < 4; i++) {
        q[i] = *(const float4*)(base + (size_t)i * 3072);
        k[i] = *(const float4*)(base + (size_t)i * 3072 + 1024);
        v[i] = *(const float4*)(base + (size_t)i * 3072 + 2048);
    }

    float sc[4][4];
#pragma unroll
    for (int i = 0; i < 4; i++)
#pragma unroll
        for (int j = 0; j < 4; j++)
            sc[i][j] = q[i].x * k[j].x + q[i].y * k[j].y +
                       q[i].z * k[j].z + q[i].w * k[j].w;

#pragma unroll
    for (int o = 16; o > 0; o >>= 1)
#pragma unroll
        for (int i = 0; i < 4; i++)
#pragma unroll
            for (int j = 0; j < 4; j++)
                sc[i][j] += __shfl_xor_sync(0xffffffffu, sc[i][j], o);

    const float scale = 0.08838834764831845f;
    float wj[4] = {0.f, 0.f, 0.f, 0.f};
#pragma unroll
    for (int i = 0; i < 4; i++) {
        float s0 = sc[i][0] * scale, s1 = sc[i][1] * scale;
        float s2 = sc[i][2] * scale, s3 = sc[i][3] * scale;
        float m = fmaxf(fmaxf(s0, s1), fmaxf(s2, s3));
        float e0 = __expf(s0 - m), e1 = __expf(s1 - m);
        float e2 = __expf(s2 - m), e3 = __expf(s3 - m);
        float inv = 0.25f / (e0 + e1 + e2 + e3);
        wj[0] += e0 * inv; wj[1] += e1 * inv;
        wj[2] += e2 * inv; wj[3] += e3 * inv;
    }

    float4 o = {0.f, 0.f, 0.f, 0.f};
#pragma unroll
    for (int j = 0; j < 4; j++) {
        o.x += wj[j] * v[j].x; o.y += wj[j] * v[j].y;
        o.z += wj[j] * v[j].z; o.w += wj[j] * v[j].w;
    }
    *(float4*)(meanout + (size_t)sb * 1024 + w * 128 + l * 4) = o;
}

// ---------------------------------------------------------------------------
// Attention stage B: L=64, dh=128. One CTA per (b, head); q/k/v in smem.
// ---------------------------------------------------------------------------
#define A2_LD 129
#define A2_SMEM ((3 * 64 * A2_LD + 64 * 65) * 4)

__global__ void __launch_bounds__(256) attn2_kernel(
    const float* __restrict__ qkv2, float* __restrict__ out)
{
    extern __shared__ float smf[];
    float* qs = smf;
    float* ks = qs + 64 * A2_LD;
    float* vs = ks + 64 * A2_LD;
    float* ps = vs + 64 * A2_LD;

    const int b = blockIdx.x >> 3;
    const int h = blockIdx.x & 7;
    const int tid = threadIdx.x;

    for (int p = tid; p < 64 * 32; p += 256) {
        int r = p >> 5, c4 = (p & 31) << 2;
        const float* src = qkv2 + (size_t)(b * 64 + r) * 3072 + h * 128 + c4;
        float4 xq = *(const float4*)(src);
        float4 xk = *(const float4*)(src + 1024);
        float4 xv = *(const float4*)(src + 2048);
        float* qd = qs + r * A2_LD + c4;
        float* kd = ks + r * A2_LD + c4;
        float* vd = vs + r * A2_LD + c4;
        qd[0] = xq.x; qd[1] = xq.y; qd[2] = xq.z; qd[3] = xq.w;
        kd[0] = xk.x; kd[1] = xk.y; kd[2] = xk.z; kd[3] = xk.w;
        vd[0] = xv.x; vd[1] = xv.y; vd[2] = xv.z; vd[3] = xv.w;
    }
    __syncthreads();

    const int w = tid >> 5, l = tid & 31;
    const float scale = 0.08838834764831845f;

    for (int r = 0; r < 8; r++) {
        int i = w * 8 + r;
        const float* qp = qs + i * A2_LD;
        const float* k0 = ks + l * A2_LD;
        const float* k1 = ks + (l + 32) * A2_LD;
        float s0 = 0.f, s1 = 0.f;
#pragma unroll 8
        for (int d = 0; d < 128; d++) {
            float qv = qp[d];
            s0 += qv * k0[d];
            s1 += qv * k1[d];
        }
        ps[i * 65 + l]      = s0 * scale;
        ps[i * 65 + l + 32] = s1 * scale;
    }
    __syncwarp();

    for (int r = 0; r < 8; r++) {
        int i = w * 8 + r;
        float a0 = ps[i * 65 + l], a1 = ps[i * 65 + l + 32];
        float m = fmaxf(a0, a1);
#pragma unroll
        for (int o = 16; o > 0; o >>= 1)
            m = fmaxf(m, __shfl_xor_sync(0xffffffffu, m, o));
        float e0 = __expf(a0 - m), e1 = __expf(a1 - m);
        float s = e0 + e1;
#pragma unroll
        for (int o = 16; o > 0; o >>= 1)
            s += __shfl_xor_sync(0xffffffffu, s, o);
        float inv = 1.0f / s;
        ps[i * 65 + l]      = e0 * inv;
        ps[i * 65 + l + 32] = e1 * inv;
    }
    __syncwarp();

    for (int r = 0; r < 8; r++) {
        int i = w * 8 + r;
        const float* pr = ps + i * 65;
        float a0 = 0.f, a1 = 0.f, a2 = 0.f, a3 = 0.f;
#pragma unroll 4
        for (int j = 0; j < 64; j++) {
            float pj = pr[j];
            const float* vp = vs + j * A2_LD;
            a0 += pj * vp[l];
            a1 += pj * vp[l + 32];
            a2 += pj * vp[l + 64];
            a3 += pj * vp[l + 96];
        }
        float* op = out + (size_t)(b * 64 + i) * 1024 + h * 128;
        op[l] = a0; op[l + 32] = a1; op[l + 64] = a2; op[l + 96] = a3;
    }
}

// ---------------------------------------------------------------------------
extern "C" void kernel_launch(void* const* d_in, const int* in_sizes, int n_in,
                              void* d_out, int out_size)
{
    (void)in_sizes; (void)n_in; (void)out_size;
    const float* hid      = (const float*)d_in[0];
    const float* mf_in_w  = (const float*)d_in[1];
    const float* mf_in_b  = (const float*)d_in[2];
    const float* mf_out_w = (const float*)d_in[3];
    const float* mf_out_b = (const float*)d_in[4];
    const float* sf_in_w  = (const float*)d_in[5];
    const float* sf_in_b  = (const float*)d_in[6];
    const float* sf_out_w = (const float*)d_in[7];
    const float* sf_out_b = (const float*)d_in[8];
    const float* pos_enc  = (const float*)d_in[9];
    float* out = (float*)d_out;

    float *qkv1, *meanb, *seq, *qkv2, *att2;
    cudaGetSymbolAddress((void**)&qkv1, g_qkv1);
    cudaGetSymbolAddress((void**)&meanb, g_mean);
    cudaGetSymbolAddress((void**)&seq,  g_seq);
    cudaGetSymbolAddress((void**)&qkv2, g_qkv2);
    cudaGetSymbolAddress((void**)&att2, g_att2);

    cudaFuncSetAttribute(tgemm<1, 0>,
        cudaFuncAttributeMaxDynamicSharedMemorySize, SMEM_BYTES);
    cudaFuncSetAttribute(tgemm<0, 0>,
        cudaFuncAttributeMaxDynamicSharedMemorySize, SMEM_BYTES);
    cudaFuncSetAttribute(tgemm<0, 1>,
        cudaFuncAttributeMaxDynamicSharedMemorySize, SMEM_BYTES);
    cudaFuncSetAttribute(tgemm<0, 2>,
        cudaFuncAttributeMaxDynamicSharedMemorySize, SMEM_BYTES);
    cudaFuncSetAttribute(attn2_kernel,
        cudaFuncAttributeMaxDynamicSharedMemorySize, A2_SMEM);

    // Stage A: qkv1 = gather(hidden) @ mf_in_w^T + b     [32768 x 3072]
    tgemm<1, 0><<<dim3(24, 256), 256, SMEM_BYTES>>>(hid, mf_in_w, mf_in_b,
                                                    nullptr, qkv1, 3072);
    // Stage A attention (L=4) + mean over models         [8192 x 1024]
    attn1_kernel<<<8192, 256>>>(qkv1, meanb);
    // Stage A out-proj + transpose to [B,S,H] + pos_enc  [8192 x 1024]
    tgemm<0, 1><<<dim3(8, 64), 256, SMEM_BYTES>>>(meanb, mf_out_w, mf_out_b,
                                                  pos_enc, seq, 1024);
    // Stage B: qkv2 = seq @ sf_in_w^T + b                [8192 x 3072]
    tgemm<0, 0><<<dim3(24, 64), 256, SMEM_BYTES>>>(seq, sf_in_w, sf_in_b,
                                                   nullptr, qkv2, 3072);
    // Stage B attention (L=64)                           [8192 x 1024]
    attn2_kernel<<<1024, 256, A2_SMEM>>>(qkv2, att2);
    // Stage B out-proj + transpose to [S,B,1,H]          -> d_out
    tgemm<0, 2><<<dim3(8, 64), 256, SMEM_BYTES>>>(att2, sf_out_w, sf_out_b,
                                                  nullptr, out, 1024);
}

// round 4
// speedup vs baseline: 3.6484x; 1.8601x over previous
#include <cuda_runtime.h>
#include <cstdint>
#include <math.h>

// ---------------------------------------------------------------------------
// HierarchicalModelFusion — tf32 mma.sync, fragment-ordered operands,
// cp.async 3-stage pipelined GEMMs.
//
// All GEMM operands (A activations, B weights) are stored in GLOBAL memory in
// mma-fragment order, pre-rounded to tf32 (rna). The GEMM kernel is then a
// pure cp.async -> conflict-free LDS.128 -> HMMA pipeline.
//
// A-frag layout for [M,1024] operand (consumed as mma A, 16x8 blocks):
//   chunk(mt,kt) = contiguous 4096 floats at (mt*32+kt)*4096
//   within chunk: block (kb0..3, mb0..7) at (kb*8+mb)*128 floats
//   within block: lane = (ri%8)*4 + (ci%4), 4 floats per lane:
//     pos0 = (ri<8,ci<4)=a0, pos1 = (ri>=8,ci<4)=a1, pos2 = a2, pos3 = a3
// B-frag layout for [N,1024] weight (consumed as mma B, 16-col groups):
//   chunk(nt,kt) = contiguous 8192 floats at (nt*32+kt)*8192
//   block (kb0..3, g0..15) at (kb*16+g)*128 floats
//   lane = (ni%8)*4 + (ci%4); pos = (ci>=4?1:0) + 2*(ni>=8?1:0)
//     => lane regs = {b0,b1 of even n8 sub-block, b0,b1 of odd}
// ---------------------------------------------------------------------------

#define KD 1024

// Scratch (device globals; no allocation allowed)
__device__ __align__(256) float g_hidA[(size_t)32768 * 1024];  // hidden, A-frag
__device__ __align__(256) float g_wmin[(size_t)3072 * 1024];   // mf_in_w, B-frag
__device__ __align__(256) float g_wmout[(size_t)1024 * 1024];  // mf_out_w, B-frag
__device__ __align__(256) float g_wsin[(size_t)3072 * 1024];   // sf_in_w, B-frag
__device__ __align__(256) float g_wsout[(size_t)1024 * 1024];  // sf_out_w, B-frag
__device__ __align__(256) float g_qkv1[(size_t)32768 * 3072];  // normal layout
__device__ __align__(256) float g_mean[(size_t)8192 * 1024];   // A-frag
__device__ __align__(256) float g_seq [(size_t)8192 * 1024];   // A-frag
__device__ __align__(256) float g_qkv2[(size_t)8192 * 3072];   // normal layout
__device__ __align__(256) float g_att2[(size_t)8192 * 1024];   // A-frag

__device__ __forceinline__ float cvtf(float x) {
    uint32_t r;
    asm("cvt.rna.tf32.f32 %0, %1;" : "=r"(r) : "f"(x));
    return __uint_as_float(r);
}

__device__ __forceinline__ size_t afrag_idx(int r, int c) {
    int mt = r >> 7, mb = (r >> 4) & 7, ri = r & 15;
    int kt = c >> 5, kb = (c >> 3) & 3, ci = c & 7;
    return ((size_t)(mt * 32 + kt) << 12) + ((kb * 8 + mb) << 7)
         + (((ri & 7) * 4 + (ci & 3)) << 2) + ((ri >> 3) & 1) + (((ci >> 2) & 1) << 1);
}

__device__ __forceinline__ void mma_tf32(float* d, uint32_t a0, uint32_t a1,
                                         uint32_t a2, uint32_t a3,
                                         uint32_t b0, uint32_t b1) {
    asm volatile(
        "mma.sync.aligned.m16n8k8.row.col.f32.tf32.tf32.f32 "
        "{%0,%1,%2,%3}, {%4,%5,%6,%7}, {%8,%9}, {%0,%1,%2,%3};"
        : "+f"(d[0]), "+f"(d[1]), "+f"(d[2]), "+f"(d[3])
        : "r"(a0), "r"(a1), "r"(a2), "r"(a3), "r"(b0), "r"(b1));
}

__device__ __forceinline__ void cp16(uint32_t dst, const void* src) {
    asm volatile("cp.async.cg.shared.global [%0], [%1], 16;"
                 :: "r"(dst), "l"(src));
}
__device__ __forceinline__ uint32_t smem_u32(const void* p) {
    uint32_t a;
    asm("{ .reg .u64 t; cvta.to.shared.u64 t, %1; cvt.u32.u64 %0, t; }"
        : "=r"(a) : "l"(p));
    return a;
}

// ---------------------------------------------------------------------------
// Prepass: hidden[S,M,B,1,H] -> gathered [32768,1024] A-frag, tf32-rounded.
// One CTA per 16 output rows; smem transpose for coalesced read AND write.
// ---------------------------------------------------------------------------
#define CONV_SMEM (16 * 1028 * 4)
__global__ void __launch_bounds__(256) conv_hidden(
    const float* __restrict__ hid, float* __restrict__ Af)
{
    extern __shared__ float tile[];    // [16][1028]
    const int tid = threadIdx.x, nb = blockIdx.x;   // 2048 blocks
#pragma unroll
    for (int i = 0; i < 16; i++) {
        int idx = tid + 256 * i;
        int r = idx >> 8, c4 = idx & 255;
        int n = nb * 16 + r;
        int s = n >> 9, b = (n >> 2) & 127, m = n & 3;
        float4 v = *(const float4*)(hid + (((size_t)((s * 4 + m) * 128 + b)) << 10)
                                        + (c4 << 2));
        *(float4*)&tile[r * 1028 + c4 * 4] = v;
    }
    __syncthreads();
    const int mt = nb >> 3, mb = nb & 7;
#pragma unroll
    for (int j = 0; j < 16; j++) {
        int g = tid + 256 * j;
        int kt = g >> 7, rr = g & 127, kb = rr >> 5, ln = rr & 31;
        int ri = ln >> 2, ci = ln & 3;
        int c = kt * 32 + kb * 8 + ci;
        float4 o;
        o.x = cvtf(tile[ri * 1028 + c]);
        o.y = cvtf(tile[(ri + 8) * 1028 + c]);
        o.z = cvtf(tile[ri * 1028 + c + 4]);
        o.w = cvtf(tile[(ri + 8) * 1028 + c + 4]);
        *(float4*)(Af + ((size_t)(mt * 32 + kt) << 12) + ((kb * 8 + mb) << 7)
                      + (ln << 2)) = o;
    }
}

// Prepass: weight [N,1024] -> B-frag, tf32-rounded. One CTA per 16 rows.
__global__ void __launch_bounds__(256) conv_w(
    const float* __restrict__ W, float* __restrict__ Bf)
{
    extern __shared__ float tile[];    // [16][1028]
    const int tid = threadIdx.x, gid = blockIdx.x;
#pragma unroll
    for (int i = 0; i < 16; i++) {
        int idx = tid + 256 * i;
        int r = idx >> 8, c4 = idx & 255;
        float4 v = *(const float4*)(W + ((size_t)(gid * 16 + r) << 10) + (c4 << 2));
        *(float4*)&tile[r * 1028 + c4 * 4] = v;
    }
    __syncthreads();
    const int nt = gid >> 4, gblk = gid & 15;
#pragma unroll
    for (int j = 0; j < 16; j++) {
        int g = tid + 256 * j;
        int kt = g >> 7, rr = g & 127, kb = rr >> 5, ln = rr & 31;
        int ni = ln >> 2, ci = ln & 3;
        int c = kt * 32 + kb * 8 + ci;
        float4 o;
        o.x = cvtf(tile[ni * 1028 + c]);          // b0 sub0
        o.y = cvtf(tile[ni * 1028 + c + 4]);      // b1 sub0
        o.z = cvtf(tile[(ni + 8) * 1028 + c]);    // b0 sub1
        o.w = cvtf(tile[(ni + 8) * 1028 + c + 4]);// b1 sub1
        *(float4*)(Bf + ((size_t)(nt * 32 + kt) << 13) + ((kb * 16 + gblk) << 7)
                      + (ln << 2)) = o;
    }
}

// ---------------------------------------------------------------------------
// GEMM: C[n,j] = sum_k A[n,k]*W[j,k] + bias[j]. CTA 128x256, warp 64x64,
// 3-stage cp.async pipeline, K chunks of 32.
// EPI: 0 = normal store; 1 = transpose to [B,S,H] + pos_enc, A-frag store
//      (tf32-rounded); 2 = transpose to [S,B,H], normal store.
// ---------------------------------------------------------------------------
#define STAGE_B 49152                    // 16KB A + 32KB B per stage
#define STAGE_F 12288
#define GSMEM   (3 * STAGE_B)

template <int EPI>
__global__ void __launch_bounds__(256, 1) tgemm2(
    const float* __restrict__ Af, const float* __restrict__ Bf,
    const float* __restrict__ bias, const float* __restrict__ pos,
    float* __restrict__ C, int N)
{
    extern __shared__ char smem_raw[];
    float* smf = (float*)smem_raw;
    const uint32_t sb = smem_u32(smem_raw);
    const int tid = threadIdx.x, wid = tid >> 5, lane = tid & 31;
    const int bm = blockIdx.y, bn = blockIdx.x;

    const float4* Af4 = (const float4*)Af + ((size_t)bm << 15) + tid; // bm*32*1024
    const float4* Bf4 = (const float4*)Bf + ((size_t)bn << 16) + tid; // bn*32*2048
    const uint32_t adst = sb + tid * 16;
    const uint32_t bdst = sb + 16384 + tid * 16;

    auto issue = [&](int kt, int s) {
        const float4* a = Af4 + (kt << 10);
        uint32_t ad = adst + s * STAGE_B;
#pragma unroll
        for (int i = 0; i < 4; i++) cp16(ad + i * 4096, a + i * 256);
        const float4* b = Bf4 + (kt << 11);
        uint32_t bd = bdst + s * STAGE_B;
#pragma unroll
        for (int i = 0; i < 8; i++) cp16(bd + i * 4096, b + i * 256);
        asm volatile("cp.async.commit_group;" ::: "memory");
    };

    float acc[4][8][4];
#pragma unroll
    for (int mt = 0; mt < 4; mt++)
#pragma unroll
        for (int nt = 0; nt < 8; nt++)
#pragma unroll
            for (int e = 0; e < 4; e++) acc[mt][nt][e] = 0.0f;

    const int wmb = (wid & 1) * 4;     // A block row base (x16 rows)
    const int wnb = (wid >> 1) * 4;    // B group base (x16 cols)

    issue(0, 0);
    issue(1, 1);

#pragma unroll 1
    for (int c = 0; c < 32; c++) {
        if (c < 31) asm volatile("cp.async.wait_group 1;" ::: "memory");
        else        asm volatile("cp.async.wait_group 0;" ::: "memory");
        __syncthreads();
        if (c + 2 < 32) issue(c + 2, (c + 2) % 3);

        const float* sA = smf + (c % 3) * STAGE_F;
        const float* sB = sA + 4096;
#pragma unroll
        for (int kb = 0; kb < 4; kb++) {
            uint4 af[4];
#pragma unroll
            for (int mt = 0; mt < 4; mt++)
                af[mt] = *(const uint4*)(sA + ((kb * 8 + wmb + mt) << 7) + (lane << 2));
#pragma unroll
            for (int gt = 0; gt < 4; gt++) {
                uint4 bb = *(const uint4*)(sB + ((kb * 16 + wnb + gt) << 7) + (lane << 2));
#pragma unroll
                for (int mt = 0; mt < 4; mt++) {
                    mma_tf32(acc[mt][2 * gt],     af[mt].x, af[mt].y, af[mt].z, af[mt].w,
                             bb.x, bb.y);
                    mma_tf32(acc[mt][2 * gt + 1], af[mt].x, af[mt].y, af[mt].z, af[mt].w,
                             bb.z, bb.w);
                }
            }
        }
    }

    // ---- epilogue ----
    const int grp = lane >> 2, tig = lane & 3;
    const int wm = (wid & 1) * 64, wn = (wid >> 1) * 64;
#pragma unroll
    for (int mt = 0; mt < 4; mt++) {
#pragma unroll
        for (int h = 0; h < 2; h++) {
            int gr = bm * 128 + wm + mt * 16 + grp + 8 * h;
#pragma unroll
            for (int nt = 0; nt < 8; nt++) {
                int gc = bn * 256 + wn + nt * 8 + 2 * tig;
                float2 b2 = *(const float2*)(bias + gc);
                float v0 = acc[mt][nt][2 * h]     + b2.x;
                float v1 = acc[mt][nt][2 * h + 1] + b2.y;
                if (EPI == 0) {
                    float2 o; o.x = v0; o.y = v1;
                    *(float2*)(C + (size_t)gr * N + gc) = o;
                } else if (EPI == 1) {
                    int srow = gr >> 7, b = gr & 127;
                    float2 p2 = *(const float2*)(pos + (size_t)srow * 1024 + gc);
                    int r_out = b * 64 + srow;
                    C[afrag_idx(r_out, gc)]     = cvtf(v0 + p2.x);
                    C[afrag_idx(r_out, gc + 1)] = cvtf(v1 + p2.y);
                } else {
                    int b = gr >> 6, s = gr & 63;
                    float2 o; o.x = v0; o.y = v1;
                    *(float2*)(C + (size_t)(s * 128 + b) * N + gc) = o;
                }
            }
        }
    }
}

// ---------------------------------------------------------------------------
// Attention stage A: L=4, dh=128. One warp per (sb, head), registers only.
// Folds mean over M=4 models; writes A-frag tf32-rounded output.
// ---------------------------------------------------------------------------
__global__ void __launch_bounds__(256) attn1_kernel(
    const float* __restrict__ qkv, float* __restrict__ meanout)
{
    const int sb = blockIdx.x;
    const int w  = threadIdx.x >> 5;
    const int l  = threadIdx.x & 31;

    const float* base = qkv + (size_t)sb * 4 * 3072 + w * 128 + l * 4;

    float4 q[4], k[4], v[4];
#pragma unroll
    for (int i = 0; i < 4; i++) {
        q[i] = *(const float4*)(base + (size_t)i * 3072);
        k[i] = *(const float4*)(base + (size_t)i * 3072 + 1024);
        v[i] = *(const float4*)(base + (size_t)i * 3072 + 2048);
    }

    float sc[4][4];
#pragma unroll
    for (int i = 0; i < 4; i++)
#pragma unroll
        for (int j = 0; j < 4; j++)
            sc[i][j] = q[i].x * k[j].x + q[i].y * k[j].y +
                       q[i].z * k[j].z + q[i].w * k[j].w;

#pragma unroll
    for (int o = 16; o > 0; o >>= 1)
#pragma unroll
        for (int i = 0; i < 4; i++)
#pragma unroll
            for (int j = 0; j < 4; j++)
                sc[i][j] += __shfl_xor_sync(0xffffffffu, sc[i][j], o);

    const float scale = 0.08838834764831845f;
    float wj[4] = {0.f, 0.f, 0.f, 0.f};
#pragma unroll
    for (int i = 0; i < 4; i++) {
        float s0 = sc[i][0] * scale, s1 = sc[i][1] * scale;
        float s2 = sc[i][2] * scale, s3 = sc[i][3] * scale;
        float m = fmaxf(fmaxf(s0, s1), fmaxf(s2, s3));
        float e0 = __expf(s0 - m), e1 = __expf(s1 - m);
        float e2 = __expf(s2 - m), e3 = __expf(s3 - m);
        float inv = 0.25f / (e0 + e1 + e2 + e3);
        wj[0] += e0 * inv; wj[1] += e1 * inv;
        wj[2] += e2 * inv; wj[3] += e3 * inv;
    }

    float4 o = {0.f, 0.f, 0.f, 0.f};
#pragma unroll
    for (int j = 0; j < 4; j++) {
        o.x += wj[j] * v[j].x; o.y += wj[j] * v[j].y;
        o.z += wj[j] * v[j].z; o.w += wj[j] * v[j].w;
    }
    int cb = w * 128 + l * 4;
    meanout[afrag_idx(sb, cb + 0)] = cvtf(o.x);
    meanout[afrag_idx(sb, cb + 1)] = cvtf(o.y);
    meanout[afrag_idx(sb, cb + 2)] = cvtf(o.z);
    meanout[afrag_idx(sb, cb + 3)] = cvtf(o.w);
}

// ---------------------------------------------------------------------------
// Attention stage B: L=64, dh=128. One CTA per (b, head); q/k/v in smem.
// Writes A-frag tf32-rounded output.
// ---------------------------------------------------------------------------
#define A2_LD 129
#define A2_SMEM ((3 * 64 * A2_LD + 64 * 65) * 4)

__global__ void __launch_bounds__(256) attn2_kernel(
    const float* __restrict__ qkv2, float* __restrict__ out)
{
    extern __shared__ float smf[];
    float* qs = smf;
    float* ks = qs + 64 * A2_LD;
    float* vs = ks + 64 * A2_LD;
    float* ps = vs + 64 * A2_LD;

    const int b = blockIdx.x >> 3;
    const int h = blockIdx.x & 7;
    const int tid = threadIdx.x;

    for (int p = tid; p < 64 * 32; p += 256) {
        int r = p >> 5, c4 = (p & 31) << 2;
        const float* src = qkv2 + (size_t)(b * 64 + r) * 3072 + h * 128 + c4;
        float4 xq = *(const float4*)(src);
        float4 xk = *(const float4*)(src + 1024);
        float4 xv = *(const float4*)(src + 2048);
        float* qd = qs + r * A2_LD + c4;
        float* kd = ks + r * A2_LD + c4;
        float* vd = vs + r * A2_LD + c4;
        qd[0] = xq.x; qd[1] = xq.y; qd[2] = xq.z; qd[3] = xq.w;
        kd[0] = xk.x; kd[1] = xk.y; kd[2] = xk.z; kd[3] = xk.w;
        vd[0] = xv.x; vd[1] = xv.y; vd[2] = xv.z; vd[3] = xv.w;
    }
    __syncthreads();

    const int w = tid >> 5, l = tid & 31;
    const float scale = 0.08838834764831845f;

    for (int r = 0; r < 8; r++) {
        int i = w * 8 + r;
        const float* qp = qs + i * A2_LD;
        const float* k0 = ks + l * A2_LD;
        const float* k1 = ks + (l + 32) * A2_LD;
        float s0 = 0.f, s1 = 0.f;
#pragma unroll 8
        for (int d = 0; d < 128; d++) {
            float qv = qp[d];
            s0 += qv * k0[d];
            s1 += qv * k1[d];
        }
        ps[i * 65 + l]      = s0 * scale;
        ps[i * 65 + l + 32] = s1 * scale;
    }
    __syncwarp();

    for (int r = 0; r < 8; r++) {
        int i = w * 8 + r;
        float a0 = ps[i * 65 + l], a1 = ps[i * 65 + l + 32];
        float m = fmaxf(a0, a1);
#pragma unroll
        for (int o = 16; o > 0; o >>= 1)
            m = fmaxf(m, __shfl_xor_sync(0xffffffffu, m, o));
        float e0 = __expf(a0 - m), e1 = __expf(a1 - m);
        float s = e0 + e1;
#pragma unroll
        for (int o = 16; o > 0; o >>= 1)
            s += __shfl_xor_sync(0xffffffffu, s, o);
        float inv = 1.0f / s;
        ps[i * 65 + l]      = e0 * inv;
        ps[i * 65 + l + 32] = e1 * inv;
    }
    __syncwarp();

    for (int r = 0; r < 8; r++) {
        int i = w * 8 + r;
        const float* pr = ps + i * 65;
        float a0 = 0.f, a1 = 0.f, a2 = 0.f, a3 = 0.f;
#pragma unroll 4
        for (int j = 0; j < 64; j++) {
            float pj = pr[j];
            const float* vp = vs + j * A2_LD;
            a0 += pj * vp[l];
            a1 += pj * vp[l + 32];
            a2 += pj * vp[l + 64];
            a3 += pj * vp[l + 96];
        }
        int row = b * 64 + i, cb = h * 128 + l;
        out[afrag_idx(row, cb)]      = cvtf(a0);
        out[afrag_idx(row, cb + 32)] = cvtf(a1);
        out[afrag_idx(row, cb + 64)] = cvtf(a2);
        out[afrag_idx(row, cb + 96)] = cvtf(a3);
    }
}

// ---------------------------------------------------------------------------
extern "C" void kernel_launch(void* const* d_in, const int* in_sizes, int n_in,
                              void* d_out, int out_size)
{
    (void)in_sizes; (void)n_in; (void)out_size;
    const float* hid      = (const float*)d_in[0];
    const float* mf_in_w  = (const float*)d_in[1];
    const float* mf_in_b  = (const float*)d_in[2];
    const float* mf_out_w = (const float*)d_in[3];
    const float* mf_out_b = (const float*)d_in[4];
    const float* sf_in_w  = (const float*)d_in[5];
    const float* sf_in_b  = (const float*)d_in[6];
    const float* sf_out_w = (const float*)d_in[7];
    const float* sf_out_b = (const float*)d_in[8];
    const float* pos_enc  = (const float*)d_in[9];
    float* out = (float*)d_out;

    float *hidA, *wmin, *wmout, *wsin, *wsout, *qkv1, *meanb, *seq, *qkv2, *att2;
    cudaGetSymbolAddress((void**)&hidA,  g_hidA);
    cudaGetSymbolAddress((void**)&wmin,  g_wmin);
    cudaGetSymbolAddress((void**)&wmout, g_wmout);
    cudaGetSymbolAddress((void**)&wsin,  g_wsin);
    cudaGetSymbolAddress((void**)&wsout, g_wsout);
    cudaGetSymbolAddress((void**)&qkv1,  g_qkv1);
    cudaGetSymbolAddress((void**)&meanb, g_mean);
    cudaGetSymbolAddress((void**)&seq,   g_seq);
    cudaGetSymbolAddress((void**)&qkv2,  g_qkv2);
    cudaGetSymbolAddress((void**)&att2,  g_att2);

    cudaFuncSetAttribute(conv_hidden,
        cudaFuncAttributeMaxDynamicSharedMemorySize, CONV_SMEM);
    cudaFuncSetAttribute(conv_w,
        cudaFuncAttributeMaxDynamicSharedMemorySize, CONV_SMEM);
    cudaFuncSetAttribute(tgemm2<0>,
        cudaFuncAttributeMaxDynamicSharedMemorySize, GSMEM);
    cudaFuncSetAttribute(tgemm2<1>,
        cudaFuncAttributeMaxDynamicSharedMemorySize, GSMEM);
    cudaFuncSetAttribute(tgemm2<2>,
        cudaFuncAttributeMaxDynamicSharedMemorySize, GSMEM);
    cudaFuncSetAttribute(attn2_kernel,
        cudaFuncAttributeMaxDynamicSharedMemorySize, A2_SMEM);

    // ---- prepass: fragment-order + tf32-round all GEMM inputs ----
    conv_hidden<<<2048, 256, CONV_SMEM>>>(hid, hidA);
    conv_w<<<192, 256, CONV_SMEM>>>(mf_in_w, wmin);
    conv_w<<< 64, 256, CONV_SMEM>>>(mf_out_w, wmout);
    conv_w<<<192, 256, CONV_SMEM>>>(sf_in_w, wsin);
    conv_w<<< 64, 256, CONV_SMEM>>>(sf_out_w, wsout);

    // Stage A: qkv1 = hidden @ mf_in_w^T + b              [32768 x 3072]
    tgemm2<0><<<dim3(12, 256), 256, GSMEM>>>(hidA, wmin, mf_in_b, nullptr,
                                             qkv1, 3072);
    // Stage A attention (L=4) + mean over models          -> A-frag
    attn1_kernel<<<8192, 256>>>(qkv1, meanb);
    // Stage A out-proj + transpose to [B,S,H] + pos_enc   -> A-frag
    tgemm2<1><<<dim3(4, 64), 256, GSMEM>>>(meanb, wmout, mf_out_b, pos_enc,
                                           seq, 1024);
    // Stage B: qkv2 = seq @ sf_in_w^T + b                 [8192 x 3072]
    tgemm2<0><<<dim3(12, 64), 256, GSMEM>>>(seq, wsin, sf_in_b, nullptr,
                                            qkv2, 3072);
    // Stage B attention (L=64)                            -> A-frag
    attn2_kernel<<<1024, 256, A2_SMEM>>>(qkv2, att2);
    // Stage B out-proj + transpose to [S,B,1,H]           -> d_out
    tgemm2<2><<<dim3(4, 64), 256, GSMEM>>>(att2, wsout, sf_out_b, nullptr,
                                           out, 1024);
}

// round 6
// speedup vs baseline: 6.1314x; 1.6806x over previous
#include <cuda_runtime.h>
#include <cuda_fp16.h>
#include <cstdint>
#include <math.h>

// ---------------------------------------------------------------------------
// HierarchicalModelFusion — fp16 mma.sync (m16n8k16, f32 accum),
// fragment-ordered packed-half operands, cp.async 3-stage pipeline.
// fp16 mantissa == tf32 mantissa (11 bits) -> same accuracy, 2x rate,
// half the bytes everywhere.
// ---------------------------------------------------------------------------

#define KD 1024

// Scratch (device globals)
__device__ __align__(256) __half g_hidA[(size_t)32768 * 1024];  // A-frag
__device__ __align__(256) __half g_wmin[(size_t)3072 * 1024];   // B-frag
__device__ __align__(256) __half g_wmout[(size_t)1024 * 1024];  // B-frag
__device__ __align__(256) __half g_wsin[(size_t)3072 * 1024];   // B-frag
__device__ __align__(256) __half g_wsout[(size_t)1024 * 1024];  // B-frag
__device__ __align__(256) __half g_qkv1[(size_t)32768 * 3072];  // row layout
__device__ __align__(256) __half g_mean[(size_t)8192 * 1024];   // A-frag
__device__ __align__(256) __half g_seq [(size_t)8192 * 1024];   // A-frag
__device__ __align__(256) __half g_qkv2[(size_t)8192 * 3072];   // row layout
__device__ __align__(256) __half g_att2[(size_t)8192 * 1024];   // A-frag

__device__ __forceinline__ uint32_t h2_u32(__half2 h) {
    return *reinterpret_cast<uint32_t*>(&h);
}

// A-frag (m16n8k16 A operand) index for a [rows,1024] half matrix.
// chunk(mt = r>>7, kt = c>>6) of 8192 halves; block(kb = (c>>4)&3, mb=(r>>4)&7)
// of 256 halves; lane = (r&7)*4 + ((c&7)>>1); idx = (c&1)+2*((r>>3)&1)+4*((c>>3)&1)
__device__ __forceinline__ size_t afrag_h(int r, int c) {
    int mt = r >> 7, mb = (r >> 4) & 7, ri = r & 15;
    int kt = c >> 6, kb = (c >> 4) & 3, ci = c & 15;
    int lane = (ri & 7) * 4 + ((ci & 7) >> 1);
    int idx = (ci & 1) + 2 * ((ri >> 3) & 1) + 4 * ((ci >> 3) & 1);
    return ((size_t)(mt * 16 + kt) << 13) + ((kb * 8 + mb) << 8) + (lane << 3) + idx;
}

__device__ __forceinline__ void mma_f16(float* d, uint32_t a0, uint32_t a1,
                                        uint32_t a2, uint32_t a3,
                                        uint32_t b0, uint32_t b1) {
    asm volatile(
        "mma.sync.aligned.m16n8k16.row.col.f32.f16.f16.f32 "
        "{%0,%1,%2,%3}, {%4,%5,%6,%7}, {%8,%9}, {%0,%1,%2,%3};"
        : "+f"(d[0]), "+f"(d[1]), "+f"(d[2]), "+f"(d[3])
        : "r"(a0), "r"(a1), "r"(a2), "r"(a3), "r"(b0), "r"(b1));
}

__device__ __forceinline__ void cp16(uint32_t dst, const void* src) {
    asm volatile("cp.async.cg.shared.global [%0], [%1], 16;"
                 :: "r"(dst), "l"(src));
}
__device__ __forceinline__ uint32_t smem_u32(const void* p) {
    uint32_t a;
    asm("{ .reg .u64 t; cvta.to.shared.u64 t, %1; cvt.u32.u64 %0, t; }"
        : "=r"(a) : "l"(p));
    return a;
}

// ---------------------------------------------------------------------------
// Prepass: hidden[S,M,B,1,H] -> gathered A-frag halves. CTA per 16 rows.
// ---------------------------------------------------------------------------
#define CONV_SMEM (16 * 1028 * 4)
__global__ void __launch_bounds__(256) conv_hidden(
    const float* __restrict__ hid, __half* __restrict__ Af)
{
    extern __shared__ float tile[];    // [16][1028]
    const int tid = threadIdx.x, nb = blockIdx.x;   // 2048 blocks
#pragma unroll
    for (int i = 0; i < 16; i++) {
        int idx = tid + 256 * i;
        int r = idx >> 8, c4 = idx & 255;
        int n = nb * 16 + r;
        int s = n >> 9, b = (n >> 2) & 127, m = n & 3;
        float4 v = *(const float4*)(hid + (((size_t)((s * 4 + m) * 128 + b)) << 10)
                                        + (c4 << 2));
        *(float4*)&tile[r * 1028 + c4 * 4] = v;
    }
    __syncthreads();
    const int mt = nb >> 3, mb = nb & 7;
#pragma unroll
    for (int j = 0; j < 8; j++) {
        int g = tid + 256 * j;              // 0..2047
        int kt = g >> 7, rr = g & 127, kb = rr >> 5, ln = rr & 31;
        int grp = ln >> 2, tig = ln & 3;
        int c0 = kt * 64 + kb * 16 + 2 * tig;
        __half2 p0 = __floats2half2_rn(tile[grp * 1028 + c0],
                                       tile[grp * 1028 + c0 + 1]);
        __half2 p1 = __floats2half2_rn(tile[(grp + 8) * 1028 + c0],
                                       tile[(grp + 8) * 1028 + c0 + 1]);
        __half2 p2 = __floats2half2_rn(tile[grp * 1028 + c0 + 8],
                                       tile[grp * 1028 + c0 + 9]);
        __half2 p3 = __floats2half2_rn(tile[(grp + 8) * 1028 + c0 + 8],
                                       tile[(grp + 8) * 1028 + c0 + 9]);
        uint4 o;
        o.x = h2_u32(p0); o.y = h2_u32(p1);
        o.z = h2_u32(p2); o.w = h2_u32(p3);
        *(uint4*)(Af + ((size_t)(mt * 16 + kt) << 13) + ((kb * 8 + mb) << 8)
                     + (ln << 3)) = o;
    }
}

// Prepass: weight [N,1024] -> B-frag halves. CTA per 16 rows (cols of C).
__global__ void __launch_bounds__(256) conv_w(
    const float* __restrict__ W, __half* __restrict__ Bf)
{
    extern __shared__ float tile[];    // [16][1028]
    const int tid = threadIdx.x, gid = blockIdx.x;
#pragma unroll
    for (int i = 0; i < 16; i++) {
        int idx = tid + 256 * i;
        int r = idx >> 8, c4 = idx & 255;
        float4 v = *(const float4*)(W + ((size_t)(gid * 16 + r) << 10) + (c4 << 2));
        *(float4*)&tile[r * 1028 + c4 * 4] = v;
    }
    __syncthreads();
    const int nt = gid >> 4, gblk = gid & 15;
#pragma unroll
    for (int j = 0; j < 8; j++) {
        int g = tid + 256 * j;
        int kt = g >> 7, rr = g & 127, kb = rr >> 5, ln = rr & 31;
        int grp = ln >> 2, tig = ln & 3;
        int c0 = kt * 64 + kb * 16 + 2 * tig;
        __half2 p0 = __floats2half2_rn(tile[grp * 1028 + c0],
                                       tile[grp * 1028 + c0 + 1]);
        __half2 p1 = __floats2half2_rn(tile[grp * 1028 + c0 + 8],
                                       tile[grp * 1028 + c0 + 9]);
        __half2 p2 = __floats2half2_rn(tile[(grp + 8) * 1028 + c0],
                                       tile[(grp + 8) * 1028 + c0 + 1]);
        __half2 p3 = __floats2half2_rn(tile[(grp + 8) * 1028 + c0 + 8],
                                       tile[(grp + 8) * 1028 + c0 + 9]);
        uint4 o;
        o.x = h2_u32(p0); o.y = h2_u32(p1);
        o.z = h2_u32(p2); o.w = h2_u32(p3);
        *(uint4*)(Bf + ((size_t)(nt * 16 + kt) << 14) + ((kb * 16 + gblk) << 8)
                     + (ln << 3)) = o;
    }
}

// ---------------------------------------------------------------------------
// GEMM: C = A @ W^T + bias. CTA 128x256, warp 64x64, K chunks of 64 halves,
// 3-stage cp.async. EPI: 0 = half row-layout store; 1 = transpose [B,S,H] +
// pos_enc -> half A-frag; 2 = transpose [S,B,H] -> float store (final out).
// ---------------------------------------------------------------------------
#define STAGE_B 49152                  // 16KB A + 32KB B halves per stage
#define GSMEM   (3 * STAGE_B)

template <int EPI>
__global__ void __launch_bounds__(256, 1) tgemm2(
    const __half* __restrict__ Af, const __half* __restrict__ Bf,
    const float* __restrict__ bias, const float* __restrict__ pos,
    void* __restrict__ Cv, int N)
{
    extern __shared__ char smem_raw[];
    const uint32_t sb = smem_u32(smem_raw);
    const int tid = threadIdx.x, wid = tid >> 5, lane = tid & 31;
    const int bm = blockIdx.y, bn = blockIdx.x;

    const uint4* Af4 = (const uint4*)Af + ((size_t)bm << 14) + tid; // bm*16*1024
    const uint4* Bf4 = (const uint4*)Bf + ((size_t)bn << 15) + tid; // bn*16*2048
    const uint32_t adst = sb + tid * 16;
    const uint32_t bdst = sb + 16384 + tid * 16;

    auto issue = [&](int kt, int s) {
        const uint4* a = Af4 + (kt << 10);
        uint32_t ad = adst + s * STAGE_B;
#pragma unroll
        for (int i = 0; i < 4; i++) cp16(ad + i * 4096, a + i * 256);
        const uint4* b = Bf4 + (kt << 11);
        uint32_t bd = bdst + s * STAGE_B;
#pragma unroll
        for (int i = 0; i < 8; i++) cp16(bd + i * 4096, b + i * 256);
        asm volatile("cp.async.commit_group;" ::: "memory");
    };

    float acc[4][8][4];
#pragma unroll
    for (int mt = 0; mt < 4; mt++)
#pragma unroll
        for (int nt = 0; nt < 8; nt++)
#pragma unroll
            for (int e = 0; e < 4; e++) acc[mt][nt][e] = 0.0f;

    const int wmb = (wid & 1) * 4;     // A 16-row block base
    const int wnb = (wid >> 1) * 4;    // B 16-col group base

    issue(0, 0);
    issue(1, 1);

#pragma unroll 1
    for (int c = 0; c < 16; c++) {
        if (c < 15) asm volatile("cp.async.wait_group 1;" ::: "memory");
        else        asm volatile("cp.async.wait_group 0;" ::: "memory");
        __syncthreads();
        if (c + 2 < 16) issue(c + 2, (c + 2) % 3);

        const __half* sA = (const __half*)(smem_raw + (c % 3) * STAGE_B);
        const __half* sB = sA + 8192;
#pragma unroll
        for (int kb = 0; kb < 4; kb++) {
            uint4 af[4];
#pragma unroll
            for (int mt = 0; mt < 4; mt++)
                af[mt] = *(const uint4*)(sA + ((kb * 8 + wmb + mt) << 8) + (lane << 3));
#pragma unroll
            for (int gt = 0; gt < 4; gt++) {
                uint4 bb = *(const uint4*)(sB + ((kb * 16 + wnb + gt) << 8) + (lane << 3));
#pragma unroll
                for (int mt = 0; mt < 4; mt++) {
                    mma_f16(acc[mt][2 * gt],     af[mt].x, af[mt].y, af[mt].z, af[mt].w,
                            bb.x, bb.y);
                    mma_f16(acc[mt][2 * gt + 1], af[mt].x, af[mt].y, af[mt].z, af[mt].w,
                            bb.z, bb.w);
                }
            }
        }
    }

    // ---- epilogue ----
    const int grp = lane >> 2, tig = lane & 3;
    const int wm = (wid & 1) * 64, wn = (wid >> 1) * 64;
#pragma unroll
    for (int mt = 0; mt < 4; mt++) {
#pragma unroll
        for (int h = 0; h < 2; h++) {
            int gr = bm * 128 + wm + mt * 16 + grp + 8 * h;
#pragma unroll
            for (int nt = 0; nt < 8; nt++) {
                int gc = bn * 256 + wn + nt * 8 + 2 * tig;
                float2 b2 = *(const float2*)(bias + gc);
                float v0 = acc[mt][nt][2 * h]     + b2.x;
                float v1 = acc[mt][nt][2 * h + 1] + b2.y;
                if (EPI == 0) {
                    __half* C = (__half*)Cv;
                    *(__half2*)(C + (size_t)gr * N + gc) = __floats2half2_rn(v0, v1);
                } else if (EPI == 1) {
                    __half* C = (__half*)Cv;
                    int srow = gr >> 7, b = gr & 127;
                    float2 p2 = *(const float2*)(pos + (size_t)srow * 1024 + gc);
                    int r_out = b * 64 + srow;
                    *(__half2*)(C + afrag_h(r_out, gc)) =
                        __floats2half2_rn(v0 + p2.x, v1 + p2.y);
                } else {
                    float* C = (float*)Cv;
                    int b = gr >> 6, s = gr & 63;
                    float2 o; o.x = v0; o.y = v1;
                    *(float2*)(C + (size_t)(s * 128 + b) * N + gc) = o;
                }
            }
        }
    }
}

// ---------------------------------------------------------------------------
// Attention stage A: L=4, dh=128, half qkv input. One warp per (sb, head).
// Folds mean over M=4 models; writes half A-frag output.
// ---------------------------------------------------------------------------
__device__ __forceinline__ float4 ld_half4(const __half* p) {
    uint2 raw = *(const uint2*)p;
    float2 a = __half22float2(*(__half2*)&raw.x);
    float2 b = __half22float2(*(__half2*)&raw.y);
    return make_float4(a.x, a.y, b.x, b.y);
}

__global__ void __launch_bounds__(256) attn1_kernel(
    const __half* __restrict__ qkv, __half* __restrict__ meanout)
{
    const int sb = blockIdx.x;
    const int w  = threadIdx.x >> 5;
    const int l  = threadIdx.x & 31;

    const __half* base = qkv + (size_t)sb * 4 * 3072 + w * 128 + l * 4;

    float4 q[4], k[4], v[4];
#pragma unroll
    for (int i = 0; i < 4; i++) {
        q[i] = ld_half4(base + (size_t)i * 3072);
        k[i] = ld_half4(base + (size_t)i * 3072 + 1024);
        v[i] = ld_half4(base + (size_t)i * 3072 + 2048);
    }

    float sc[4][4];
#pragma unroll
    for (int i = 0; i < 4; i++)
#pragma unroll
        for (int j = 0; j < 4; j++)
            sc[i][j] = q[i].x * k[j].x + q[i].y * k[j].y +
                       q[i].z * k[j].z + q[i].w * k[j].w;

#pragma unroll
    for (int o = 16; o > 0; o >>= 1)
#pragma unroll
        for (int i = 0; i < 4; i++)
#pragma unroll
            for (int j = 0; j < 4; j++)
                sc[i][j] += __shfl_xor_sync(0xffffffffu, sc[i][j], o);

    const float scale = 0.08838834764831845f;
    float wj[4] = {0.f, 0.f, 0.f, 0.f};
#pragma unroll
    for (int i = 0; i < 4; i++) {
        float s0 = sc[i][0] * scale, s1 = sc[i][1] * scale;
        float s2 = sc[i][2] * scale, s3 = sc[i][3] * scale;
        float m = fmaxf(fmaxf(s0, s1), fmaxf(s2, s3));
        float e0 = __expf(s0 - m), e1 = __expf(s1 - m);
        float e2 = __expf(s2 - m), e3 = __expf(s3 - m);
        float inv = 0.25f / (e0 + e1 + e2 + e3);
        wj[0] += e0 * inv; wj[1] += e1 * inv;
        wj[2] += e2 * inv; wj[3] += e3 * inv;
    }

    float4 o = {0.f, 0.f, 0.f, 0.f};
#pragma unroll
    for (int j = 0; j < 4; j++) {
        o.x += wj[j] * v[j].x; o.y += wj[j] * v[j].y;
        o.z += wj[j] * v[j].z; o.w += wj[j] * v[j].w;
    }
    int cb = w * 128 + l * 4;
    *(__half2*)(meanout + afrag_h(sb, cb))     = __floats2half2_rn(o.x, o.y);
    *(__half2*)(meanout + afrag_h(sb, cb + 2)) = __floats2half2_rn(o.z, o.w);
}

// ---------------------------------------------------------------------------
// Attention stage B: L=64, dh=128, half qkv input. One CTA per (b, head).
// Writes half A-frag output.
// ---------------------------------------------------------------------------
#define A2_LD 130
#define A2_SMEM ((3 * 64 * A2_LD + 64 * 65) * 4)

__global__ void __launch_bounds__(256) attn2_kernel(
    const __half* __restrict__ qkv2, __half* __restrict__ out)
{
    extern __shared__ float smf[];
    float* qs = smf;
    float* ks = qs + 64 * A2_LD;
    float* vs = ks + 64 * A2_LD;
    float* ps = vs + 64 * A2_LD;

    const int b = blockIdx.x >> 3;
    const int h = blockIdx.x & 7;
    const int tid = threadIdx.x;

    for (int p = tid; p < 64 * 32; p += 256) {
        int r = p >> 5, c4 = (p & 31) << 2;
        const __half* src = qkv2 + (size_t)(b * 64 + r) * 3072 + h * 128 + c4;
        float4 xq = ld_half4(src);
        float4 xk = ld_half4(src + 1024);
        float4 xv = ld_half4(src + 2048);
        float* qd = qs + r * A2_LD + c4;
        float* kd = ks + r * A2_LD + c4;
        float* vd = vs + r * A2_LD + c4;
        qd[0] = xq.x; qd[1] = xq.y; qd[2] = xq.z; qd[3] = xq.w;
        kd[0] = xk.x; kd[1] = xk.y; kd[2] = xk.z; kd[3] = xk.w;
        vd[0] = xv.x; vd[1] = xv.y; vd[2] = xv.z; vd[3] = xv.w;
    }
    __syncthreads();

    const int w = tid >> 5, l = tid & 31;
    const float scale = 0.08838834764831845f;

    for (int r = 0; r < 8; r++) {
        int i = w * 8 + r;
        const float* qp = qs + i * A2_LD;
        const float* k0 = ks + l * A2_LD;
        const float* k1 = ks + (l + 32) * A2_LD;
        float s0 = 0.f, s1 = 0.f;
#pragma unroll 8
        for (int d = 0; d < 128; d++) {
            float qv = qp[d];
            s0 += qv * k0[d];
            s1 += qv * k1[d];
        }
        ps[i * 65 + l]      = s0 * scale;
        ps[i * 65 + l + 32] = s1 * scale;
    }
    __syncwarp();

    for (int r = 0; r < 8; r++) {
        int i = w * 8 + r;
        float a0 = ps[i * 65 + l], a1 = ps[i * 65 + l + 32];
        float m = fmaxf(a0, a1);
#pragma unroll
        for (int o = 16; o > 0; o >>= 1)
            m = fmaxf(m, __shfl_xor_sync(0xffffffffu, m, o));
        float e0 = __expf(a0 - m), e1 = __expf(a1 - m);
        float s = e0 + e1;
#pragma unroll
        for (int o = 16; o > 0; o >>= 1)
            s += __shfl_xor_sync(0xffffffffu, s, o);
        float inv = 1.0f / s;
        ps[i * 65 + l]      = e0 * inv;
        ps[i * 65 + l + 32] = e1 * inv;
    }
    __syncwarp();

    // out[i][d]: thread l covers cols {2l, 2l+1, 2l+64, 2l+65}
    for (int r = 0; r < 8; r++) {
        int i = w * 8 + r;
        const float* pr = ps + i * 65;
        float a0 = 0.f, a1 = 0.f, a2 = 0.f, a3 = 0.f;
#pragma unroll 4
        for (int j = 0; j < 64; j++) {
            float pj = pr[j];
            const float* vp = vs + j * A2_LD;
            float2 lo = *(const float2*)(vp + 2 * l);
            float2 hi = *(const float2*)(vp + 2 * l + 64);
            a0 += pj * lo.x; a1 += pj * lo.y;
            a2 += pj * hi.x; a3 += pj * hi.y;
        }
        int row = b * 64 + i, cb = h * 128 + 2 * l;
        *(__half2*)(out + afrag_h(row, cb))      = __floats2half2_rn(a0, a1);
        *(__half2*)(out + afrag_h(row, cb + 64)) = __floats2half2_rn(a2, a3);
    }
}

// ---------------------------------------------------------------------------
extern "C" void kernel_launch(void* const* d_in, const int* in_sizes, int n_in,
                              void* d_out, int out_size)
{
    (void)in_sizes; (void)n_in; (void)out_size;
    const float* hid      = (const float*)d_in[0];
    const float* mf_in_w  = (const float*)d_in[1];
    const float* mf_in_b  = (const float*)d_in[2];
    const float* mf_out_w = (const float*)d_in[3];
    const float* mf_out_b = (const float*)d_in[4];
    const float* sf_in_w  = (const float*)d_in[5];
    const float* sf_in_b  = (const float*)d_in[6];
    const float* sf_out_w = (const float*)d_in[7];
    const float* sf_out_b = (const float*)d_in[8];
    const float* pos_enc  = (const float*)d_in[9];
    float* out = (float*)d_out;

    __half *hidA, *wmin, *wmout, *wsin, *wsout, *qkv1, *meanb, *seq, *qkv2, *att2;
    cudaGetSymbolAddress((void**)&hidA,  g_hidA);
    cudaGetSymbolAddress((void**)&wmin,  g_wmin);
    cudaGetSymbolAddress((void**)&wmout, g_wmout);
    cudaGetSymbolAddress((void**)&wsin,  g_wsin);
    cudaGetSymbolAddress((void**)&wsout, g_wsout);
    cudaGetSymbolAddress((void**)&qkv1,  g_qkv1);
    cudaGetSymbolAddress((void**)&meanb, g_mean);
    cudaGetSymbolAddress((void**)&seq,   g_seq);
    cudaGetSymbolAddress((void**)&qkv2,  g_qkv2);
    cudaGetSymbolAddress((void**)&att2,  g_att2);

    cudaFuncSetAttribute(conv_hidden,
        cudaFuncAttributeMaxDynamicSharedMemorySize, CONV_SMEM);
    cudaFuncSetAttribute(conv_w,
        cudaFuncAttributeMaxDynamicSharedMemorySize, CONV_SMEM);
    cudaFuncSetAttribute(tgemm2<0>,
        cudaFuncAttributeMaxDynamicSharedMemorySize, GSMEM);
    cudaFuncSetAttribute(tgemm2<1>,
        cudaFuncAttributeMaxDynamicSharedMemorySize, GSMEM);
    cudaFuncSetAttribute(tgemm2<2>,
        cudaFuncAttributeMaxDynamicSharedMemorySize, GSMEM);
    cudaFuncSetAttribute(attn2_kernel,
        cudaFuncAttributeMaxDynamicSharedMemorySize, A2_SMEM);

    // ---- prepass: fragment-order + fp16-round all GEMM inputs ----
    conv_hidden<<<2048, 256, CONV_SMEM>>>(hid, hidA);
    conv_w<<<192, 256, CONV_SMEM>>>(mf_in_w, wmin);
    conv_w<<< 64, 256, CONV_SMEM>>>(mf_out_w, wmout);
    conv_w<<<192, 256, CONV_SMEM>>>(sf_in_w, wsin);
    conv_w<<< 64, 256, CONV_SMEM>>>(sf_out_w, wsout);

    // Stage A: qkv1 = hidden @ mf_in_w^T + b              [32768 x 3072] half
    tgemm2<0><<<dim3(12, 256), 256, GSMEM>>>(hidA, wmin, mf_in_b, nullptr,
                                             qkv1, 3072);
    // Stage A attention (L=4) + mean over models          -> A-frag half
    attn1_kernel<<<8192, 256>>>(qkv1, meanb);
    // Stage A out-proj + transpose to [B,S,H] + pos_enc   -> A-frag half
    tgemm2<1><<<dim3(4, 64), 256, GSMEM>>>(meanb, wmout, mf_out_b, pos_enc,
                                           seq, 1024);
    // Stage B: qkv2 = seq @ sf_in_w^T + b                 [8192 x 3072] half
    tgemm2<0><<<dim3(12, 64), 256, GSMEM>>>(seq, wsin, sf_in_b, nullptr,
                                            qkv2, 3072);
    // Stage B attention (L=64)                            -> A-frag half
    attn2_kernel<<<1024, 256, A2_SMEM>>>(qkv2, att2);
    // Stage B out-proj + transpose to [S,B,1,H]           -> d_out (float)
    tgemm2<2><<<dim3(4, 64), 256, GSMEM>>>(att2, wsout, sf_out_b, nullptr,
                                           out, 1024);
}

// round 7
// speedup vs baseline: 6.2417x; 1.0180x over previous
#include <cuda_runtime.h>
#include <cuda_fp16.h>
#include <cstdint>
#include <math.h>

// ---------------------------------------------------------------------------
// HierarchicalModelFusion — fp16 mma.sync (m16n8k16, f32 accum),
// fragment-ordered packed-half operands, cp.async 4-stage pipeline.
// ---------------------------------------------------------------------------

#define KD 1024

// Scratch (device globals)
__device__ __align__(256) __half g_hidA[(size_t)32768 * 1024];  // A-frag
__device__ __align__(256) __half g_wmin[(size_t)3072 * 1024];   // B-frag
__device__ __align__(256) __half g_wmout[(size_t)1024 * 1024];  // B-frag
__device__ __align__(256) __half g_wsin[(size_t)3072 * 1024];   // B-frag
__device__ __align__(256) __half g_wsout[(size_t)1024 * 1024];  // B-frag
__device__ __align__(256) __half g_qkv1[(size_t)32768 * 3072];  // row layout
__device__ __align__(256) __half g_mean[(size_t)8192 * 1024];   // A-frag
__device__ __align__(256) __half g_seq [(size_t)8192 * 1024];   // A-frag
__device__ __align__(256) __half g_qkv2[(size_t)8192 * 3072];   // row layout
__device__ __align__(256) __half g_att2[(size_t)8192 * 1024];   // A-frag

__device__ __forceinline__ uint32_t h2_u32(__half2 h) {
    return *reinterpret_cast<uint32_t*>(&h);
}

// A-frag (m16n8k16 A operand) index for a [rows,1024] half matrix.
__device__ __forceinline__ size_t afrag_h(int r, int c) {
    int mt = r >> 7, mb = (r >> 4) & 7, ri = r & 15;
    int kt = c >> 6, kb = (c >> 4) & 3, ci = c & 15;
    int lane = (ri & 7) * 4 + ((ci & 7) >> 1);
    int idx = (ci & 1) + 2 * ((ri >> 3) & 1) + 4 * ((ci >> 3) & 1);
    return ((size_t)(mt * 16 + kt) << 13) + ((kb * 8 + mb) << 8) + (lane << 3) + idx;
}

__device__ __forceinline__ void mma_f16(float* d, uint32_t a0, uint32_t a1,
                                        uint32_t a2, uint32_t a3,
                                        uint32_t b0, uint32_t b1) {
    asm volatile(
        "mma.sync.aligned.m16n8k16.row.col.f32.f16.f16.f32 "
        "{%0,%1,%2,%3}, {%4,%5,%6,%7}, {%8,%9}, {%0,%1,%2,%3};"
        : "+f"(d[0]), "+f"(d[1]), "+f"(d[2]), "+f"(d[3])
        : "r"(a0), "r"(a1), "r"(a2), "r"(a3), "r"(b0), "r"(b1));
}

__device__ __forceinline__ void cp16(uint32_t dst, const void* src) {
    asm volatile("cp.async.cg.shared.global [%0], [%1], 16;"
                 :: "r"(dst), "l"(src));
}
__device__ __forceinline__ uint32_t smem_u32(const void* p) {
    uint32_t a;
    asm("{ .reg .u64 t; cvta.to.shared.u64 t, %1; cvt.u32.u64 %0, t; }"
        : "=r"(a) : "l"(p));
    return a;
}

// ---------------------------------------------------------------------------
// Prepass: hidden[S,M,B,1,H] -> gathered A-frag halves. CTA per 16 rows.
// ---------------------------------------------------------------------------
#define CONV_SMEM (16 * 1028 * 4)
__global__ void __launch_bounds__(256) conv_hidden(
    const float* __restrict__ hid, __half* __restrict__ Af)
{
    extern __shared__ float tile[];    // [16][1028]
    const int tid = threadIdx.x, nb = blockIdx.x;   // 2048 blocks
#pragma unroll
    for (int i = 0; i < 16; i++) {
        int idx = tid + 256 * i;
        int r = idx >> 8, c4 = idx & 255;
        int n = nb * 16 + r;
        int s = n >> 9, b = (n >> 2) & 127, m = n & 3;
        float4 v = *(const float4*)(hid + (((size_t)((s * 4 + m) * 128 + b)) << 10)
                                        + (c4 << 2));
        *(float4*)&tile[r * 1028 + c4 * 4] = v;
    }
    __syncthreads();
    const int mt = nb >> 3, mb = nb & 7;
#pragma unroll
    for (int j = 0; j < 8; j++) {
        int g = tid + 256 * j;              // 0..2047
        int kt = g >> 7, rr = g & 127, kb = rr >> 5, ln = rr & 31;
        int grp = ln >> 2, tig = ln & 3;
        int c0 = kt * 64 + kb * 16 + 2 * tig;
        __half2 p0 = __floats2half2_rn(tile[grp * 1028 + c0],
                                       tile[grp * 1028 + c0 + 1]);
        __half2 p1 = __floats2half2_rn(tile[(grp + 8) * 1028 + c0],
                                       tile[(grp + 8) * 1028 + c0 + 1]);
        __half2 p2 = __floats2half2_rn(tile[grp * 1028 + c0 + 8],
                                       tile[grp * 1028 + c0 + 9]);
        __half2 p3 = __floats2half2_rn(tile[(grp + 8) * 1028 + c0 + 8],
                                       tile[(grp + 8) * 1028 + c0 + 9]);
        uint4 o;
        o.x = h2_u32(p0); o.y = h2_u32(p1);
        o.z = h2_u32(p2); o.w = h2_u32(p3);
        *(uint4*)(Af + ((size_t)(mt * 16 + kt) << 13) + ((kb * 8 + mb) << 8)
                     + (ln << 3)) = o;
    }
}

// Batched prepass: all 4 weight matrices -> B-frag halves in ONE launch.
// Blocks [0,192): mf_in_w; [192,256): mf_out_w; [256,448): sf_in_w;
// [448,512): sf_out_w. Each block converts 16 weight rows.
__global__ void __launch_bounds__(256) conv_w4(
    const float* __restrict__ w0, const float* __restrict__ w1,
    const float* __restrict__ w2, const float* __restrict__ w3,
    __half* __restrict__ o0, __half* __restrict__ o1,
    __half* __restrict__ o2, __half* __restrict__ o3)
{
    extern __shared__ float tile[];    // [16][1028]
    const int tid = threadIdx.x;
    int gid = blockIdx.x;
    const float* W; __half* Bf;
    if (gid < 192)      { W = w0; Bf = o0; }
    else if (gid < 256) { W = w1; Bf = o1; gid -= 192; }
    else if (gid < 448) { W = w2; Bf = o2; gid -= 256; }
    else                { W = w3; Bf = o3; gid -= 448; }
#pragma unroll
    for (int i = 0; i < 16; i++) {
        int idx = tid + 256 * i;
        int r = idx >> 8, c4 = idx & 255;
        float4 v = *(const float4*)(W + ((size_t)(gid * 16 + r) << 10) + (c4 << 2));
        *(float4*)&tile[r * 1028 + c4 * 4] = v;
    }
    __syncthreads();
    const int nt = gid >> 4, gblk = gid & 15;
#pragma unroll
    for (int j = 0; j < 8; j++) {
        int g = tid + 256 * j;
        int kt = g >> 7, rr = g & 127, kb = rr >> 5, ln = rr & 31;
        int grp = ln >> 2, tig = ln & 3;
        int c0 = kt * 64 + kb * 16 + 2 * tig;
        __half2 p0 = __floats2half2_rn(tile[grp * 1028 + c0],
                                       tile[grp * 1028 + c0 + 1]);
        __half2 p1 = __floats2half2_rn(tile[grp * 1028 + c0 + 8],
                                       tile[grp * 1028 + c0 + 9]);
        __half2 p2 = __floats2half2_rn(tile[(grp + 8) * 1028 + c0],
                                       tile[(grp + 8) * 1028 + c0 + 1]);
        __half2 p3 = __floats2half2_rn(tile[(grp + 8) * 1028 + c0 + 8],
                                       tile[(grp + 8) * 1028 + c0 + 9]);
        uint4 o;
        o.x = h2_u32(p0); o.y = h2_u32(p1);
        o.z = h2_u32(p2); o.w = h2_u32(p3);
        *(uint4*)(Bf + ((size_t)(nt * 16 + kt) << 14) + ((kb * 16 + gblk) << 8)
                     + (ln << 3)) = o;
    }
}

// ---------------------------------------------------------------------------
// GEMM: C = A @ W^T + bias. CTA 128x256, warp 64x64, K chunks of 64 halves,
// 4-stage cp.async. EPI: 0 = half row-layout store; 1 = transpose [B,S,H] +
// pos_enc -> half A-frag; 2 = transpose [S,B,H] -> float store (final out).
// ---------------------------------------------------------------------------
#define STAGE_B 49152                  // 16KB A + 32KB B per stage
#define GSMEM   (4 * STAGE_B)          // 192KB

template <int EPI>
__global__ void __launch_bounds__(256, 1) tgemm2(
    const __half* __restrict__ Af, const __half* __restrict__ Bf,
    const float* __restrict__ bias, const float* __restrict__ pos,
    void* __restrict__ Cv, int N)
{
    extern __shared__ char smem_raw[];
    const uint32_t sb = smem_u32(smem_raw);
    const int tid = threadIdx.x, wid = tid >> 5, lane = tid & 31;
    const int bm = blockIdx.y, bn = blockIdx.x;

    const uint4* Af4 = (const uint4*)Af + ((size_t)bm << 14) + tid; // bm*16*1024
    const uint4* Bf4 = (const uint4*)Bf + ((size_t)bn << 15) + tid; // bn*16*2048
    const uint32_t adst = sb + tid * 16;
    const uint32_t bdst = sb + 16384 + tid * 16;

    auto issue = [&](int kt, int s) {
        const uint4* a = Af4 + (kt << 10);
        uint32_t ad = adst + s * STAGE_B;
#pragma unroll
        for (int i = 0; i < 4; i++) cp16(ad + i * 4096, a + i * 256);
        const uint4* b = Bf4 + (kt << 11);
        uint32_t bd = bdst + s * STAGE_B;
#pragma unroll
        for (int i = 0; i < 8; i++) cp16(bd + i * 4096, b + i * 256);
        asm volatile("cp.async.commit_group;" ::: "memory");
    };

    float acc[4][8][4];
#pragma unroll
    for (int mt = 0; mt < 4; mt++)
#pragma unroll
        for (int nt = 0; nt < 8; nt++)
#pragma unroll
            for (int e = 0; e < 4; e++) acc[mt][nt][e] = 0.0f;

    const int wmb = (wid & 1) * 4;     // A 16-row block base
    const int wnb = (wid >> 1) * 4;    // B 16-col group base

    issue(0, 0);
    issue(1, 1);
    issue(2, 2);

#pragma unroll 1
    for (int c = 0; c < 16; c++) {
        if (c < 14)      asm volatile("cp.async.wait_group 2;" ::: "memory");
        else if (c == 14) asm volatile("cp.async.wait_group 1;" ::: "memory");
        else             asm volatile("cp.async.wait_group 0;" ::: "memory");
        __syncthreads();
        if (c + 3 < 16) issue(c + 3, (c + 3) & 3);

        const __half* sA = (const __half*)(smem_raw + (c & 3) * STAGE_B);
        const __half* sB = sA + 8192;
#pragma unroll
        for (int kb = 0; kb < 4; kb++) {
            uint4 af[4];
#pragma unroll
            for (int mt = 0; mt < 4; mt++)
                af[mt] = *(const uint4*)(sA + ((kb * 8 + wmb + mt) << 8) + (lane << 3));
#pragma unroll
            for (int gt = 0; gt < 4; gt++) {
                uint4 bb = *(const uint4*)(sB + ((kb * 16 + wnb + gt) << 8) + (lane << 3));
#pragma unroll
                for (int mt = 0; mt < 4; mt++) {
                    mma_f16(acc[mt][2 * gt],     af[mt].x, af[mt].y, af[mt].z, af[mt].w,
                            bb.x, bb.y);
                    mma_f16(acc[mt][2 * gt + 1], af[mt].x, af[mt].y, af[mt].z, af[mt].w,
                            bb.z, bb.w);
                }
            }
        }
    }

    // ---- epilogue ----
    const int grp = lane >> 2, tig = lane & 3;
    const int wm = (wid & 1) * 64, wn = (wid >> 1) * 64;
#pragma unroll
    for (int mt = 0; mt < 4; mt++) {
#pragma unroll
        for (int h = 0; h < 2; h++) {
            int gr = bm * 128 + wm + mt * 16 + grp + 8 * h;
#pragma unroll
            for (int nt = 0; nt < 8; nt++) {
                int gc = bn * 256 + wn + nt * 8 + 2 * tig;
                float2 b2 = *(const float2*)(bias + gc);
                float v0 = acc[mt][nt][2 * h]     + b2.x;
                float v1 = acc[mt][nt][2 * h + 1] + b2.y;
                if (EPI == 0) {
                    __half* C = (__half*)Cv;
                    *(__half2*)(C + (size_t)gr * N + gc) = __floats2half2_rn(v0, v1);
                } else if (EPI == 1) {
                    __half* C = (__half*)Cv;
                    int srow = gr >> 7, b = gr & 127;
                    float2 p2 = *(const float2*)(pos + (size_t)srow * 1024 + gc);
                    int r_out = b * 64 + srow;
                    *(__half2*)(C + afrag_h(r_out, gc)) =
                        __floats2half2_rn(v0 + p2.x, v1 + p2.y);
                } else {
                    float* C = (float*)Cv;
                    int b = gr >> 6, s = gr & 63;
                    float2 o; o.x = v0; o.y = v1;
                    *(float2*)(C + (size_t)(s * 128 + b) * N + gc) = o;
                }
            }
        }
    }
}

// ---------------------------------------------------------------------------
// Attention stage A: L=4, dh=128, half qkv input. One warp per (sb, head).
// ---------------------------------------------------------------------------
__device__ __forceinline__ float4 ld_half4(const __half* p) {
    uint2 raw = *(const uint2*)p;
    float2 a = __half22float2(*(__half2*)&raw.x);
    float2 b = __half22float2(*(__half2*)&raw.y);
    return make_float4(a.x, a.y, b.x, b.y);
}

__global__ void __launch_bounds__(256) attn1_kernel(
    const __half* __restrict__ qkv, __half* __restrict__ meanout)
{
    const int sb = blockIdx.x;
    const int w  = threadIdx.x >> 5;
    const int l  = threadIdx.x & 31;

    const __half* base = qkv + (size_t)sb * 4 * 3072 + w * 128 + l * 4;

    float4 q[4], k[4], v[4];
#pragma unroll
    for (int i = 0; i < 4; i++) {
        q[i] = ld_half4(base + (size_t)i * 3072);
        k[i] = ld_half4(base + (size_t)i * 3072 + 1024);
        v[i] = ld_half4(base + (size_t)i * 3072 + 2048);
    }

    float sc[4][4];
#pragma unroll
    for (int i = 0; i < 4; i++)
#pragma unroll
        for (int j = 0; j < 4; j++)
            sc[i][j] = q[i].x * k[j].x + q[i].y * k[j].y +
                       q[i].z * k[j].z + q[i].w * k[j].w;

#pragma unroll
    for (int o = 16; o > 0; o >>= 1)
#pragma unroll
        for (int i = 0; i < 4; i++)
#pragma unroll
            for (int j = 0; j < 4; j++)
                sc[i][j] += __shfl_xor_sync(0xffffffffu, sc[i][j], o);

    const float scale = 0.08838834764831845f;
    float wj[4] = {0.f, 0.f, 0.f, 0.f};
#pragma unroll
    for (int i = 0; i < 4; i++) {
        float s0 = sc[i][0] * scale, s1 = sc[i][1] * scale;
        float s2 = sc[i][2] * scale, s3 = sc[i][3] * scale;
        float m = fmaxf(fmaxf(s0, s1), fmaxf(s2, s3));
        float e0 = __expf(s0 - m), e1 = __expf(s1 - m);
        float e2 = __expf(s2 - m), e3 = __expf(s3 - m);
        float inv = 0.25f / (e0 + e1 + e2 + e3);
        wj[0] += e0 * inv; wj[1] += e1 * inv;
        wj[2] += e2 * inv; wj[3] += e3 * inv;
    }

    float4 o = {0.f, 0.f, 0.f, 0.f};
#pragma unroll
    for (int j = 0; j < 4; j++) {
        o.x += wj[j] * v[j].x; o.y += wj[j] * v[j].y;
        o.z += wj[j] * v[j].z; o.w += wj[j] * v[j].w;
    }
    int cb = w * 128 + l * 4;
    *(__half2*)(meanout + afrag_h(sb, cb))     = __floats2half2_rn(o.x, o.y);
    *(__half2*)(meanout + afrag_h(sb, cb + 2)) = __floats2half2_rn(o.z, o.w);
}

// ---------------------------------------------------------------------------
// Attention stage B: L=64, dh=128, half qkv input. One CTA per (b, head).
// ---------------------------------------------------------------------------
#define A2_LD 130
#define A2_SMEM ((3 * 64 * A2_LD + 64 * 65) * 4)

__global__ void __launch_bounds__(256) attn2_kernel(
    const __half* __restrict__ qkv2, __half* __restrict__ out)
{
    extern __shared__ float smf[];
    float* qs = smf;
    float* ks = qs + 64 * A2_LD;
    float* vs = ks + 64 * A2_LD;
    float* ps = vs + 64 * A2_LD;

    const int b = blockIdx.x >> 3;
    const int h = blockIdx.x & 7;
    const int tid = threadIdx.x;

    for (int p = tid; p < 64 * 32; p += 256) {
        int r = p >> 5, c4 = (p & 31) << 2;
        const __half* src = qkv2 + (size_t)(b * 64 + r) * 3072 + h * 128 + c4;
        float4 xq = ld_half4(src);
        float4 xk = ld_half4(src + 1024);
        float4 xv = ld_half4(src + 2048);
        float* qd = qs + r * A2_LD + c4;
        float* kd = ks + r * A2_LD + c4;
        float* vd = vs + r * A2_LD + c4;
        qd[0] = xq.x; qd[1] = xq.y; qd[2] = xq.z; qd[3] = xq.w;
        kd[0] = xk.x; kd[1] = xk.y; kd[2] = xk.z; kd[3] = xk.w;
        vd[0] = xv.x; vd[1] = xv.y; vd[2] = xv.z; vd[3] = xv.w;
    }
    __syncthreads();

    const int w = tid >> 5, l = tid & 31;
    const float scale = 0.08838834764831845f;

    for (int r = 0; r < 8; r++) {
        int i = w * 8 + r;
        const float* qp = qs + i * A2_LD;
        const float* k0 = ks + l * A2_LD;
        const float* k1 = ks + (l + 32) * A2_LD;
        float s0 = 0.f, s1 = 0.f;
#pragma unroll 8
        for (int d = 0; d < 128; d++) {
            float qv = qp[d];
            s0 += qv * k0[d];
            s1 += qv * k1[d];
        }
        ps[i * 65 + l]      = s0 * scale;
        ps[i * 65 + l + 32] = s1 * scale;
    }
    __syncwarp();

    for (int r = 0; r < 8; r++) {
        int i = w * 8 + r;
        float a0 = ps[i * 65 + l], a1 = ps[i * 65 + l + 32];
        float m = fmaxf(a0, a1);
#pragma unroll
        for (int o = 16; o > 0; o >>= 1)
            m = fmaxf(m, __shfl_xor_sync(0xffffffffu, m, o));
        float e0 = __expf(a0 - m), e1 = __expf(a1 - m);
        float s = e0 + e1;
#pragma unroll
        for (int o = 16; o > 0; o >>= 1)
            s += __shfl_xor_sync(0xffffffffu, s, o);
        float inv = 1.0f / s;
        ps[i * 65 + l]      = e0 * inv;
        ps[i * 65 + l + 32] = e1 * inv;
    }
    __syncwarp();

    // out[i][d]: thread l covers cols {2l, 2l+1, 2l+64, 2l+65}
    for (int r = 0; r < 8; r++) {
        int i = w * 8 + r;
        const float* pr = ps + i * 65;
        float a0 = 0.f, a1 = 0.f, a2 = 0.f, a3 = 0.f;
#pragma unroll 4
        for (int j = 0; j < 64; j++) {
            float pj = pr[j];
            const float* vp = vs + j * A2_LD;
            float2 lo = *(const float2*)(vp + 2 * l);
            float2 hi = *(const float2*)(vp + 2 * l + 64);
            a0 += pj * lo.x; a1 += pj * lo.y;
            a2 += pj * hi.x; a3 += pj * hi.y;
        }
        int row = b * 64 + i, cb = h * 128 + 2 * l;
        *(__half2*)(out + afrag_h(row, cb))      = __floats2half2_rn(a0, a1);
        *(__half2*)(out + afrag_h(row, cb + 64)) = __floats2half2_rn(a2, a3);
    }
}

// ---------------------------------------------------------------------------
extern "C" void kernel_launch(void* const* d_in, const int* in_sizes, int n_in,
                              void* d_out, int out_size)
{
    (void)in_sizes; (void)n_in; (void)out_size;
    const float* hid      = (const float*)d_in[0];
    const float* mf_in_w  = (const float*)d_in[1];
    const float* mf_in_b  = (const float*)d_in[2];
    const float* mf_out_w = (const float*)d_in[3];
    const float* mf_out_b = (const float*)d_in[4];
    const float* sf_in_w  = (const float*)d_in[5];
    const float* sf_in_b  = (const float*)d_in[6];
    const float* sf_out_w = (const float*)d_in[7];
    const float* sf_out_b = (const float*)d_in[8];
    const float* pos_enc  = (const float*)d_in[9];
    float* out = (float*)d_out;

    __half *hidA, *wmin, *wmout, *wsin, *wsout, *qkv1, *meanb, *seq, *qkv2, *att2;
    cudaGetSymbolAddress((void**)&hidA,  g_hidA);
    cudaGetSymbolAddress((void**)&wmin,  g_wmin);
    cudaGetSymbolAddress((void**)&wmout, g_wmout);
    cudaGetSymbolAddress((void**)&wsin,  g_wsin);
    cudaGetSymbolAddress((void**)&wsout, g_wsout);
    cudaGetSymbolAddress((void**)&qkv1,  g_qkv1);
    cudaGetSymbolAddress((void**)&meanb, g_mean);
    cudaGetSymbolAddress((void**)&seq,   g_seq);
    cudaGetSymbolAddress((void**)&qkv2,  g_qkv2);
    cudaGetSymbolAddress((void**)&att2,  g_att2);

    cudaFuncSetAttribute(conv_hidden,
        cudaFuncAttributeMaxDynamicSharedMemorySize, CONV_SMEM);
    cudaFuncSetAttribute(conv_w4,
        cudaFuncAttributeMaxDynamicSharedMemorySize, CONV_SMEM);
    cudaFuncSetAttribute(tgemm2<0>,
        cudaFuncAttributeMaxDynamicSharedMemorySize, GSMEM);
    cudaFuncSetAttribute(tgemm2<1>,
        cudaFuncAttributeMaxDynamicSharedMemorySize, GSMEM);
    cudaFuncSetAttribute(tgemm2<2>,
        cudaFuncAttributeMaxDynamicSharedMemorySize, GSMEM);
    cudaFuncSetAttribute(attn2_kernel,
        cudaFuncAttributeMaxDynamicSharedMemorySize, A2_SMEM);

    // ---- prepass: fragment-order + fp16-round all GEMM inputs ----
    conv_hidden<<<2048, 256, CONV_SMEM>>>(hid, hidA);
    conv_w4<<<512, 256, CONV_SMEM>>>(mf_in_w, mf_out_w, sf_in_w, sf_out_w,
                                     wmin, wmout, wsin, wsout);

    // Stage A: qkv1 = hidden @ mf_in_w^T + b              [32768 x 3072] half
    tgemm2<0><<<dim3(12, 256), 256, GSMEM>>>(hidA, wmin, mf_in_b, nullptr,
                                             qkv1, 3072);
    // Stage A attention (L=4) + mean over models          -> A-frag half
    attn1_kernel<<<8192, 256>>>(qkv1, meanb);
    // Stage A out-proj + transpose to [B,S,H] + pos_enc   -> A-frag half
    tgemm2<1><<<dim3(4, 64), 256, GSMEM>>>(meanb, wmout, mf_out_b, pos_enc,
                                           seq, 1024);
    // Stage B: qkv2 = seq @ sf_in_w^T + b                 [8192 x 3072] half
    tgemm2<0><<<dim3(12, 64), 256, GSMEM>>>(seq, wsin, sf_in_b, nullptr,
                                            qkv2, 3072);
    // Stage B attention (L=64)                            -> A-frag half
    attn2_kernel<<<1024, 256, A2_SMEM>>>(qkv2, att2);
    // Stage B out-proj + transpose to [S,B,1,H]           -> d_out (float)
    tgemm2<2><<<dim3(4, 64), 256, GSMEM>>>(att2, wsout, sf_out_b, nullptr,
                                           out, 1024);
}

// round 9
// speedup vs baseline: 6.5601x; 1.0510x over previous
#include <cuda_runtime.h>
#include <cuda_fp16.h>
#include <cstdint>
#include <math.h>

// ---------------------------------------------------------------------------
// HierarchicalModelFusion — fp16 mma.sync (m16n8k16, f32 accum),
// fragment-ordered packed-half operands, cp.async pipeline (4-stage for
// TN=256, 3-stage for TN=384 due to the 227KB smem cap).
// Stage-A attention is FUSED into the qkv1 GEMM epilogue: mf_in_w columns are
// permuted head-major ([h][q|k|v] x 128), CTA tile N=384 = one head, so each
// CTA holds complete q,k,v for 32 L=4 attention groups and writes only the
// 128-dim mean output. qkv1 never touches DRAM.
// ---------------------------------------------------------------------------

#define KD 1024

// Scratch (device globals)
__device__ __align__(256) __half g_hidA[(size_t)32768 * 1024];  // A-frag
__device__ __align__(256) __half g_wmin[(size_t)3072 * 1024];   // B-frag TN=384, head-permuted
__device__ __align__(256) __half g_wmout[(size_t)1024 * 1024];  // B-frag TN=256
__device__ __align__(256) __half g_wsin[(size_t)3072 * 1024];   // B-frag TN=256
__device__ __align__(256) __half g_wsout[(size_t)1024 * 1024];  // B-frag TN=256
__device__ __align__(256) __half g_mean[(size_t)8192 * 1024];   // A-frag
__device__ __align__(256) __half g_seq [(size_t)8192 * 1024];   // A-frag
__device__ __align__(256) __half g_qkv2[(size_t)8192 * 3072];   // row layout
__device__ __align__(256) __half g_att2[(size_t)8192 * 1024];   // A-frag

__device__ __forceinline__ uint32_t h2_u32(__half2 h) {
    return *reinterpret_cast<uint32_t*>(&h);
}
__device__ __forceinline__ float4 ld_half4(const __half* p) {
    uint2 raw = *(const uint2*)p;
    float2 a = __half22float2(*(__half2*)&raw.x);
    float2 b = __half22float2(*(__half2*)&raw.y);
    return make_float4(a.x, a.y, b.x, b.y);
}

// A-frag (m16n8k16 A operand) index for a [rows,1024] half matrix.
__device__ __forceinline__ size_t afrag_h(int r, int c) {
    int mt = r >> 7, mb = (r >> 4) & 7, ri = r & 15;
    int kt = c >> 6, kb = (c >> 4) & 3, ci = c & 15;
    int lane = (ri & 7) * 4 + ((ci & 7) >> 1);
    int idx = (ci & 1) + 2 * ((ri >> 3) & 1) + 4 * ((ci >> 3) & 1);
    return ((size_t)(mt * 16 + kt) << 13) + ((kb * 8 + mb) << 8) + (lane << 3) + idx;
}

__device__ __forceinline__ void mma_f16(float* d, uint32_t a0, uint32_t a1,
                                        uint32_t a2, uint32_t a3,
                                        uint32_t b0, uint32_t b1) {
    asm volatile(
        "mma.sync.aligned.m16n8k16.row.col.f32.f16.f16.f32 "
        "{%0,%1,%2,%3}, {%4,%5,%6,%7}, {%8,%9}, {%0,%1,%2,%3};"
        : "+f"(d[0]), "+f"(d[1]), "+f"(d[2]), "+f"(d[3])
        : "r"(a0), "r"(a1), "r"(a2), "r"(a3), "r"(b0), "r"(b1));
}

__device__ __forceinline__ void cp16(uint32_t dst, const void* src) {
    asm volatile("cp.async.cg.shared.global [%0], [%1], 16;"
                 :: "r"(dst), "l"(src));
}
__device__ __forceinline__ uint32_t smem_u32(const void* p) {
    uint32_t a;
    asm("{ .reg .u64 t; cvta.to.shared.u64 t, %1; cvt.u32.u64 %0, t; }"
        : "=r"(a) : "l"(p));
    return a;
}

// ---------------------------------------------------------------------------
// Prepass: hidden[S,M,B,1,H] -> gathered A-frag halves. CTA per 16 rows.
// ---------------------------------------------------------------------------
#define CONV_SMEM (16 * 1028 * 4)
__global__ void __launch_bounds__(256) conv_hidden(
    const float* __restrict__ hid, __half* __restrict__ Af)
{
    extern __shared__ float tile[];    // [16][1028]
    const int tid = threadIdx.x, nb = blockIdx.x;   // 2048 blocks
#pragma unroll
    for (int i = 0; i < 16; i++) {
        int idx = tid + 256 * i;
        int r = idx >> 8, c4 = idx & 255;
        int n = nb * 16 + r;
        int s = n >> 9, b = (n >> 2) & 127, m = n & 3;
        float4 v = *(const float4*)(hid + (((size_t)((s * 4 + m) * 128 + b)) << 10)
                                        + (c4 << 2));
        *(float4*)&tile[r * 1028 + c4 * 4] = v;
    }
    __syncthreads();
    const int mt = nb >> 3, mb = nb & 7;
#pragma unroll
    for (int j = 0; j < 8; j++) {
        int g = tid + 256 * j;              // 0..2047
        int kt = g >> 7, rr = g & 127, kb = rr >> 5, ln = rr & 31;
        int grp = ln >> 2, tig = ln & 3;
        int c0 = kt * 64 + kb * 16 + 2 * tig;
        __half2 p0 = __floats2half2_rn(tile[grp * 1028 + c0],
                                       tile[grp * 1028 + c0 + 1]);
        __half2 p1 = __floats2half2_rn(tile[(grp + 8) * 1028 + c0],
                                       tile[(grp + 8) * 1028 + c0 + 1]);
        __half2 p2 = __floats2half2_rn(tile[grp * 1028 + c0 + 8],
                                       tile[grp * 1028 + c0 + 9]);
        __half2 p3 = __floats2half2_rn(tile[(grp + 8) * 1028 + c0 + 8],
                                       tile[(grp + 8) * 1028 + c0 + 9]);
        uint4 o;
        o.x = h2_u32(p0); o.y = h2_u32(p1);
        o.z = h2_u32(p2); o.w = h2_u32(p3);
        *(uint4*)(Af + ((size_t)(mt * 16 + kt) << 13) + ((kb * 8 + mb) << 8)
                     + (ln << 3)) = o;
    }
}

// Batched prepass: 4 weight matrices -> B-frag halves in ONE launch.
// Blocks [0,192): mf_in_w  -> TN=384 layout, head-permuted columns
//        [192,256): mf_out_w -> TN=256; [256,448): sf_in_w -> TN=256;
//        [448,512): sf_out_w -> TN=256.
__global__ void __launch_bounds__(256) conv_w4(
    const float* __restrict__ w0, const float* __restrict__ w1,
    const float* __restrict__ w2, const float* __restrict__ w3,
    __half* __restrict__ o0, __half* __restrict__ o1,
    __half* __restrict__ o2, __half* __restrict__ o3)
{
    extern __shared__ float tile[];    // [16][1028]
    const int tid = threadIdx.x;
    int gid = blockIdx.x;
    const float* W; __half* Bf;
    bool perm384 = false;
    if (gid < 192)      { W = w0; Bf = o0; perm384 = true; }
    else if (gid < 256) { W = w1; Bf = o1; gid -= 192; }
    else if (gid < 448) { W = w2; Bf = o2; gid -= 256; }
    else                { W = w3; Bf = o3; gid -= 448; }
#pragma unroll
    for (int i = 0; i < 16; i++) {
        int idx = tid + 256 * i;
        int r = idx >> 8, c4 = idx & 255;
        float4 v = *(const float4*)(W + ((size_t)(gid * 16 + r) << 10) + (c4 << 2));
        *(float4*)&tile[r * 1028 + c4 * 4] = v;
    }
    __syncthreads();

    // Output tile coordinates
    int ntile, gblk, ngroups;
    if (perm384) {
        int j0 = gid * 16;
        int p = j0 >> 10, rem = j0 & 1023;
        int h = rem >> 7, d0 = rem & 127;
        ntile = h;                     // 384-wide tile = head
        gblk = p * 8 + (d0 >> 4);      // 16-col group within 384 (24 groups)
        ngroups = 24;
    } else {
        ntile = gid >> 4;
        gblk = gid & 15;
        ngroups = 16;
    }

#pragma unroll
    for (int j = 0; j < 8; j++) {
        int g = tid + 256 * j;
        int kt = g >> 7, rr = g & 127, kb = rr >> 5, ln = rr & 31;
        int grp = ln >> 2, tig = ln & 3;
        int c0 = kt * 64 + kb * 16 + 2 * tig;
        __half2 p0 = __floats2half2_rn(tile[grp * 1028 + c0],
                                       tile[grp * 1028 + c0 + 1]);
        __half2 p1 = __floats2half2_rn(tile[grp * 1028 + c0 + 8],
                                       tile[grp * 1028 + c0 + 9]);
        __half2 p2 = __floats2half2_rn(tile[(grp + 8) * 1028 + c0],
                                       tile[(grp + 8) * 1028 + c0 + 1]);
        __half2 p3 = __floats2half2_rn(tile[(grp + 8) * 1028 + c0 + 8],
                                       tile[(grp + 8) * 1028 + c0 + 9]);
        uint4 o;
        o.x = h2_u32(p0); o.y = h2_u32(p1);
        o.z = h2_u32(p2); o.w = h2_u32(p3);
        size_t off = ((size_t)(ntile * 16 + kt) * (ngroups * 16 * 64))
                   + ((size_t)(kb * ngroups + gblk) << 8) + (ln << 3);
        *(uint4*)(Bf + off) = o;
    }
}

// ---------------------------------------------------------------------------
// GEMM: C = A @ W^T + bias. CTA 128xTN, warp 64x64, K chunks of 64 halves.
// NSTAGE = 4 for TN=256 (196KB), 3 for TN=384 (196KB).
// EPI 0: half row-layout store (TN=256)
// EPI 1: transpose [B,S,H] + pos_enc -> half A-frag (TN=256)
// EPI 2: transpose [S,B,H] -> float store, final out (TN=256)
// EPI 3: FUSED stage-A attention (TN=384, one head per CTA) -> mean A-frag
// ---------------------------------------------------------------------------
template <int EPI, int TN, int NT>
__global__ void __launch_bounds__(NT, 1) tgemm2(
    const __half* __restrict__ Af, const __half* __restrict__ Bf,
    const float* __restrict__ bias, const float* __restrict__ pos,
    void* __restrict__ Cv, int N)
{
    constexpr int NWARP = NT / 32;          // 8 or 12
    constexpr int BCH = TN * 64 * 2;        // B bytes per chunk
    constexpr int SSTAGE = 16384 + BCH;     // stage bytes (49152 or 65536)
    constexpr int BGRP = TN / 16;           // 16-col groups per tile
    constexpr int NSTAGE = (TN == 384) ? 3 : 4;

    extern __shared__ char smem_raw[];
    const uint32_t sb = smem_u32(smem_raw);
    const int tid = threadIdx.x, wid = tid >> 5, lane = tid & 31;
    const int bm = blockIdx.y, bn = blockIdx.x;

    const uint4* Af4 = (const uint4*)Af + ((size_t)bm << 14) + tid;
    const uint4* Bf4 = (const uint4*)Bf + (size_t)bn * (TN * 128) + tid;
    const uint32_t adst = sb + tid * 16;
    const uint32_t bdst = sb + 16384 + tid * 16;

    auto issue = [&](int kt, int s) {
        if (NT == 256 || tid < 256) {
            const uint4* a = Af4 + (kt << 10);
            uint32_t ad = adst + s * SSTAGE;
#pragma unroll
            for (int i = 0; i < 4; i++) cp16(ad + i * 4096, a + i * 256);
        }
        const uint4* b = Bf4 + kt * (TN * 8);
        uint32_t bd = bdst + s * SSTAGE;
#pragma unroll
        for (int i = 0; i < 8; i++)
            cp16(bd + i * (NT * 16), b + i * NT);
        asm volatile("cp.async.commit_group;" ::: "memory");
    };

    float acc[4][8][4];
#pragma unroll
    for (int mt = 0; mt < 4; mt++)
#pragma unroll
        for (int nt = 0; nt < 8; nt++)
#pragma unroll
            for (int e = 0; e < 4; e++) acc[mt][nt][e] = 0.0f;

    const int wmb = (wid & 1) * 4;     // A 16-row block base
    const int wnb = (wid >> 1) * 4;    // B 16-col group base

    issue(0, 0);
    issue(1, 1);
    if (NSTAGE == 4) issue(2, 2);

#pragma unroll 1
    for (int c = 0; c < 16; c++) {
        // allowed outstanding groups = min(NSTAGE-2, 15-c)
        if (NSTAGE == 4) {
            if (c < 14)       asm volatile("cp.async.wait_group 2;" ::: "memory");
            else if (c == 14) asm volatile("cp.async.wait_group 1;" ::: "memory");
            else              asm volatile("cp.async.wait_group 0;" ::: "memory");
        } else {
            if (c < 15)       asm volatile("cp.async.wait_group 1;" ::: "memory");
            else              asm volatile("cp.async.wait_group 0;" ::: "memory");
        }
        __syncthreads();
        if (c + NSTAGE - 1 < 16)
            issue(c + NSTAGE - 1, (c + NSTAGE - 1) % NSTAGE);

        const __half* sA = (const __half*)(smem_raw + (c % NSTAGE) * SSTAGE);
        const __half* sB = sA + 8192;
#pragma unroll
        for (int kb = 0; kb < 4; kb++) {
            uint4 af[4];
#pragma unroll
            for (int mt = 0; mt < 4; mt++)
                af[mt] = *(const uint4*)(sA + ((kb * 8 + wmb + mt) << 8) + (lane << 3));
#pragma unroll
            for (int gt = 0; gt < 4; gt++) {
                uint4 bb = *(const uint4*)(sB + ((kb * BGRP + wnb + gt) << 8) + (lane << 3));
#pragma unroll
                for (int mt = 0; mt < 4; mt++) {
                    mma_f16(acc[mt][2 * gt],     af[mt].x, af[mt].y, af[mt].z, af[mt].w,
                            bb.x, bb.y);
                    mma_f16(acc[mt][2 * gt + 1], af[mt].x, af[mt].y, af[mt].z, af[mt].w,
                            bb.z, bb.w);
                }
            }
        }
    }

    const int grp = lane >> 2, tig = lane & 3;
    const int wm = (wid & 1) * 64, wn = (wid >> 1) * 64;

    if (EPI == 3) {
        // ---- fused stage-A attention epilogue (TN=384, head = bn) ----
        constexpr int ALD = 392;
        __half* sAtt = (__half*)smem_raw;     // 128 x 392 halves = 100352 B
        __syncthreads();                       // pipeline smem reads all done
#pragma unroll
        for (int mt = 0; mt < 4; mt++) {
#pragma unroll
            for (int h = 0; h < 2; h++) {
                int lr = wm + mt * 16 + grp + 8 * h;
#pragma unroll
                for (int nt = 0; nt < 8; nt++) {
                    int lc = wn + nt * 8 + 2 * tig;
                    int p = lc >> 7, d = lc & 127;
                    int j = p * 1024 + bn * 128 + d;
                    float2 b2 = *(const float2*)(bias + j);
                    *(__half2*)(sAtt + lr * ALD + lc) =
                        __floats2half2_rn(acc[mt][nt][2 * h] + b2.x,
                                          acc[mt][nt][2 * h + 1] + b2.y);
                }
            }
        }
        __syncthreads();

        __half* meanout = (__half*)Cv;
        const int l = lane;
        for (int g = wid; g < 32; g += NWARP) {
            float4 q[4], k[4], v[4];
#pragma unroll
            for (int i = 0; i < 4; i++) {
                const __half* rp = sAtt + (4 * g + i) * ALD;
                q[i] = ld_half4(rp + 4 * l);
                k[i] = ld_half4(rp + 128 + 4 * l);
                v[i] = ld_half4(rp + 256 + 4 * l);
            }
            float sc[4][4];
#pragma unroll
            for (int i = 0; i < 4; i++)
#pragma unroll
                for (int j = 0; j < 4; j++)
                    sc[i][j] = q[i].x * k[j].x + q[i].y * k[j].y +
                               q[i].z * k[j].z + q[i].w * k[j].w;
#pragma unroll
            for (int o = 16; o > 0; o >>= 1)
#pragma unroll
                for (int i = 0; i < 4; i++)
#pragma unroll
                    for (int j = 0; j < 4; j++)
                        sc[i][j] += __shfl_xor_sync(0xffffffffu, sc[i][j], o);

            const float scale = 0.08838834764831845f;
            float wj[4] = {0.f, 0.f, 0.f, 0.f};
#pragma unroll
            for (int i = 0; i < 4; i++) {
                float s0 = sc[i][0] * scale, s1 = sc[i][1] * scale;
                float s2 = sc[i][2] * scale, s3 = sc[i][3] * scale;
                float m = fmaxf(fmaxf(s0, s1), fmaxf(s2, s3));
                float e0 = __expf(s0 - m), e1 = __expf(s1 - m);
                float e2 = __expf(s2 - m), e3 = __expf(s3 - m);
                float inv = 0.25f / (e0 + e1 + e2 + e3);
                wj[0] += e0 * inv; wj[1] += e1 * inv;
                wj[2] += e2 * inv; wj[3] += e3 * inv;
            }
            float4 o = {0.f, 0.f, 0.f, 0.f};
#pragma unroll
            for (int j = 0; j < 4; j++) {
                o.x += wj[j] * v[j].x; o.y += wj[j] * v[j].y;
                o.z += wj[j] * v[j].z; o.w += wj[j] * v[j].w;
            }
            int row = bm * 32 + g;
            int cb = bn * 128 + 4 * l;
            *(__half2*)(meanout + afrag_h(row, cb))     = __floats2half2_rn(o.x, o.y);
            *(__half2*)(meanout + afrag_h(row, cb + 2)) = __floats2half2_rn(o.z, o.w);
        }
        return;
    }

    // ---- standard epilogues (TN=256) ----
#pragma unroll
    for (int mt = 0; mt < 4; mt++) {
#pragma unroll
        for (int h = 0; h < 2; h++) {
            int gr = bm * 128 + wm + mt * 16 + grp + 8 * h;
#pragma unroll
            for (int nt = 0; nt < 8; nt++) {
                int gc = bn * TN + wn + nt * 8 + 2 * tig;
                float2 b2 = *(const float2*)(bias + gc);
                float v0 = acc[mt][nt][2 * h]     + b2.x;
                float v1 = acc[mt][nt][2 * h + 1] + b2.y;
                if (EPI == 0) {
                    __half* C = (__half*)Cv;
                    *(__half2*)(C + (size_t)gr * N + gc) = __floats2half2_rn(v0, v1);
                } else if (EPI == 1) {
                    __half* C = (__half*)Cv;
                    int srow = gr >> 7, b = gr & 127;
                    float2 p2 = *(const float2*)(pos + (size_t)srow * 1024 + gc);
                    int r_out = b * 64 + srow;
                    *(__half2*)(C + afrag_h(r_out, gc)) =
                        __floats2half2_rn(v0 + p2.x, v1 + p2.y);
                } else {
                    float* C = (float*)Cv;
                    int b = gr >> 6, s = gr & 63;
                    float2 o; o.x = v0; o.y = v1;
                    *(float2*)(C + (size_t)(s * 128 + b) * N + gc) = o;
                }
            }
        }
    }
}

#define GSMEM_T256 (4 * (16384 + 256 * 64 * 2))   // 196608
#define GSMEM_T384 (3 * (16384 + 384 * 64 * 2))   // 196608

// ---------------------------------------------------------------------------
// Attention stage B: L=64, dh=128, half qkv input. One CTA per (b, head).
// ---------------------------------------------------------------------------
#define A2_LD 130
#define A2_SMEM ((3 * 64 * A2_LD + 64 * 65) * 4)

__global__ void __launch_bounds__(256) attn2_kernel(
    const __half* __restrict__ qkv2, __half* __restrict__ out)
{
    extern __shared__ float smf[];
    float* qs = smf;
    float* ks = qs + 64 * A2_LD;
    float* vs = ks + 64 * A2_LD;
    float* ps = vs + 64 * A2_LD;

    const int b = blockIdx.x >> 3;
    const int h = blockIdx.x & 7;
    const int tid = threadIdx.x;

    for (int p = tid; p < 64 * 32; p += 256) {
        int r = p >> 5, c4 = (p & 31) << 2;
        const __half* src = qkv2 + (size_t)(b * 64 + r) * 3072 + h * 128 + c4;
        float4 xq = ld_half4(src);
        float4 xk = ld_half4(src + 1024);
        float4 xv = ld_half4(src + 2048);
        float* qd = qs + r * A2_LD + c4;
        float* kd = ks + r * A2_LD + c4;
        float* vd = vs + r * A2_LD + c4;
        qd[0] = xq.x; qd[1] = xq.y; qd[2] = xq.z; qd[3] = xq.w;
        kd[0] = xk.x; kd[1] = xk.y; kd[2] = xk.z; kd[3] = xk.w;
        vd[0] = xv.x; vd[1] = xv.y; vd[2] = xv.z; vd[3] = xv.w;
    }
    __syncthreads();

    const int w = tid >> 5, l = tid & 31;
    const float scale = 0.08838834764831845f;

    for (int r = 0; r < 8; r++) {
        int i = w * 8 + r;
        const float* qp = qs + i * A2_LD;
        const float* k0 = ks + l * A2_LD;
        const float* k1 = ks + (l + 32) * A2_LD;
        float s0 = 0.f, s1 = 0.f;
#pragma unroll 8
        for (int d = 0; d < 128; d++) {
            float qv = qp[d];
            s0 += qv * k0[d];
            s1 += qv * k1[d];
        }
        ps[i * 65 + l]      = s0 * scale;
        ps[i * 65 + l + 32] = s1 * scale;
    }
    __syncwarp();

    for (int r = 0; r < 8; r++) {
        int i = w * 8 + r;
        float a0 = ps[i * 65 + l], a1 = ps[i * 65 + l + 32];
        float m = fmaxf(a0, a1);
#pragma unroll
        for (int o = 16; o > 0; o >>= 1)
            m = fmaxf(m, __shfl_xor_sync(0xffffffffu, m, o));
        float e0 = __expf(a0 - m), e1 = __expf(a1 - m);
        float s = e0 + e1;
#pragma unroll
        for (int o = 16; o > 0; o >>= 1)
            s += __shfl_xor_sync(0xffffffffu, s, o);
        float inv = 1.0f / s;
        ps[i * 65 + l]      = e0 * inv;
        ps[i * 65 + l + 32] = e1 * inv;
    }
    __syncwarp();

    for (int r = 0; r < 8; r++) {
        int i = w * 8 + r;
        const float* pr = ps + i * 65;
        float a0 = 0.f, a1 = 0.f, a2 = 0.f, a3 = 0.f;
#pragma unroll 4
        for (int j = 0; j < 64; j++) {
            float pj = pr[j];
            const float* vp = vs + j * A2_LD;
            float2 lo = *(const float2*)(vp + 2 * l);
            float2 hi = *(const float2*)(vp + 2 * l + 64);
            a0 += pj * lo.x; a1 += pj * lo.y;
            a2 += pj * hi.x; a3 += pj * hi.y;
        }
        int row = b * 64 + i, cb = h * 128 + 2 * l;
        *(__half2*)(out + afrag_h(row, cb))      = __floats2half2_rn(a0, a1);
        *(__half2*)(out + afrag_h(row, cb + 64)) = __floats2half2_rn(a2, a3);
    }
}

// ---------------------------------------------------------------------------
extern "C" void kernel_launch(void* const* d_in, const int* in_sizes, int n_in,
                              void* d_out, int out_size)
{
    (void)in_sizes; (void)n_in; (void)out_size;
    const float* hid      = (const float*)d_in[0];
    const float* mf_in_w  = (const float*)d_in[1];
    const float* mf_in_b  = (const float*)d_in[2];
    const float* mf_out_w = (const float*)d_in[3];
    const float* mf_out_b = (const float*)d_in[4];
    const float* sf_in_w  = (const float*)d_in[5];
    const float* sf_in_b  = (const float*)d_in[6];
    const float* sf_out_w = (const float*)d_in[7];
    const float* sf_out_b = (const float*)d_in[8];
    const float* pos_enc  = (const float*)d_in[9];
    float* out = (float*)d_out;

    __half *hidA, *wmin, *wmout, *wsin, *wsout, *meanb, *seq, *qkv2, *att2;
    cudaGetSymbolAddress((void**)&hidA,  g_hidA);
    cudaGetSymbolAddress((void**)&wmin,  g_wmin);
    cudaGetSymbolAddress((void**)&wmout, g_wmout);
    cudaGetSymbolAddress((void**)&wsin,  g_wsin);
    cudaGetSymbolAddress((void**)&wsout, g_wsout);
    cudaGetSymbolAddress((void**)&meanb, g_mean);
    cudaGetSymbolAddress((void**)&seq,   g_seq);
    cudaGetSymbolAddress((void**)&qkv2,  g_qkv2);
    cudaGetSymbolAddress((void**)&att2,  g_att2);

    cudaFuncSetAttribute(conv_hidden,
        cudaFuncAttributeMaxDynamicSharedMemorySize, CONV_SMEM);
    cudaFuncSetAttribute(conv_w4,
        cudaFuncAttributeMaxDynamicSharedMemorySize, CONV_SMEM);
    cudaFuncSetAttribute((tgemm2<3, 384, 384>),
        cudaFuncAttributeMaxDynamicSharedMemorySize, GSMEM_T384);
    cudaFuncSetAttribute((tgemm2<0, 256, 256>),
        cudaFuncAttributeMaxDynamicSharedMemorySize, GSMEM_T256);
    cudaFuncSetAttribute((tgemm2<1, 256, 256>),
        cudaFuncAttributeMaxDynamicSharedMemorySize, GSMEM_T256);
    cudaFuncSetAttribute((tgemm2<2, 256, 256>),
        cudaFuncAttributeMaxDynamicSharedMemorySize, GSMEM_T256);
    cudaFuncSetAttribute(attn2_kernel,
        cudaFuncAttributeMaxDynamicSharedMemorySize, A2_SMEM);

    // ---- prepass: fragment-order + fp16-round all GEMM inputs ----
    conv_hidden<<<2048, 256, CONV_SMEM>>>(hid, hidA);
    conv_w4<<<512, 256, CONV_SMEM>>>(mf_in_w, mf_out_w, sf_in_w, sf_out_w,
                                     wmin, wmout, wsin, wsout);

    // Stage A: fused qkv GEMM + L=4 attention + mean -> meanb (A-frag half)
    tgemm2<3, 384, 384><<<dim3(8, 256), 384, GSMEM_T384>>>(
        hidA, wmin, mf_in_b, nullptr, meanb, 384);
    // Stage A out-proj + transpose to [B,S,H] + pos_enc   -> A-frag half
    tgemm2<1, 256, 256><<<dim3(4, 64), 256, GSMEM_T256>>>(
        meanb, wmout, mf_out_b, pos_enc, seq, 1024);
    // Stage B: qkv2 = seq @ sf_in_w^T + b                 [8192 x 3072] half
    tgemm2<0, 256, 256><<<dim3(12, 64), 256, GSMEM_T256>>>(
        seq, wsin, sf_in_b, nullptr, qkv2, 3072);
    // Stage B attention (L=64)                            -> A-frag half
    attn2_kernel<<<1024, 256, A2_SMEM>>>(qkv2, att2);
    // Stage B out-proj + transpose to [S,B,1,H]           -> d_out (float)
    tgemm2<2, 256, 256><<<dim3(4, 64), 256, GSMEM_T256>>>(
        att2, wsout, sf_out_b, nullptr, out, 1024);
}

// round 10
// speedup vs baseline: 6.9660x; 1.0619x over previous
#include <cuda_runtime.h>
#include <cuda_fp16.h>
#include <cstdint>
#include <math.h>

// ---------------------------------------------------------------------------
// HierarchicalModelFusion — fp16 mma.sync (m16n8k16, f32 accum),
// fragment-ordered packed-half operands, cp.async pipeline (4-stage TN=256,
// 3-stage TN=384). BOTH attention stages are fused into their qkv GEMM
// epilogues via head-major weight permutation (TN=384 tile = one head's
// q|k|v). qkv tensors never touch DRAM. GEMMs run at the legacy-HMMA
// f32-accumulate ceiling (~512 MAC/cyc/SM).
// ---------------------------------------------------------------------------

#define KD 1024

// Scratch (device globals)
__device__ __align__(256) __half g_hidA[(size_t)32768 * 1024];  // A-frag
__device__ __align__(256) __half g_wmin[(size_t)3072 * 1024];   // B-frag TN=384 head-perm
__device__ __align__(256) __half g_wmout[(size_t)1024 * 1024];  // B-frag TN=256
__device__ __align__(256) __half g_wsin[(size_t)3072 * 1024];   // B-frag TN=384 head-perm
__device__ __align__(256) __half g_wsout[(size_t)1024 * 1024];  // B-frag TN=256
__device__ __align__(256) __half g_mean[(size_t)8192 * 1024];   // A-frag
__device__ __align__(256) __half g_seq [(size_t)8192 * 1024];   // A-frag
__device__ __align__(256) __half g_att2[(size_t)8192 * 1024];   // A-frag

__device__ __forceinline__ uint32_t h2_u32(__half2 h) {
    return *reinterpret_cast<uint32_t*>(&h);
}
__device__ __forceinline__ float4 ld_half4(const __half* p) {
    uint2 raw = *(const uint2*)p;
    float2 a = __half22float2(*(__half2*)&raw.x);
    float2 b = __half22float2(*(__half2*)&raw.y);
    return make_float4(a.x, a.y, b.x, b.y);
}

// A-frag (m16n8k16 A operand) index for a [rows,1024] half matrix.
__device__ __forceinline__ size_t afrag_h(int r, int c) {
    int mt = r >> 7, mb = (r >> 4) & 7, ri = r & 15;
    int kt = c >> 6, kb = (c >> 4) & 3, ci = c & 15;
    int lane = (ri & 7) * 4 + ((ci & 7) >> 1);
    int idx = (ci & 1) + 2 * ((ri >> 3) & 1) + 4 * ((ci >> 3) & 1);
    return ((size_t)(mt * 16 + kt) << 13) + ((kb * 8 + mb) << 8) + (lane << 3) + idx;
}

__device__ __forceinline__ void mma_f16(float* d, uint32_t a0, uint32_t a1,
                                        uint32_t a2, uint32_t a3,
                                        uint32_t b0, uint32_t b1) {
    asm volatile(
        "mma.sync.aligned.m16n8k16.row.col.f32.f16.f16.f32 "
        "{%0,%1,%2,%3}, {%4,%5,%6,%7}, {%8,%9}, {%0,%1,%2,%3};"
        : "+f"(d[0]), "+f"(d[1]), "+f"(d[2]), "+f"(d[3])
        : "r"(a0), "r"(a1), "r"(a2), "r"(a3), "r"(b0), "r"(b1));
}

__device__ __forceinline__ void cp16(uint32_t dst, const void* src) {
    asm volatile("cp.async.cg.shared.global [%0], [%1], 16;"
                 :: "r"(dst), "l"(src));
}
__device__ __forceinline__ uint32_t smem_u32(const void* p) {
    uint32_t a;
    asm("{ .reg .u64 t; cvta.to.shared.u64 t, %1; cvt.u32.u64 %0, t; }"
        : "=r"(a) : "l"(p));
    return a;
}

// ---------------------------------------------------------------------------
// Unified prepass (ONE launch):
//   blocks [0,2048):     hidden[S,M,B,1,H] -> gathered A-frag halves
//   blocks [2048,2240):  mf_in_w  -> B-frag TN=384 head-permuted
//   blocks [2240,2304):  mf_out_w -> B-frag TN=256
//   blocks [2304,2496):  sf_in_w  -> B-frag TN=384 head-permuted
//   blocks [2496,2560):  sf_out_w -> B-frag TN=256
// ---------------------------------------------------------------------------
#define CONV_SMEM (16 * 1028 * 4)
__global__ void __launch_bounds__(256) conv_all(
    const float* __restrict__ hid, __half* __restrict__ Af,
    const float* __restrict__ w0, const float* __restrict__ w1,
    const float* __restrict__ w2, const float* __restrict__ w3,
    __half* __restrict__ o0, __half* __restrict__ o1,
    __half* __restrict__ o2, __half* __restrict__ o3)
{
    extern __shared__ float tile[];    // [16][1028]
    const int tid = threadIdx.x;

    if (blockIdx.x < 2048) {
        const int nb = blockIdx.x;
#pragma unroll
        for (int i = 0; i < 16; i++) {
            int idx = tid + 256 * i;
            int r = idx >> 8, c4 = idx & 255;
            int n = nb * 16 + r;
            int s = n >> 9, b = (n >> 2) & 127, m = n & 3;
            float4 v = *(const float4*)(hid + (((size_t)((s * 4 + m) * 128 + b)) << 10)
                                            + (c4 << 2));
            *(float4*)&tile[r * 1028 + c4 * 4] = v;
        }
        __syncthreads();
        const int mt = nb >> 3, mb = nb & 7;
#pragma unroll
        for (int j = 0; j < 8; j++) {
            int g = tid + 256 * j;
            int kt = g >> 7, rr = g & 127, kb = rr >> 5, ln = rr & 31;
            int grp = ln >> 2, tig = ln & 3;
            int c0 = kt * 64 + kb * 16 + 2 * tig;
            __half2 p0 = __floats2half2_rn(tile[grp * 1028 + c0],
                                           tile[grp * 1028 + c0 + 1]);
            __half2 p1 = __floats2half2_rn(tile[(grp + 8) * 1028 + c0],
                                           tile[(grp + 8) * 1028 + c0 + 1]);
            __half2 p2 = __floats2half2_rn(tile[grp * 1028 + c0 + 8],
                                           tile[grp * 1028 + c0 + 9]);
            __half2 p3 = __floats2half2_rn(tile[(grp + 8) * 1028 + c0 + 8],
                                           tile[(grp + 8) * 1028 + c0 + 9]);
            uint4 o;
            o.x = h2_u32(p0); o.y = h2_u32(p1);
            o.z = h2_u32(p2); o.w = h2_u32(p3);
            *(uint4*)(Af + ((size_t)(mt * 16 + kt) << 13) + ((kb * 8 + mb) << 8)
                         + (ln << 3)) = o;
        }
        return;
    }

    int gid = blockIdx.x - 2048;
    const float* W; __half* Bf;
    bool perm384 = false;
    if (gid < 192)      { W = w0; Bf = o0; perm384 = true; }
    else if (gid < 256) { W = w1; Bf = o1; gid -= 192; }
    else if (gid < 448) { W = w2; Bf = o2; gid -= 256; perm384 = true; }
    else                { W = w3; Bf = o3; gid -= 448; }
#pragma unroll
    for (int i = 0; i < 16; i++) {
        int idx = tid + 256 * i;
        int r = idx >> 8, c4 = idx & 255;
        float4 v = *(const float4*)(W + ((size_t)(gid * 16 + r) << 10) + (c4 << 2));
        *(float4*)&tile[r * 1028 + c4 * 4] = v;
    }
    __syncthreads();

    int ntile, gblk, ngroups;
    if (perm384) {
        int j0 = gid * 16;
        int p = j0 >> 10, rem = j0 & 1023;
        int h = rem >> 7, d0 = rem & 127;
        ntile = h;                     // 384-wide tile = head
        gblk = p * 8 + (d0 >> 4);      // 16-col group within 384 (24 groups)
        ngroups = 24;
    } else {
        ntile = gid >> 4;
        gblk = gid & 15;
        ngroups = 16;
    }

#pragma unroll
    for (int j = 0; j < 8; j++) {
        int g = tid + 256 * j;
        int kt = g >> 7, rr = g & 127, kb = rr >> 5, ln = rr & 31;
        int grp = ln >> 2, tig = ln & 3;
        int c0 = kt * 64 + kb * 16 + 2 * tig;
        __half2 p0 = __floats2half2_rn(tile[grp * 1028 + c0],
                                       tile[grp * 1028 + c0 + 1]);
        __half2 p1 = __floats2half2_rn(tile[grp * 1028 + c0 + 8],
                                       tile[grp * 1028 + c0 + 9]);
        __half2 p2 = __floats2half2_rn(tile[(grp + 8) * 1028 + c0],
                                       tile[(grp + 8) * 1028 + c0 + 1]);
        __half2 p3 = __floats2half2_rn(tile[(grp + 8) * 1028 + c0 + 8],
                                       tile[(grp + 8) * 1028 + c0 + 9]);
        uint4 o;
        o.x = h2_u32(p0); o.y = h2_u32(p1);
        o.z = h2_u32(p2); o.w = h2_u32(p3);
        size_t off = ((size_t)(ntile * 16 + kt) * (ngroups * 16 * 64))
                   + ((size_t)(kb * ngroups + gblk) << 8) + (ln << 3);
        *(uint4*)(Bf + off) = o;
    }
}

// ---------------------------------------------------------------------------
// GEMM: C = A @ W^T + bias. CTA 128xTN, warp 64x64, K chunks of 64 halves.
// NSTAGE = 4 for TN=256, 3 for TN=384.
// EPI 1: transpose [B,S,H] + pos_enc -> half A-frag (TN=256)
// EPI 2: transpose [S,B,H] -> float store, final out (TN=256)
// EPI 3: FUSED stage-A attention (TN=384, head=bn, L=4 x32 groups) -> A-frag
// EPI 4: FUSED stage-B attention (TN=384, head=bn, L=64 x2 problems) -> A-frag
// ---------------------------------------------------------------------------
template <int EPI, int TN, int NT>
__global__ void __launch_bounds__(NT, 1) tgemm2(
    const __half* __restrict__ Af, const __half* __restrict__ Bf,
    const float* __restrict__ bias, const float* __restrict__ pos,
    void* __restrict__ Cv, int N)
{
    constexpr int NWARP = NT / 32;          // 8 or 12
    constexpr int BCH = TN * 64 * 2;        // B bytes per chunk
    constexpr int SSTAGE = 16384 + BCH;     // stage bytes (49152 or 65536)
    constexpr int BGRP = TN / 16;           // 16-col groups per tile
    constexpr int NSTAGE = (TN == 384) ? 3 : 4;

    extern __shared__ char smem_raw[];
    const uint32_t sb = smem_u32(smem_raw);
    const int tid = threadIdx.x, wid = tid >> 5, lane = tid & 31;
    const int bm = blockIdx.y, bn = blockIdx.x;

    const uint4* Af4 = (const uint4*)Af + ((size_t)bm << 14) + tid;
    const uint4* Bf4 = (const uint4*)Bf + (size_t)bn * (TN * 128) + tid;
    const uint32_t adst = sb + tid * 16;
    const uint32_t bdst = sb + 16384 + tid * 16;

    auto issue = [&](int kt, int s) {
        if (NT == 256 || tid < 256) {
            const uint4* a = Af4 + (kt << 10);
            uint32_t ad = adst + s * SSTAGE;
#pragma unroll
            for (int i = 0; i < 4; i++) cp16(ad + i * 4096, a + i * 256);
        }
        const uint4* b = Bf4 + kt * (TN * 8);
        uint32_t bd = bdst + s * SSTAGE;
#pragma unroll
        for (int i = 0; i < 8; i++)
            cp16(bd + i * (NT * 16), b + i * NT);
        asm volatile("cp.async.commit_group;" ::: "memory");
    };

    float acc[4][8][4];
#pragma unroll
    for (int mt = 0; mt < 4; mt++)
#pragma unroll
        for (int nt = 0; nt < 8; nt++)
#pragma unroll
            for (int e = 0; e < 4; e++) acc[mt][nt][e] = 0.0f;

    const int wmb = (wid & 1) * 4;     // A 16-row block base
    const int wnb = (wid >> 1) * 4;    // B 16-col group base

    issue(0, 0);
    issue(1, 1);
    if (NSTAGE == 4) issue(2, 2);

#pragma unroll 1
    for (int c = 0; c < 16; c++) {
        if (NSTAGE == 4) {
            if (c < 14)       asm volatile("cp.async.wait_group 2;" ::: "memory");
            else if (c == 14) asm volatile("cp.async.wait_group 1;" ::: "memory");
            else              asm volatile("cp.async.wait_group 0;" ::: "memory");
        } else {
            if (c < 15)       asm volatile("cp.async.wait_group 1;" ::: "memory");
            else              asm volatile("cp.async.wait_group 0;" ::: "memory");
        }
        __syncthreads();
        if (c + NSTAGE - 1 < 16)
            issue(c + NSTAGE - 1, (c + NSTAGE - 1) % NSTAGE);

        const __half* sA = (const __half*)(smem_raw + (c % NSTAGE) * SSTAGE);
        const __half* sB = sA + 8192;
#pragma unroll
        for (int kb = 0; kb < 4; kb++) {
            uint4 af[4];
#pragma unroll
            for (int mt = 0; mt < 4; mt++)
                af[mt] = *(const uint4*)(sA + ((kb * 8 + wmb + mt) << 8) + (lane << 3));
#pragma unroll
            for (int gt = 0; gt < 4; gt++) {
                uint4 bb = *(const uint4*)(sB + ((kb * BGRP + wnb + gt) << 8) + (lane << 3));
#pragma unroll
                for (int mt = 0; mt < 4; mt++) {
                    mma_f16(acc[mt][2 * gt],     af[mt].x, af[mt].y, af[mt].z, af[mt].w,
                            bb.x, bb.y);
                    mma_f16(acc[mt][2 * gt + 1], af[mt].x, af[mt].y, af[mt].z, af[mt].w,
                            bb.z, bb.w);
                }
            }
        }
    }

    const int grp = lane >> 2, tig = lane & 3;
    const int wm = (wid & 1) * 64, wn = (wid >> 1) * 64;

    if (EPI == 3 || EPI == 4) {
        // ---- fused attention epilogues (TN=384, head = bn) ----
        constexpr int ALD = 392;
        __half* sAtt = (__half*)smem_raw;     // 128 x 392 halves = 100352 B
        __syncthreads();                       // pipeline smem reads all done
        // dump acc + permuted bias: cols [q 0..127 | k 128..255 | v 256..383]
#pragma unroll
        for (int mt = 0; mt < 4; mt++) {
#pragma unroll
            for (int h = 0; h < 2; h++) {
                int lr = wm + mt * 16 + grp + 8 * h;
#pragma unroll
                for (int nt = 0; nt < 8; nt++) {
                    int lc = wn + nt * 8 + 2 * tig;
                    int p = lc >> 7, d = lc & 127;
                    int j = p * 1024 + bn * 128 + d;
                    float2 b2 = *(const float2*)(bias + j);
                    *(__half2*)(sAtt + lr * ALD + lc) =
                        __floats2half2_rn(acc[mt][nt][2 * h] + b2.x,
                                          acc[mt][nt][2 * h + 1] + b2.y);
                }
            }
        }
        __syncthreads();

        __half* outp = (__half*)Cv;
        const float scale = 0.08838834764831845f;
        const int l = lane;

        if (EPI == 3) {
            // 32 L=4 groups (4 consecutive rows each); mean over models folded
            for (int g = wid; g < 32; g += NWARP) {
                float4 q[4], k[4], v[4];
#pragma unroll
                for (int i = 0; i < 4; i++) {
                    const __half* rp = sAtt + (4 * g + i) * ALD;
                    q[i] = ld_half4(rp + 4 * l);
                    k[i] = ld_half4(rp + 128 + 4 * l);
                    v[i] = ld_half4(rp + 256 + 4 * l);
                }
                float sc[4][4];
#pragma unroll
                for (int i = 0; i < 4; i++)
#pragma unroll
                    for (int j = 0; j < 4; j++)
                        sc[i][j] = q[i].x * k[j].x + q[i].y * k[j].y +
                                   q[i].z * k[j].z + q[i].w * k[j].w;
#pragma unroll
                for (int o = 16; o > 0; o >>= 1)
#pragma unroll
                    for (int i = 0; i < 4; i++)
#pragma unroll
                        for (int j = 0; j < 4; j++)
                            sc[i][j] += __shfl_xor_sync(0xffffffffu, sc[i][j], o);

                float wj[4] = {0.f, 0.f, 0.f, 0.f};
#pragma unroll
                for (int i = 0; i < 4; i++) {
                    float s0 = sc[i][0] * scale, s1 = sc[i][1] * scale;
                    float s2 = sc[i][2] * scale, s3 = sc[i][3] * scale;
                    float m = fmaxf(fmaxf(s0, s1), fmaxf(s2, s3));
                    float e0 = __expf(s0 - m), e1 = __expf(s1 - m);
                    float e2 = __expf(s2 - m), e3 = __expf(s3 - m);
                    float inv = 0.25f / (e0 + e1 + e2 + e3);
                    wj[0] += e0 * inv; wj[1] += e1 * inv;
                    wj[2] += e2 * inv; wj[3] += e3 * inv;
                }
                float4 o = {0.f, 0.f, 0.f, 0.f};
#pragma unroll
                for (int j = 0; j < 4; j++) {
                    o.x += wj[j] * v[j].x; o.y += wj[j] * v[j].y;
                    o.z += wj[j] * v[j].z; o.w += wj[j] * v[j].w;
                }
                int row = bm * 32 + g;
                int cb = bn * 128 + 4 * l;
                *(__half2*)(outp + afrag_h(row, cb))     = __floats2half2_rn(o.x, o.y);
                *(__half2*)(outp + afrag_h(row, cb + 2)) = __floats2half2_rn(o.z, o.w);
            }
        } else {
            // EPI 4: two L=64 problems (rows [0,64) and [64,128))
            float* ps = (float*)(smem_raw + 128 * ALD * 2);   // [2][64][65] f32
            const int pid = wid / 6, wl = wid - pid * 6;       // 6 warps/problem
            const int rb = pid * 64;
            float* psp = ps + pid * (64 * 65);
            for (int i = wl; i < 64; i += 6) {
                const __half* qp = sAtt + (rb + i) * ALD;
                const __half* k0 = sAtt + (rb + l) * ALD + 128;
                const __half* k1 = sAtt + (rb + l + 32) * ALD + 128;
                float s0 = 0.f, s1 = 0.f;
#pragma unroll 8
                for (int d = 0; d < 128; d += 4) {
                    float4 qv = ld_half4(qp + d);
                    float4 ka = ld_half4(k0 + d);
                    float4 kb = ld_half4(k1 + d);
                    s0 += qv.x * ka.x + qv.y * ka.y + qv.z * ka.z + qv.w * ka.w;
                    s1 += qv.x * kb.x + qv.y * kb.y + qv.z * kb.z + qv.w * kb.w;
                }
                s0 *= scale; s1 *= scale;
                float m = fmaxf(s0, s1);
#pragma unroll
                for (int o = 16; o > 0; o >>= 1)
                    m = fmaxf(m, __shfl_xor_sync(0xffffffffu, m, o));
                float e0 = __expf(s0 - m), e1 = __expf(s1 - m);
                float s = e0 + e1;
#pragma unroll
                for (int o = 16; o > 0; o >>= 1)
                    s += __shfl_xor_sync(0xffffffffu, s, o);
                float inv = 1.0f / s;
                psp[i * 65 + l]      = e0 * inv;
                psp[i * 65 + l + 32] = e1 * inv;
                __syncwarp();
                // PV: lane covers d = {2l, 2l+1, 2l+64, 2l+65}
                float a0 = 0.f, a1 = 0.f, a2 = 0.f, a3 = 0.f;
                const float* pr = psp + i * 65;
#pragma unroll 4
                for (int j = 0; j < 64; j++) {
                    float pj = pr[j];
                    const __half* vp = sAtt + (rb + j) * ALD + 256;
                    float2 lo = __half22float2(*(const __half2*)(vp + 2 * l));
                    float2 hi = __half22float2(*(const __half2*)(vp + 2 * l + 64));
                    a0 += pj * lo.x; a1 += pj * lo.y;
                    a2 += pj * hi.x; a3 += pj * hi.y;
                }
                int row = (bm * 2 + pid) * 64 + i;
                int cb = bn * 128 + 2 * l;
                *(__half2*)(outp + afrag_h(row, cb))      = __floats2half2_rn(a0, a1);
                *(__half2*)(outp + afrag_h(row, cb + 64)) = __floats2half2_rn(a2, a3);
            }
        }
        return;
    }

    // ---- standard epilogues (TN=256) ----
#pragma unroll
    for (int mt = 0; mt < 4; mt++) {
#pragma unroll
        for (int h = 0; h < 2; h++) {
            int gr = bm * 128 + wm + mt * 16 + grp + 8 * h;
#pragma unroll
            for (int nt = 0; nt < 8; nt++) {
                int gc = bn * TN + wn + nt * 8 + 2 * tig;
                float2 b2 = *(const float2*)(bias + gc);
                float v0 = acc[mt][nt][2 * h]     + b2.x;
                float v1 = acc[mt][nt][2 * h + 1] + b2.y;
                if (EPI == 1) {
                    __half* C = (__half*)Cv;
                    int srow = gr >> 7, b = gr & 127;
                    float2 p2 = *(const float2*)(pos + (size_t)srow * 1024 + gc);
                    int r_out = b * 64 + srow;
                    *(__half2*)(C + afrag_h(r_out, gc)) =
                        __floats2half2_rn(v0 + p2.x, v1 + p2.y);
                } else {
                    float* C = (float*)Cv;
                    int b = gr >> 6, s = gr & 63;
                    float2 o; o.x = v0; o.y = v1;
                    *(float2*)(C + (size_t)(s * 128 + b) * N + gc) = o;
                }
            }
        }
    }
}

#define GSMEM_T256 (4 * (16384 + 256 * 64 * 2))   // 196608
#define GSMEM_T384 (3 * (16384 + 384 * 64 * 2))   // 196608

// ---------------------------------------------------------------------------
extern "C" void kernel_launch(void* const* d_in, const int* in_sizes, int n_in,
                              void* d_out, int out_size)
{
    (void)in_sizes; (void)n_in; (void)out_size;
    const float* hid      = (const float*)d_in[0];
    const float* mf_in_w  = (const float*)d_in[1];
    const float* mf_in_b  = (const float*)d_in[2];
    const float* mf_out_w = (const float*)d_in[3];
    const float* mf_out_b = (const float*)d_in[4];
    const float* sf_in_w  = (const float*)d_in[5];
    const float* sf_in_b  = (const float*)d_in[6];
    const float* sf_out_w = (const float*)d_in[7];
    const float* sf_out_b = (const float*)d_in[8];
    const float* pos_enc  = (const float*)d_in[9];
    float* out = (float*)d_out;

    __half *hidA, *wmin, *wmout, *wsin, *wsout, *meanb, *seq, *att2;
    cudaGetSymbolAddress((void**)&hidA,  g_hidA);
    cudaGetSymbolAddress((void**)&wmin,  g_wmin);
    cudaGetSymbolAddress((void**)&wmout, g_wmout);
    cudaGetSymbolAddress((void**)&wsin,  g_wsin);
    cudaGetSymbolAddress((void**)&wsout, g_wsout);
    cudaGetSymbolAddress((void**)&meanb, g_mean);
    cudaGetSymbolAddress((void**)&seq,   g_seq);
    cudaGetSymbolAddress((void**)&att2,  g_att2);

    cudaFuncSetAttribute(conv_all,
        cudaFuncAttributeMaxDynamicSharedMemorySize, CONV_SMEM);
    cudaFuncSetAttribute((tgemm2<3, 384, 384>),
        cudaFuncAttributeMaxDynamicSharedMemorySize, GSMEM_T384);
    cudaFuncSetAttribute((tgemm2<4, 384, 384>),
        cudaFuncAttributeMaxDynamicSharedMemorySize, GSMEM_T384);
    cudaFuncSetAttribute((tgemm2<1, 256, 256>),
        cudaFuncAttributeMaxDynamicSharedMemorySize, GSMEM_T256);
    cudaFuncSetAttribute((tgemm2<2, 256, 256>),
        cudaFuncAttributeMaxDynamicSharedMemorySize, GSMEM_T256);

    // ---- unified prepass: gather + fragment-order + fp16-round everything
    conv_all<<<2560, 256, CONV_SMEM>>>(hid, hidA,
                                       mf_in_w, mf_out_w, sf_in_w, sf_out_w,
                                       wmin, wmout, wsin, wsout);

    // Stage A: fused qkv GEMM + L=4 attention + model-mean -> meanb (A-frag)
    tgemm2<3, 384, 384><<<dim3(8, 256), 384, GSMEM_T384>>>(
        hidA, wmin, mf_in_b, nullptr, meanb, 384);
    // Stage A out-proj + transpose to [B,S,H] + pos_enc   -> seq (A-frag)
    tgemm2<1, 256, 256><<<dim3(4, 64), 256, GSMEM_T256>>>(
        meanb, wmout, mf_out_b, pos_enc, seq, 1024);
    // Stage B: fused qkv GEMM + L=64 attention            -> att2 (A-frag)
    tgemm2<4, 384, 384><<<dim3(8, 64), 384, GSMEM_T384>>>(
        seq, wsin, sf_in_b, nullptr, att2, 384);
    // Stage B out-proj + transpose to [S,B,1,H]           -> d_out (float)
    tgemm2<2, 256, 256><<<dim3(4, 64), 256, GSMEM_T256>>>(
        att2, wsout, sf_out_b, nullptr, out, 1024);
}

// round 15
// speedup vs baseline: 7.9832x; 1.1460x over previous
#include <cuda_runtime.h>
#include <cuda_fp16.h>
#include <cstdint>
#include <math.h>

// ---------------------------------------------------------------------------
// HierarchicalModelFusion — fp16 mma.sync (m16n8k16, f32 accum),
// fragment-ordered packed-half operands, cp.async pipeline (4-stage TN=256,
// 3-stage TN=384). BOTH attention stages fused into their qkv GEMM epilogues
// via head-major weight permutation. Stage-B epilogue attention is itself
// TENSORIZED: q/k/v are dumped straight into mma fragment layouts in smem,
// QK^T and PV run on HMMA, P stays in registers (C-frag -> A-frag identity).
// ---------------------------------------------------------------------------

#define KD 1024

// Scratch (device globals)
__device__ __align__(256) __half g_hidA[(size_t)32768 * 1024];  // A-frag
__device__ __align__(256) __half g_wmin[(size_t)3072 * 1024];   // B-frag TN=384 head-perm
__device__ __align__(256) __half g_wmout[(size_t)1024 * 1024];  // B-frag TN=256
__device__ __align__(256) __half g_wsin[(size_t)3072 * 1024];   // B-frag TN=384 head-perm
__device__ __align__(256) __half g_wsout[(size_t)1024 * 1024];  // B-frag TN=256
__device__ __align__(256) __half g_mean[(size_t)8192 * 1024];   // A-frag
__device__ __align__(256) __half g_seq [(size_t)8192 * 1024];   // A-frag
__device__ __align__(256) __half g_att2[(size_t)8192 * 1024];   // A-frag

__device__ __forceinline__ uint32_t h2_u32(__half2 h) {
    return *reinterpret_cast<uint32_t*>(&h);
}
__device__ __forceinline__ float4 ld_half4(const __half* p) {
    uint2 raw = *(const uint2*)p;
    float2 a = __half22float2(*(__half2*)&raw.x);
    float2 b = __half22float2(*(__half2*)&raw.y);
    return make_float4(a.x, a.y, b.x, b.y);
}

// A-frag (m16n8k16 A operand) index for a [rows,1024] half matrix.
__device__ __forceinline__ size_t afrag_h(int r, int c) {
    int mt = r >> 7, mb = (r >> 4) & 7, ri = r & 15;
    int kt = c >> 6, kb = (c >> 4) & 3, ci = c & 15;
    int lane = (ri & 7) * 4 + ((ci & 7) >> 1);
    int idx = (ci & 1) + 2 * ((ri >> 3) & 1) + 4 * ((ci >> 3) & 1);
    return ((size_t)(mt * 16 + kt) << 13) + ((kb * 8 + mb) << 8) + (lane << 3) + idx;
}

__device__ __forceinline__ void mma_f16(float* d, uint32_t a0, uint32_t a1,
                                        uint32_t a2, uint32_t a3,
                                        uint32_t b0, uint32_t b1) {
    asm volatile(
        "mma.sync.aligned.m16n8k16.row.col.f32.f16.f16.f32 "
        "{%0,%1,%2,%3}, {%4,%5,%6,%7}, {%8,%9}, {%0,%1,%2,%3};"
        : "+f"(d[0]), "+f"(d[1]), "+f"(d[2]), "+f"(d[3])
        : "r"(a0), "r"(a1), "r"(a2), "r"(a3), "r"(b0), "r"(b1));
}

__device__ __forceinline__ void cp16(uint32_t dst, const void* src) {
    asm volatile("cp.async.cg.shared.global [%0], [%1], 16;"
                 :: "r"(dst), "l"(src));
}
__device__ __forceinline__ uint32_t smem_u32(const void* p) {
    uint32_t a;
    asm("{ .reg .u64 t; cvta.to.shared.u64 t, %1; cvt.u32.u64 %0, t; }"
        : "=r"(a) : "l"(p));
    return a;
}

// ---------------------------------------------------------------------------
// Unified prepass (ONE launch):
//   blocks [0,2048):     hidden[S,M,B,1,H] -> gathered A-frag halves
//   blocks [2048,2240):  mf_in_w  -> B-frag TN=384 head-permuted
//   blocks [2240,2304):  mf_out_w -> B-frag TN=256
//   blocks [2304,2496):  sf_in_w  -> B-frag TN=384 head-permuted
//   blocks [2496,2560):  sf_out_w -> B-frag TN=256
// ---------------------------------------------------------------------------
#define CONV_SMEM (16 * 1028 * 4)
__global__ void __launch_bounds__(256) conv_all(
    const float* __restrict__ hid, __half* __restrict__ Af,
    const float* __restrict__ w0, const float* __restrict__ w1,
    const float* __restrict__ w2, const float* __restrict__ w3,
    __half* __restrict__ o0, __half* __restrict__ o1,
    __half* __restrict__ o2, __half* __restrict__ o3)
{
    extern __shared__ float tile[];    // [16][1028]
    const int tid = threadIdx.x;

    if (blockIdx.x < 2048) {
        const int nb = blockIdx.x;
#pragma unroll
        for (int i = 0; i < 16; i++) {
            int idx = tid + 256 * i;
            int r = idx >> 8, c4 = idx & 255;
            int n = nb * 16 + r;
            int s = n >> 9, b = (n >> 2) & 127, m = n & 3;
            float4 v = *(const float4*)(hid + (((size_t)((s * 4 + m) * 128 + b)) << 10)
                                            + (c4 << 2));
            *(float4*)&tile[r * 1028 + c4 * 4] = v;
        }
        __syncthreads();
        const int mt = nb >> 3, mb = nb & 7;
#pragma unroll
        for (int j = 0; j < 8; j++) {
            int g = tid + 256 * j;
            int kt = g >> 7, rr = g & 127, kb = rr >> 5, ln = rr & 31;
            int grp = ln >> 2, tig = ln & 3;
            int c0 = kt * 64 + kb * 16 + 2 * tig;
            __half2 p0 = __floats2half2_rn(tile[grp * 1028 + c0],
                                           tile[grp * 1028 + c0 + 1]);
            __half2 p1 = __floats2half2_rn(tile[(grp + 8) * 1028 + c0],
                                           tile[(grp + 8) * 1028 + c0 + 1]);
            __half2 p2 = __floats2half2_rn(tile[grp * 1028 + c0 + 8],
                                           tile[grp * 1028 + c0 + 9]);
            __half2 p3 = __floats2half2_rn(tile[(grp + 8) * 1028 + c0 + 8],
                                           tile[(grp + 8) * 1028 + c0 + 9]);
            uint4 o;
            o.x = h2_u32(p0); o.y = h2_u32(p1);
            o.z = h2_u32(p2); o.w = h2_u32(p3);
            *(uint4*)(Af + ((size_t)(mt * 16 + kt) << 13) + ((kb * 8 + mb) << 8)
                         + (ln << 3)) = o;
        }
        return;
    }

    int gid = blockIdx.x - 2048;
    const float* W; __half* Bf;
    bool perm384 = false;
    if (gid < 192)      { W = w0; Bf = o0; perm384 = true; }
    else if (gid < 256) { W = w1; Bf = o1; gid -= 192; }
    else if (gid < 448) { W = w2; Bf = o2; gid -= 256; perm384 = true; }
    else                { W = w3; Bf = o3; gid -= 448; }
#pragma unroll
    for (int i = 0; i < 16; i++) {
        int idx = tid + 256 * i;
        int r = idx >> 8, c4 = idx & 255;
        float4 v = *(const float4*)(W + ((size_t)(gid * 16 + r) << 10) + (c4 << 2));
        *(float4*)&tile[r * 1028 + c4 * 4] = v;
    }
    __syncthreads();

    int ntile, gblk, ngroups;
    if (perm384) {
        int j0 = gid * 16;
        int p = j0 >> 10, rem = j0 & 1023;
        int h = rem >> 7, d0 = rem & 127;
        ntile = h;                     // 384-wide tile = head
        gblk = p * 8 + (d0 >> 4);      // 16-col group within 384 (24 groups)
        ngroups = 24;
    } else {
        ntile = gid >> 4;
        gblk = gid & 15;
        ngroups = 16;
    }

#pragma unroll
    for (int j = 0; j < 8; j++) {
        int g = tid + 256 * j;
        int kt = g >> 7, rr = g & 127, kb = rr >> 5, ln = rr & 31;
        int grp = ln >> 2, tig = ln & 3;
        int c0 = kt * 64 + kb * 16 + 2 * tig;
        __half2 p0 = __floats2half2_rn(tile[grp * 1028 + c0],
                                       tile[grp * 1028 + c0 + 1]);
        __half2 p1 = __floats2half2_rn(tile[grp * 1028 + c0 + 8],
                                       tile[grp * 1028 + c0 + 9]);
        __half2 p2 = __floats2half2_rn(tile[(grp + 8) * 1028 + c0],
                                       tile[(grp + 8) * 1028 + c0 + 1]);
        __half2 p3 = __floats2half2_rn(tile[(grp + 8) * 1028 + c0 + 8],
                                       tile[(grp + 8) * 1028 + c0 + 9]);
        uint4 o;
        o.x = h2_u32(p0); o.y = h2_u32(p1);
        o.z = h2_u32(p2); o.w = h2_u32(p3);
        size_t off = ((size_t)(ntile * 16 + kt) * (ngroups * 16 * 64))
                   + ((size_t)(kb * ngroups + gblk) << 8) + (ln << 3);
        *(uint4*)(Bf + off) = o;
    }
}

// ---------------------------------------------------------------------------
// GEMM: C = A @ W^T + bias. CTA 128xTN, warp 64x64, K chunks of 64 halves.
// NSTAGE = 4 for TN=256, 3 for TN=384.
// EPI 1: transpose [B,S,H] + pos_enc -> half A-frag (TN=256)
// EPI 2: transpose [S,B,H] -> float store, final out (TN=256)
// EPI 3: FUSED stage-A attention (TN=384, head=bn, L=4 x32 groups) -> A-frag
// EPI 4: FUSED stage-B attention (TN=384, head=bn, L=64 x2, TENSORIZED)
// ---------------------------------------------------------------------------
template <int EPI, int TN, int NT>
__global__ void __launch_bounds__(NT, 1) tgemm2(
    const __half* __restrict__ Af, const __half* __restrict__ Bf,
    const float* __restrict__ bias, const float* __restrict__ pos,
    void* __restrict__ Cv, int N)
{
    constexpr int NWARP = NT / 32;          // 8 or 12
    constexpr int BCH = TN * 64 * 2;        // B bytes per chunk
    constexpr int SSTAGE = 16384 + BCH;     // stage bytes (49152 or 65536)
    constexpr int BGRP = TN / 16;           // 16-col groups per tile
    constexpr int NSTAGE = (TN == 384) ? 3 : 4;

    extern __shared__ char smem_raw[];
    const uint32_t sb = smem_u32(smem_raw);
    const int tid = threadIdx.x, wid = tid >> 5, lane = tid & 31;
    const int bm = blockIdx.y, bn = blockIdx.x;

    const uint4* Af4 = (const uint4*)Af + ((size_t)bm << 14) + tid;
    const uint4* Bf4 = (const uint4*)Bf + (size_t)bn * (TN * 128) + tid;
    const uint32_t adst = sb + tid * 16;
    const uint32_t bdst = sb + 16384 + tid * 16;

    auto issue = [&](int kt, int s) {
        if (NT == 256 || tid < 256) {
            const uint4* a = Af4 + (kt << 10);
            uint32_t ad = adst + s * SSTAGE;
#pragma unroll
            for (int i = 0; i < 4; i++) cp16(ad + i * 4096, a + i * 256);
        }
        const uint4* b = Bf4 + kt * (TN * 8);
        uint32_t bd = bdst + s * SSTAGE;
#pragma unroll
        for (int i = 0; i < 8; i++)
            cp16(bd + i * (NT * 16), b + i * NT);
        asm volatile("cp.async.commit_group;" ::: "memory");
    };

    float acc[4][8][4];
#pragma unroll
    for (int mt = 0; mt < 4; mt++)
#pragma unroll
        for (int nt = 0; nt < 8; nt++)
#pragma unroll
            for (int e = 0; e < 4; e++) acc[mt][nt][e] = 0.0f;

    const int wmb = (wid & 1) * 4;     // A 16-row block base
    const int wnb = (wid >> 1) * 4;    // B 16-col group base

    issue(0, 0);
    issue(1, 1);
    if (NSTAGE == 4) issue(2, 2);

#pragma unroll 1
    for (int c = 0; c < 16; c++) {
        if (NSTAGE == 4) {
            if (c < 14)       asm volatile("cp.async.wait_group 2;" ::: "memory");
            else if (c == 14) asm volatile("cp.async.wait_group 1;" ::: "memory");
            else              asm volatile("cp.async.wait_group 0;" ::: "memory");
        } else {
            if (c < 15)       asm volatile("cp.async.wait_group 1;" ::: "memory");
            else              asm volatile("cp.async.wait_group 0;" ::: "memory");
        }
        __syncthreads();
        if (c + NSTAGE - 1 < 16)
            issue(c + NSTAGE - 1, (c + NSTAGE - 1) % NSTAGE);

        const __half* sA = (const __half*)(smem_raw + (c % NSTAGE) * SSTAGE);
        const __half* sB = sA + 8192;
#pragma unroll
        for (int kb = 0; kb < 4; kb++) {
            uint4 af[4];
#pragma unroll
            for (int mt = 0; mt < 4; mt++)
                af[mt] = *(const uint4*)(sA + ((kb * 8 + wmb + mt) << 8) + (lane << 3));
#pragma unroll
            for (int gt = 0; gt < 4; gt++) {
                uint4 bb = *(const uint4*)(sB + ((kb * BGRP + wnb + gt) << 8) + (lane << 3));
#pragma unroll
                for (int mt = 0; mt < 4; mt++) {
                    mma_f16(acc[mt][2 * gt],     af[mt].x, af[mt].y, af[mt].z, af[mt].w,
                            bb.x, bb.y);
                    mma_f16(acc[mt][2 * gt + 1], af[mt].x, af[mt].y, af[mt].z, af[mt].w,
                            bb.z, bb.w);
                }
            }
        }
    }

    const int grp = lane >> 2, tig = lane & 3;
    const int wm = (wid & 1) * 64, wn = (wid >> 1) * 64;

    if (EPI == 4) {
        // ---- TENSORIZED stage-B attention epilogue (TN=384, head = bn) ----
        // Dump acc+bias straight into mma fragment layouts in smem:
        //   per problem (24576 halves): Q A-frags [kb8 x mb4], K B-frags
        //   [kb8 x g4], V B-frags transposed (n=d, k=j) [kt4 x dg8].
        __half* sF = (__half*)smem_raw;
        __syncthreads();
#pragma unroll
        for (int mt = 0; mt < 4; mt++) {
#pragma unroll
            for (int h = 0; h < 2; h++) {
                int lr = wm + mt * 16 + grp + 8 * h;
                int pid = lr >> 6, r = lr & 63;
                int base = pid * 24576;
#pragma unroll
                for (int nt = 0; nt < 8; nt++) {
                    int lc = wn + nt * 8 + 2 * tig;
                    int p = lc >> 7, d = lc & 127;
                    int j = p * 1024 + bn * 128 + d;
                    float2 b2 = *(const float2*)(bias + j);
                    __half2 hv = __floats2half2_rn(acc[mt][nt][2 * h] + b2.x,
                                                   acc[mt][nt][2 * h + 1] + b2.y);
                    if (p == 0) {
                        int kb = d >> 4, mb = r >> 4, ri = r & 15, ci = d & 15;
                        int ln2 = (ri & 7) * 4 + ((ci & 7) >> 1);
                        int ix = (ci & 1) + 2 * ((ri >> 3) & 1) + 4 * ((ci >> 3) & 1);
                        *(__half2*)(sF + base + ((kb * 4 + mb) << 8) + ln2 * 8 + ix) = hv;
                    } else if (p == 1) {
                        int kb = d >> 4, g = r >> 4, ni = r & 15, ci = d & 15;
                        int ln2 = (ni & 7) * 4 + ((ci & 7) >> 1);
                        int ix = (ci & 1) + 2 * ((ci >> 3) & 1) + 4 * ((ni >> 3) & 1);
                        *(__half2*)(sF + base + 8192 + ((kb * 4 + g) << 8) + ln2 * 8 + ix) = hv;
                    } else {
                        int kt = r >> 4, ci = r & 15;
#pragma unroll
                        for (int u = 0; u < 2; u++) {
                            int dd = d + u;
                            int dg = dd >> 4, ni = dd & 15;
                            int ln2 = (ni & 7) * 4 + ((ci & 7) >> 1);
                            int ix = (ci & 1) + 2 * ((ci >> 3) & 1) + 4 * ((ni >> 3) & 1);
                            sF[base + 16384 + ((kt * 8 + dg) << 8) + ln2 * 8 + ix] =
                                (u == 0) ? __low2half(hv) : __high2half(hv);
                        }
                    }
                }
            }
        }
        __syncthreads();

        if (wid < 8) {
            const int pid = wid >> 2, amt = wid & 3;
            const __half* qf = sF + pid * 24576;
            const __half* kf = qf + 8192;
            const __half* vf = qf + 16384;

            // P = Q K^T for rows [amt*16, amt*16+16), all 64 kv cols
            float p[8][4];
#pragma unroll
            for (int nb = 0; nb < 8; nb++)
#pragma unroll
                for (int e = 0; e < 4; e++) p[nb][e] = 0.0f;
#pragma unroll
            for (int kt = 0; kt < 8; kt++) {
                uint4 af = *(const uint4*)(qf + ((kt * 4 + amt) << 8) + (lane << 3));
#pragma unroll
                for (int g = 0; g < 4; g++) {
                    uint4 bb = *(const uint4*)(kf + ((kt * 4 + g) << 8) + (lane << 3));
                    mma_f16(p[2 * g],     af.x, af.y, af.z, af.w, bb.x, bb.y);
                    mma_f16(p[2 * g + 1], af.x, af.y, af.z, af.w, bb.z, bb.w);
                }
            }

            // softmax on fragments: rows grp (c0,c1) and grp+8 (c2,c3)
            const float scale = 0.08838834764831845f;
            float m0 = -1e30f, m1 = -1e30f;
#pragma unroll
            for (int nb = 0; nb < 8; nb++) {
                p[nb][0] *= scale; p[nb][1] *= scale;
                p[nb][2] *= scale; p[nb][3] *= scale;
                m0 = fmaxf(m0, fmaxf(p[nb][0], p[nb][1]));
                m1 = fmaxf(m1, fmaxf(p[nb][2], p[nb][3]));
            }
            m0 = fmaxf(m0, __shfl_xor_sync(0xffffffffu, m0, 1));
            m0 = fmaxf(m0, __shfl_xor_sync(0xffffffffu, m0, 2));
            m1 = fmaxf(m1, __shfl_xor_sync(0xffffffffu, m1, 1));
            m1 = fmaxf(m1, __shfl_xor_sync(0xffffffffu, m1, 2));
            float s0 = 0.f, s1 = 0.f;
#pragma unroll
            for (int nb = 0; nb < 8; nb++) {
                p[nb][0] = __expf(p[nb][0] - m0);
                p[nb][1] = __expf(p[nb][1] - m0);
                p[nb][2] = __expf(p[nb][2] - m1);
                p[nb][3] = __expf(p[nb][3] - m1);
                s0 += p[nb][0] + p[nb][1];
                s1 += p[nb][2] + p[nb][3];
            }
            s0 += __shfl_xor_sync(0xffffffffu, s0, 1);
            s0 += __shfl_xor_sync(0xffffffffu, s0, 2);
            s1 += __shfl_xor_sync(0xffffffffu, s1, 1);
            s1 += __shfl_xor_sync(0xffffffffu, s1, 2);
            float inv0 = 1.0f / s0, inv1 = 1.0f / s1;

            // Re-pack P (C-frag) as A-frags over k=j (register-only)
            uint32_t pf[4][4];
#pragma unroll
            for (int kt = 0; kt < 4; kt++) {
                pf[kt][0] = h2_u32(__floats2half2_rn(p[2 * kt][0], p[2 * kt][1]));
                pf[kt][1] = h2_u32(__floats2half2_rn(p[2 * kt][2], p[2 * kt][3]));
                pf[kt][2] = h2_u32(__floats2half2_rn(p[2 * kt + 1][0], p[2 * kt + 1][1]));
                pf[kt][3] = h2_u32(__floats2half2_rn(p[2 * kt + 1][2], p[2 * kt + 1][3]));
            }

            // O = P V (V-frags transposed: n=d, k=j)
            float o[16][4];
#pragma unroll
            for (int nb = 0; nb < 16; nb++)
#pragma unroll
                for (int e = 0; e < 4; e++) o[nb][e] = 0.0f;
#pragma unroll
            for (int dg = 0; dg < 8; dg++)
#pragma unroll
                for (int kt = 0; kt < 4; kt++) {
                    uint4 bb = *(const uint4*)(vf + ((kt * 8 + dg) << 8) + (lane << 3));
                    mma_f16(o[2 * dg],     pf[kt][0], pf[kt][1], pf[kt][2], pf[kt][3],
                            bb.x, bb.y);
                    mma_f16(o[2 * dg + 1], pf[kt][0], pf[kt][1], pf[kt][2], pf[kt][3],
                            bb.z, bb.w);
                }

            __half* outp = (__half*)Cv;
            int row0 = (bm * 2 + pid) * 64 + amt * 16 + grp;
#pragma unroll
            for (int nb = 0; nb < 16; nb++) {
                int cb = bn * 128 + nb * 8 + 2 * tig;
                *(__half2*)(outp + afrag_h(row0, cb)) =
                    __floats2half2_rn(o[nb][0] * inv0, o[nb][1] * inv0);
                *(__half2*)(outp + afrag_h(row0 + 8, cb)) =
                    __floats2half2_rn(o[nb][2] * inv1, o[nb][3] * inv1);
            }
        }
        return;
    }

    if (EPI == 3) {
        // ---- fused stage-A attention epilogue (TN=384, head = bn) ----
        constexpr int ALD = 392;
        __half* sAtt = (__half*)smem_raw;     // 128 x 392 halves
        __syncthreads();
#pragma unroll
        for (int mt = 0; mt < 4; mt++) {
#pragma unroll
            for (int h = 0; h < 2; h++) {
                int lr = wm + mt * 16 + grp + 8 * h;
#pragma unroll
                for (int nt = 0; nt < 8; nt++) {
                    int lc = wn + nt * 8 + 2 * tig;
                    int p = lc >> 7, d = lc & 127;
                    int j = p * 1024 + bn * 128 + d;
                    float2 b2 = *(const float2*)(bias + j);
                    *(__half2*)(sAtt + lr * ALD + lc) =
                        __floats2half2_rn(acc[mt][nt][2 * h] + b2.x,
                                          acc[mt][nt][2 * h + 1] + b2.y);
                }
            }
        }
        __syncthreads();

        __half* outp = (__half*)Cv;
        const float scale = 0.08838834764831845f;
        const int l = lane;
        for (int g = wid; g < 32; g += NWARP) {
            float4 q[4], k[4], v[4];
#pragma unroll
            for (int i = 0; i < 4; i++) {
                const __half* rp = sAtt + (4 * g + i) * ALD;
                q[i] = ld_half4(rp + 4 * l);
                k[i] = ld_half4(rp + 128 + 4 * l);
                v[i] = ld_half4(rp + 256 + 4 * l);
            }
            float sc[4][4];
#pragma unroll
            for (int i = 0; i < 4; i++)
#pragma unroll
                for (int j = 0; j < 4; j++)
                    sc[i][j] = q[i].x * k[j].x + q[i].y * k[j].y +
                               q[i].z * k[j].z + q[i].w * k[j].w;
#pragma unroll
            for (int o = 16; o > 0; o >>= 1)
#pragma unroll
                for (int i = 0; i < 4; i++)
#pragma unroll
                    for (int j = 0; j < 4; j++)
                        sc[i][j] += __shfl_xor_sync(0xffffffffu, sc[i][j], o);

            float wj[4] = {0.f, 0.f, 0.f, 0.f};
#pragma unroll
            for (int i = 0; i < 4; i++) {
                float s0 = sc[i][0] * scale, s1 = sc[i][1] * scale;
                float s2 = sc[i][2] * scale, s3 = sc[i][3] * scale;
                float m = fmaxf(fmaxf(s0, s1), fmaxf(s2, s3));
                float e0 = __expf(s0 - m), e1 = __expf(s1 - m);
                float e2 = __expf(s2 - m), e3 = __expf(s3 - m);
                float inv = 0.25f / (e0 + e1 + e2 + e3);
                wj[0] += e0 * inv; wj[1] += e1 * inv;
                wj[2] += e2 * inv; wj[3] += e3 * inv;
            }
            float4 o = {0.f, 0.f, 0.f, 0.f};
#pragma unroll
            for (int j = 0; j < 4; j++) {
                o.x += wj[j] * v[j].x; o.y += wj[j] * v[j].y;
                o.z += wj[j] * v[j].z; o.w += wj[j] * v[j].w;
            }
            int row = bm * 32 + g;
            int cb = bn * 128 + 4 * l;
            *(__half2*)(outp + afrag_h(row, cb))     = __floats2half2_rn(o.x, o.y);
            *(__half2*)(outp + afrag_h(row, cb + 2)) = __floats2half2_rn(o.z, o.w);
        }
        return;
    }

    // ---- standard epilogues (TN=256) ----
#pragma unroll
    for (int mt = 0; mt < 4; mt++) {
#pragma unroll
        for (int h = 0; h < 2; h++) {
            int gr = bm * 128 + wm + mt * 16 + grp + 8 * h;
#pragma unroll
            for (int nt = 0; nt < 8; nt++) {
                int gc = bn * TN + wn + nt * 8 + 2 * tig;
                float2 b2 = *(const float2*)(bias + gc);
                float v0 = acc[mt][nt][2 * h]     + b2.x;
                float v1 = acc[mt][nt][2 * h + 1] + b2.y;
                if (EPI == 1) {
                    __half* C = (__half*)Cv;
                    int srow = gr >> 7, b = gr & 127;
                    float2 p2 = *(const float2*)(pos + (size_t)srow * 1024 + gc);
                    int r_out = b * 64 + srow;
                    *(__half2*)(C + afrag_h(r_out, gc)) =
                        __floats2half2_rn(v0 + p2.x, v1 + p2.y);
                } else {
                    float* C = (float*)Cv;
                    int b = gr >> 6, s = gr & 63;
                    float2 o; o.x = v0; o.y = v1;
                    *(float2*)(C + (size_t)(s * 128 + b) * N + gc) = o;
                }
            }
        }
    }
}

#define GSMEM_T256 (4 * (16384 + 256 * 64 * 2))   // 196608
#define GSMEM_T384 (3 * (16384 + 384 * 64 * 2))   // 196608

// ---------------------------------------------------------------------------
extern "C" void kernel_launch(void* const* d_in, const int* in_sizes, int n_in,
                              void* d_out, int out_size)
{
    (void)in_sizes; (void)n_in; (void)out_size;
    const float* hid      = (const float*)d_in[0];
    const float* mf_in_w  = (const float*)d_in[1];
    const float* mf_in_b  = (const float*)d_in[2];
    const float* mf_out_w = (const float*)d_in[3];
    const float* mf_out_b = (const float*)d_in[4];
    const float* sf_in_w  = (const float*)d_in[5];
    const float* sf_in_b  = (const float*)d_in[6];
    const float* sf_out_w = (const float*)d_in[7];
    const float* sf_out_b = (const float*)d_in[8];
    const float* pos_enc  = (const float*)d_in[9];
    float* out = (float*)d_out;

    __half *hidA, *wmin, *wmout, *wsin, *wsout, *meanb, *seq, *att2;
    cudaGetSymbolAddress((void**)&hidA,  g_hidA);
    cudaGetSymbolAddress((void**)&wmin,  g_wmin);
    cudaGetSymbolAddress((void**)&wmout, g_wmout);
    cudaGetSymbolAddress((void**)&wsin,  g_wsin);
    cudaGetSymbolAddress((void**)&wsout, g_wsout);
    cudaGetSymbolAddress((void**)&meanb, g_mean);
    cudaGetSymbolAddress((void**)&seq,   g_seq);
    cudaGetSymbolAddress((void**)&att2,  g_att2);

    cudaFuncSetAttribute(conv_all,
        cudaFuncAttributeMaxDynamicSharedMemorySize, CONV_SMEM);
    cudaFuncSetAttribute((tgemm2<3, 384, 384>),
        cudaFuncAttributeMaxDynamicSharedMemorySize, GSMEM_T384);
    cudaFuncSetAttribute((tgemm2<4, 384, 384>),
        cudaFuncAttributeMaxDynamicSharedMemorySize, GSMEM_T384);
    cudaFuncSetAttribute((tgemm2<1, 256, 256>),
        cudaFuncAttributeMaxDynamicSharedMemorySize, GSMEM_T256);
    cudaFuncSetAttribute((tgemm2<2, 256, 256>),
        cudaFuncAttributeMaxDynamicSharedMemorySize, GSMEM_T256);

    // ---- unified prepass: gather + fragment-order + fp16-round everything
    conv_all<<<2560, 256, CONV_SMEM>>>(hid, hidA,
                                       mf_in_w, mf_out_w, sf_in_w, sf_out_w,
                                       wmin, wmout, wsin, wsout);

    // Stage A: fused qkv GEMM + L=4 attention + model-mean -> meanb (A-frag)
    tgemm2<3, 384, 384><<<dim3(8, 256), 384, GSMEM_T384>>>(
        hidA, wmin, mf_in_b, nullptr, meanb, 384);
    // Stage A out-proj + transpose to [B,S,H] + pos_enc   -> seq (A-frag)
    tgemm2<1, 256, 256><<<dim3(4, 64), 256, GSMEM_T256>>>(
        meanb, wmout, mf_out_b, pos_enc, seq, 1024);
    // Stage B: fused qkv GEMM + TENSORIZED L=64 attention -> att2 (A-frag)
    tgemm2<4, 384, 384><<<dim3(8, 64), 384, GSMEM_T384>>>(
        seq, wsin, sf_in_b, nullptr, att2, 384);
    // Stage B out-proj + transpose to [S,B,1,H]           -> d_out (float)
    tgemm2<2, 256, 256><<<dim3(4, 64), 256, GSMEM_T256>>>(
        att2, wsout, sf_out_b, nullptr, out, 1024);
}

// round 16
// speedup vs baseline: 8.3751x; 1.0491x over previous
#include <cuda_runtime.h>
#include <cuda_fp16.h>
#include <cstdint>
#include <math.h>

// ---------------------------------------------------------------------------
// HierarchicalModelFusion — fp16 mma.sync (m16n8k16, f32 accum),
// fragment-ordered packed-half operands, cp.async pipeline (4-stage TN=256,
// 3-stage TN=384). BOTH attention stages fused into their qkv GEMM epilogues.
// Stage-B epilogue attention TENSORIZED (frag-layout smem dump, HMMA QK/PV).
// This round: cp.async issues are interleaved through the chunk's kb loop so
// fragment LDSes are not queued behind the LDGSTS burst on the shared LSU.
// ---------------------------------------------------------------------------

#define KD 1024

// Scratch (device globals)
__device__ __align__(256) __half g_hidA[(size_t)32768 * 1024];  // A-frag
__device__ __align__(256) __half g_wmin[(size_t)3072 * 1024];   // B-frag TN=384 head-perm
__device__ __align__(256) __half g_wmout[(size_t)1024 * 1024];  // B-frag TN=256
__device__ __align__(256) __half g_wsin[(size_t)3072 * 1024];   // B-frag TN=384 head-perm
__device__ __align__(256) __half g_wsout[(size_t)1024 * 1024];  // B-frag TN=256
__device__ __align__(256) __half g_mean[(size_t)8192 * 1024];   // A-frag
__device__ __align__(256) __half g_seq [(size_t)8192 * 1024];   // A-frag
__device__ __align__(256) __half g_att2[(size_t)8192 * 1024];   // A-frag

__device__ __forceinline__ uint32_t h2_u32(__half2 h) {
    return *reinterpret_cast<uint32_t*>(&h);
}
__device__ __forceinline__ float4 ld_half4(const __half* p) {
    uint2 raw = *(const uint2*)p;
    float2 a = __half22float2(*(__half2*)&raw.x);
    float2 b = __half22float2(*(__half2*)&raw.y);
    return make_float4(a.x, a.y, b.x, b.y);
}

// A-frag (m16n8k16 A operand) index for a [rows,1024] half matrix.
__device__ __forceinline__ size_t afrag_h(int r, int c) {
    int mt = r >> 7, mb = (r >> 4) & 7, ri = r & 15;
    int kt = c >> 6, kb = (c >> 4) & 3, ci = c & 15;
    int lane = (ri & 7) * 4 + ((ci & 7) >> 1);
    int idx = (ci & 1) + 2 * ((ri >> 3) & 1) + 4 * ((ci >> 3) & 1);
    return ((size_t)(mt * 16 + kt) << 13) + ((kb * 8 + mb) << 8) + (lane << 3) + idx;
}

__device__ __forceinline__ void mma_f16(float* d, uint32_t a0, uint32_t a1,
                                        uint32_t a2, uint32_t a3,
                                        uint32_t b0, uint32_t b1) {
    asm volatile(
        "mma.sync.aligned.m16n8k16.row.col.f32.f16.f16.f32 "
        "{%0,%1,%2,%3}, {%4,%5,%6,%7}, {%8,%9}, {%0,%1,%2,%3};"
        : "+f"(d[0]), "+f"(d[1]), "+f"(d[2]), "+f"(d[3])
        : "r"(a0), "r"(a1), "r"(a2), "r"(a3), "r"(b0), "r"(b1));
}

__device__ __forceinline__ void cp16(uint32_t dst, const void* src) {
    asm volatile("cp.async.cg.shared.global [%0], [%1], 16;"
                 :: "r"(dst), "l"(src));
}
__device__ __forceinline__ uint32_t smem_u32(const void* p) {
    uint32_t a;
    asm("{ .reg .u64 t; cvta.to.shared.u64 t, %1; cvt.u32.u64 %0, t; }"
        : "=r"(a) : "l"(p));
    return a;
}

// ---------------------------------------------------------------------------
// Unified prepass (ONE launch):
//   blocks [0,2048):     hidden[S,M,B,1,H] -> gathered A-frag halves
//   blocks [2048,2240):  mf_in_w  -> B-frag TN=384 head-permuted
//   blocks [2240,2304):  mf_out_w -> B-frag TN=256
//   blocks [2304,2496):  sf_in_w  -> B-frag TN=384 head-permuted
//   blocks [2496,2560):  sf_out_w -> B-frag TN=256
// ---------------------------------------------------------------------------
#define CONV_SMEM (16 * 1028 * 4)
__global__ void __launch_bounds__(256) conv_all(
    const float* __restrict__ hid, __half* __restrict__ Af,
    const float* __restrict__ w0, const float* __restrict__ w1,
    const float* __restrict__ w2, const float* __restrict__ w3,
    __half* __restrict__ o0, __half* __restrict__ o1,
    __half* __restrict__ o2, __half* __restrict__ o3)
{
    extern __shared__ float tile[];    // [16][1028]
    const int tid = threadIdx.x;

    if (blockIdx.x < 2048) {
        const int nb = blockIdx.x;
#pragma unroll
        for (int i = 0; i < 16; i++) {
            int idx = tid + 256 * i;
            int r = idx >> 8, c4 = idx & 255;
            int n = nb * 16 + r;
            int s = n >> 9, b = (n >> 2) & 127, m = n & 3;
            float4 v = *(const float4*)(hid + (((size_t)((s * 4 + m) * 128 + b)) << 10)
                                            + (c4 << 2));
            *(float4*)&tile[r * 1028 + c4 * 4] = v;
        }
        __syncthreads();
        const int mt = nb >> 3, mb = nb & 7;
#pragma unroll
        for (int j = 0; j < 8; j++) {
            int g = tid + 256 * j;
            int kt = g >> 7, rr = g & 127, kb = rr >> 5, ln = rr & 31;
            int grp = ln >> 2, tig = ln & 3;
            int c0 = kt * 64 + kb * 16 + 2 * tig;
            __half2 p0 = __floats2half2_rn(tile[grp * 1028 + c0],
                                           tile[grp * 1028 + c0 + 1]);
            __half2 p1 = __floats2half2_rn(tile[(grp + 8) * 1028 + c0],
                                           tile[(grp + 8) * 1028 + c0 + 1]);
            __half2 p2 = __floats2half2_rn(tile[grp * 1028 + c0 + 8],
                                           tile[grp * 1028 + c0 + 9]);
            __half2 p3 = __floats2half2_rn(tile[(grp + 8) * 1028 + c0 + 8],
                                           tile[(grp + 8) * 1028 + c0 + 9]);
            uint4 o;
            o.x = h2_u32(p0); o.y = h2_u32(p1);
            o.z = h2_u32(p2); o.w = h2_u32(p3);
            *(uint4*)(Af + ((size_t)(mt * 16 + kt) << 13) + ((kb * 8 + mb) << 8)
                         + (ln << 3)) = o;
        }
        return;
    }

    int gid = blockIdx.x - 2048;
    const float* W; __half* Bf;
    bool perm384 = false;
    if (gid < 192)      { W = w0; Bf = o0; perm384 = true; }
    else if (gid < 256) { W = w1; Bf = o1; gid -= 192; }
    else if (gid < 448) { W = w2; Bf = o2; gid -= 256; perm384 = true; }
    else                { W = w3; Bf = o3; gid -= 448; }
#pragma unroll
    for (int i = 0; i < 16; i++) {
        int idx = tid + 256 * i;
        int r = idx >> 8, c4 = idx & 255;
        float4 v = *(const float4*)(W + ((size_t)(gid * 16 + r) << 10) + (c4 << 2));
        *(float4*)&tile[r * 1028 + c4 * 4] = v;
    }
    __syncthreads();

    int ntile, gblk, ngroups;
    if (perm384) {
        int j0 = gid * 16;
        int p = j0 >> 10, rem = j0 & 1023;
        int h = rem >> 7, d0 = rem & 127;
        ntile = h;                     // 384-wide tile = head
        gblk = p * 8 + (d0 >> 4);      // 16-col group within 384 (24 groups)
        ngroups = 24;
    } else {
        ntile = gid >> 4;
        gblk = gid & 15;
        ngroups = 16;
    }

#pragma unroll
    for (int j = 0; j < 8; j++) {
        int g = tid + 256 * j;
        int kt = g >> 7, rr = g & 127, kb = rr >> 5, ln = rr & 31;
        int grp = ln >> 2, tig = ln & 3;
        int c0 = kt * 64 + kb * 16 + 2 * tig;
        __half2 p0 = __floats2half2_rn(tile[grp * 1028 + c0],
                                       tile[grp * 1028 + c0 + 1]);
        __half2 p1 = __floats2half2_rn(tile[grp * 1028 + c0 + 8],
                                       tile[grp * 1028 + c0 + 9]);
        __half2 p2 = __floats2half2_rn(tile[(grp + 8) * 1028 + c0],
                                       tile[(grp + 8) * 1028 + c0 + 1]);
        __half2 p3 = __floats2half2_rn(tile[(grp + 8) * 1028 + c0 + 8],
                                       tile[(grp + 8) * 1028 + c0 + 9]);
        uint4 o;
        o.x = h2_u32(p0); o.y = h2_u32(p1);
        o.z = h2_u32(p2); o.w = h2_u32(p3);
        size_t off = ((size_t)(ntile * 16 + kt) * (ngroups * 16 * 64))
                   + ((size_t)(kb * ngroups + gblk) << 8) + (ln << 3);
        *(uint4*)(Bf + off) = o;
    }
}

// ---------------------------------------------------------------------------
// GEMM: C = A @ W^T + bias. CTA 128xTN, warp 64x64, K chunks of 64 halves.
// NSTAGE = 4 for TN=256, 3 for TN=384. cp.async issues for chunk c+NSTAGE-1
// are interleaved across the kb loop (A after kb0, B after kb1/kb2, commit
// after kb3) so fragment LDSes are never queued behind the LDGSTS burst.
// EPI 1: transpose [B,S,H] + pos_enc -> half A-frag (TN=256)
// EPI 2: transpose [S,B,H] -> float store, final out (TN=256)
// EPI 3: FUSED stage-A attention (TN=384, head=bn, L=4 x32 groups) -> A-frag
// EPI 4: FUSED stage-B attention (TN=384, head=bn, L=64 x2, TENSORIZED)
// ---------------------------------------------------------------------------
template <int EPI, int TN, int NT>
__global__ void __launch_bounds__(NT, 1) tgemm2(
    const __half* __restrict__ Af, const __half* __restrict__ Bf,
    const float* __restrict__ bias, const float* __restrict__ pos,
    void* __restrict__ Cv, int N)
{
    constexpr int NWARP = NT / 32;          // 8 or 12
    constexpr int BCH = TN * 64 * 2;        // B bytes per chunk
    constexpr int SSTAGE = 16384 + BCH;     // stage bytes (49152 or 65536)
    constexpr int BGRP = TN / 16;           // 16-col groups per tile
    constexpr int NSTAGE = (TN == 384) ? 3 : 4;

    extern __shared__ char smem_raw[];
    const uint32_t sb = smem_u32(smem_raw);
    const int tid = threadIdx.x, wid = tid >> 5, lane = tid & 31;
    const int bm = blockIdx.y, bn = blockIdx.x;

    const uint4* Af4 = (const uint4*)Af + ((size_t)bm << 14) + tid;
    const uint4* Bf4 = (const uint4*)Bf + (size_t)bn * (TN * 128) + tid;
    const uint32_t adst = sb + tid * 16;
    const uint32_t bdst = sb + 16384 + tid * 16;

    auto issue = [&](int kt, int s) {
        if (NT == 256 || tid < 256) {
            const uint4* a = Af4 + (kt << 10);
            uint32_t ad = adst + s * SSTAGE;
#pragma unroll
            for (int i = 0; i < 4; i++) cp16(ad + i * 4096, a + i * 256);
        }
        const uint4* b = Bf4 + kt * (TN * 8);
        uint32_t bd = bdst + s * SSTAGE;
#pragma unroll
        for (int i = 0; i < 8; i++)
            cp16(bd + i * (NT * 16), b + i * NT);
        asm volatile("cp.async.commit_group;" ::: "memory");
    };

    float acc[4][8][4];
#pragma unroll
    for (int mt = 0; mt < 4; mt++)
#pragma unroll
        for (int nt = 0; nt < 8; nt++)
#pragma unroll
            for (int e = 0; e < 4; e++) acc[mt][nt][e] = 0.0f;

    const int wmb = (wid & 1) * 4;     // A 16-row block base
    const int wnb = (wid >> 1) * 4;    // B 16-col group base

    issue(0, 0);
    issue(1, 1);
    if (NSTAGE == 4) issue(2, 2);

#pragma unroll 1
    for (int c = 0; c < 16; c++) {
        if (NSTAGE == 4) {
            if (c < 14)       asm volatile("cp.async.wait_group 2;" ::: "memory");
            else if (c == 14) asm volatile("cp.async.wait_group 1;" ::: "memory");
            else              asm volatile("cp.async.wait_group 0;" ::: "memory");
        } else {
            if (c < 15)       asm volatile("cp.async.wait_group 1;" ::: "memory");
            else              asm volatile("cp.async.wait_group 0;" ::: "memory");
        }
        __syncthreads();

        // pointers for the interleaved issue of chunk c+NSTAGE-1
        const bool doIssue = (c + NSTAGE - 1 < 16);
        const int ktn = c + NSTAGE - 1;
        const int sn = ktn % NSTAGE;
        const uint4* an = Af4 + (ktn << 10);
        const uint4* bnp = Bf4 + ktn * (TN * 8);
        const uint32_t adn = adst + sn * SSTAGE;
        const uint32_t bdn = bdst + sn * SSTAGE;

        const __half* sA = (const __half*)(smem_raw + (c % NSTAGE) * SSTAGE);
        const __half* sB = sA + 8192;
#pragma unroll
        for (int kb = 0; kb < 4; kb++) {
            uint4 af[4];
#pragma unroll
            for (int mt = 0; mt < 4; mt++)
                af[mt] = *(const uint4*)(sA + ((kb * 8 + wmb + mt) << 8) + (lane << 3));
#pragma unroll
            for (int gt = 0; gt < 4; gt++) {
                uint4 bb = *(const uint4*)(sB + ((kb * BGRP + wnb + gt) << 8) + (lane << 3));
#pragma unroll
                for (int mt = 0; mt < 4; mt++) {
                    mma_f16(acc[mt][2 * gt],     af[mt].x, af[mt].y, af[mt].z, af[mt].w,
                            bb.x, bb.y);
                    mma_f16(acc[mt][2 * gt + 1], af[mt].x, af[mt].y, af[mt].z, af[mt].w,
                            bb.z, bb.w);
                }
            }
            // interleaved cp.async issue: A after kb0, B halves after kb1/kb2,
            // commit after kb3 — fragment LDSes always reach the LSU first.
            if (doIssue) {
                if (kb == 0) {
                    if (NT == 256 || tid < 256) {
#pragma unroll
                        for (int i = 0; i < 4; i++)
                            cp16(adn + i * 4096, an + i * 256);
                    }
                } else if (kb == 1) {
#pragma unroll
                    for (int i = 0; i < 4; i++)
                        cp16(bdn + i * (NT * 16), bnp + i * NT);
                } else if (kb == 2) {
#pragma unroll
                    for (int i = 4; i < 8; i++)
                        cp16(bdn + i * (NT * 16), bnp + i * NT);
                } else {
                    asm volatile("cp.async.commit_group;" ::: "memory");
                }
            }
        }
    }

    const int grp = lane >> 2, tig = lane & 3;
    const int wm = (wid & 1) * 64, wn = (wid >> 1) * 64;

    if (EPI == 4) {
        // ---- TENSORIZED stage-B attention epilogue (TN=384, head = bn) ----
        __half* sF = (__half*)smem_raw;
        __syncthreads();
#pragma unroll
        for (int mt = 0; mt < 4; mt++) {
#pragma unroll
            for (int h = 0; h < 2; h++) {
                int lr = wm + mt * 16 + grp + 8 * h;
                int pid = lr >> 6, r = lr & 63;
                int base = pid * 24576;
#pragma unroll
                for (int nt = 0; nt < 8; nt++) {
                    int lc = wn + nt * 8 + 2 * tig;
                    int p = lc >> 7, d = lc & 127;
                    int j = p * 1024 + bn * 128 + d;
                    float2 b2 = *(const float2*)(bias + j);
                    __half2 hv = __floats2half2_rn(acc[mt][nt][2 * h] + b2.x,
                                                   acc[mt][nt][2 * h + 1] + b2.y);
                    if (p == 0) {
                        int kb = d >> 4, mb = r >> 4, ri = r & 15, ci = d & 15;
                        int ln2 = (ri & 7) * 4 + ((ci & 7) >> 1);
                        int ix = (ci & 1) + 2 * ((ri >> 3) & 1) + 4 * ((ci >> 3) & 1);
                        *(__half2*)(sF + base + ((kb * 4 + mb) << 8) + ln2 * 8 + ix) = hv;
                    } else if (p == 1) {
                        int kb = d >> 4, g = r >> 4, ni = r & 15, ci = d & 15;
                        int ln2 = (ni & 7) * 4 + ((ci & 7) >> 1);
                        int ix = (ci & 1) + 2 * ((ci >> 3) & 1) + 4 * ((ni >> 3) & 1);
                        *(__half2*)(sF + base + 8192 + ((kb * 4 + g) << 8) + ln2 * 8 + ix) = hv;
                    } else {
                        int kt = r >> 4, ci = r & 15;
#pragma unroll
                        for (int u = 0; u < 2; u++) {
                            int dd = d + u;
                            int dg = dd >> 4, ni = dd & 15;
                            int ln2 = (ni & 7) * 4 + ((ci & 7) >> 1);
                            int ix = (ci & 1) + 2 * ((ci >> 3) & 1) + 4 * ((ni >> 3) & 1);
                            sF[base + 16384 + ((kt * 8 + dg) << 8) + ln2 * 8 + ix] =
                                (u == 0) ? __low2half(hv) : __high2half(hv);
                        }
                    }
                }
            }
        }
        __syncthreads();

        if (wid < 8) {
            const int pid = wid >> 2, amt = wid & 3;
            const __half* qf = sF + pid * 24576;
            const __half* kf = qf + 8192;
            const __half* vf = qf + 16384;

            float p[8][4];
#pragma unroll
            for (int nb = 0; nb < 8; nb++)
#pragma unroll
                for (int e = 0; e < 4; e++) p[nb][e] = 0.0f;
#pragma unroll
            for (int kt = 0; kt < 8; kt++) {
                uint4 af = *(const uint4*)(qf + ((kt * 4 + amt) << 8) + (lane << 3));
#pragma unroll
                for (int g = 0; g < 4; g++) {
                    uint4 bb = *(const uint4*)(kf + ((kt * 4 + g) << 8) + (lane << 3));
                    mma_f16(p[2 * g],     af.x, af.y, af.z, af.w, bb.x, bb.y);
                    mma_f16(p[2 * g + 1], af.x, af.y, af.z, af.w, bb.z, bb.w);
                }
            }

            const float scale = 0.08838834764831845f;
            float m0 = -1e30f, m1 = -1e30f;
#pragma unroll
            for (int nb = 0; nb < 8; nb++) {
                p[nb][0] *= scale; p[nb][1] *= scale;
                p[nb][2] *= scale; p[nb][3] *= scale;
                m0 = fmaxf(m0, fmaxf(p[nb][0], p[nb][1]));
                m1 = fmaxf(m1, fmaxf(p[nb][2], p[nb][3]));
            }
            m0 = fmaxf(m0, __shfl_xor_sync(0xffffffffu, m0, 1));
            m0 = fmaxf(m0, __shfl_xor_sync(0xffffffffu, m0, 2));
            m1 = fmaxf(m1, __shfl_xor_sync(0xffffffffu, m1, 1));
            m1 = fmaxf(m1, __shfl_xor_sync(0xffffffffu, m1, 2));
            float s0 = 0.f, s1 = 0.f;
#pragma unroll
            for (int nb = 0; nb < 8; nb++) {
                p[nb][0] = __expf(p[nb][0] - m0);
                p[nb][1] = __expf(p[nb][1] - m0);
                p[nb][2] = __expf(p[nb][2] - m1);
                p[nb][3] = __expf(p[nb][3] - m1);
                s0 += p[nb][0] + p[nb][1];
                s1 += p[nb][2] + p[nb][3];
            }
            s0 += __shfl_xor_sync(0xffffffffu, s0, 1);
            s0 += __shfl_xor_sync(0xffffffffu, s0, 2);
            s1 += __shfl_xor_sync(0xffffffffu, s1, 1);
            s1 += __shfl_xor_sync(0xffffffffu, s1, 2);
            float inv0 = 1.0f / s0, inv1 = 1.0f / s1;

            uint32_t pf[4][4];
#pragma unroll
            for (int kt = 0; kt < 4; kt++) {
                pf[kt][0] = h2_u32(__floats2half2_rn(p[2 * kt][0], p[2 * kt][1]));
                pf[kt][1] = h2_u32(__floats2half2_rn(p[2 * kt][2], p[2 * kt][3]));
                pf[kt][2] = h2_u32(__floats2half2_rn(p[2 * kt + 1][0], p[2 * kt + 1][1]));
                pf[kt][3] = h2_u32(__floats2half2_rn(p[2 * kt + 1][2], p[2 * kt + 1][3]));
            }

            float o[16][4];
#pragma unroll
            for (int nb = 0; nb < 16; nb++)
#pragma unroll
                for (int e = 0; e < 4; e++) o[nb][e] = 0.0f;
#pragma unroll
            for (int dg = 0; dg < 8; dg++)
#pragma unroll
                for (int kt = 0; kt < 4; kt++) {
                    uint4 bb = *(const uint4*)(vf + ((kt * 8 + dg) << 8) + (lane << 3));
                    mma_f16(o[2 * dg],     pf[kt][0], pf[kt][1], pf[kt][2], pf[kt][3],
                            bb.x, bb.y);
                    mma_f16(o[2 * dg + 1], pf[kt][0], pf[kt][1], pf[kt][2], pf[kt][3],
                            bb.z, bb.w);
                }

            __half* outp = (__half*)Cv;
            int row0 = (bm * 2 + pid) * 64 + amt * 16 + grp;
#pragma unroll
            for (int nb = 0; nb < 16; nb++) {
                int cb = bn * 128 + nb * 8 + 2 * tig;
                *(__half2*)(outp + afrag_h(row0, cb)) =
                    __floats2half2_rn(o[nb][0] * inv0, o[nb][1] * inv0);
                *(__half2*)(outp + afrag_h(row0 + 8, cb)) =
                    __floats2half2_rn(o[nb][2] * inv1, o[nb][3] * inv1);
            }
        }
        return;
    }

    if (EPI == 3) {
        // ---- fused stage-A attention epilogue (TN=384, head = bn) ----
        constexpr int ALD = 392;
        __half* sAtt = (__half*)smem_raw;     // 128 x 392 halves
        __syncthreads();
#pragma unroll
        for (int mt = 0; mt < 4; mt++) {
#pragma unroll
            for (int h = 0; h < 2; h++) {
                int lr = wm + mt * 16 + grp + 8 * h;
#pragma unroll
                for (int nt = 0; nt < 8; nt++) {
                    int lc = wn + nt * 8 + 2 * tig;
                    int p = lc >> 7, d = lc & 127;
                    int j = p * 1024 + bn * 128 + d;
                    float2 b2 = *(const float2*)(bias + j);
                    *(__half2*)(sAtt + lr * ALD + lc) =
                        __floats2half2_rn(acc[mt][nt][2 * h] + b2.x,
                                          acc[mt][nt][2 * h + 1] + b2.y);
                }
            }
        }
        __syncthreads();

        __half* outp = (__half*)Cv;
        const float scale = 0.08838834764831845f;
        const int l = lane;
        for (int g = wid; g < 32; g += NWARP) {
            float4 q[4], k[4], v[4];
#pragma unroll
            for (int i = 0; i < 4; i++) {
                const __half* rp = sAtt + (4 * g + i) * ALD;
                q[i] = ld_half4(rp + 4 * l);
                k[i] = ld_half4(rp + 128 + 4 * l);
                v[i] = ld_half4(rp + 256 + 4 * l);
            }
            float sc[4][4];
#pragma unroll
            for (int i = 0; i < 4; i++)
#pragma unroll
                for (int j = 0; j < 4; j++)
                    sc[i][j] = q[i].x * k[j].x + q[i].y * k[j].y +
                               q[i].z * k[j].z + q[i].w * k[j].w;
#pragma unroll
            for (int o = 16; o > 0; o >>= 1)
#pragma unroll
                for (int i = 0; i < 4; i++)
#pragma unroll
                    for (int j = 0; j < 4; j++)
                        sc[i][j] += __shfl_xor_sync(0xffffffffu, sc[i][j], o);

            float wj[4] = {0.f, 0.f, 0.f, 0.f};
#pragma unroll
            for (int i = 0; i < 4; i++) {
                float s0 = sc[i][0] * scale, s1 = sc[i][1] * scale;
                float s2 = sc[i][2] * scale, s3 = sc[i][3] * scale;
                float m = fmaxf(fmaxf(s0, s1), fmaxf(s2, s3));
                float e0 = __expf(s0 - m), e1 = __expf(s1 - m);
                float e2 = __expf(s2 - m), e3 = __expf(s3 - m);
                float inv = 0.25f / (e0 + e1 + e2 + e3);
                wj[0] += e0 * inv; wj[1] += e1 * inv;
                wj[2] += e2 * inv; wj[3] += e3 * inv;
            }
            float4 o = {0.f, 0.f, 0.f, 0.f};
#pragma unroll
            for (int j = 0; j < 4; j++) {
                o.x += wj[j] * v[j].x; o.y += wj[j] * v[j].y;
                o.z += wj[j] * v[j].z; o.w += wj[j] * v[j].w;
            }
            int row = bm * 32 + g;
            int cb = bn * 128 + 4 * l;
            *(__half2*)(outp + afrag_h(row, cb))     = __floats2half2_rn(o.x, o.y);
            *(__half2*)(outp + afrag_h(row, cb + 2)) = __floats2half2_rn(o.z, o.w);
        }
        return;
    }

    // ---- standard epilogues (TN=256) ----
#pragma unroll
    for (int mt = 0; mt < 4; mt++) {
#pragma unroll
        for (int h = 0; h < 2; h++) {
            int gr = bm * 128 + wm + mt * 16 + grp + 8 * h;
#pragma unroll
            for (int nt = 0; nt < 8; nt++) {
                int gc = bn * TN + wn + nt * 8 + 2 * tig;
                float2 b2 = *(const float2*)(bias + gc);
                float v0 = acc[mt][nt][2 * h]     + b2.x;
                float v1 = acc[mt][nt][2 * h + 1] + b2.y;
                if (EPI == 1) {
                    __half* C = (__half*)Cv;
                    int srow = gr >> 7, b = gr & 127;
                    float2 p2 = *(const float2*)(pos + (size_t)srow * 1024 + gc);
                    int r_out = b * 64 + srow;
                    *(__half2*)(C + afrag_h(r_out, gc)) =
                        __floats2half2_rn(v0 + p2.x, v1 + p2.y);
                } else {
                    float* C = (float*)Cv;
                    int b = gr >> 6, s = gr & 63;
                    float2 o; o.x = v0; o.y = v1;
                    *(float2*)(C + (size_t)(s * 128 + b) * N + gc) = o;
                }
            }
        }
    }
}

#define GSMEM_T256 (4 * (16384 + 256 * 64 * 2))   // 196608
#define GSMEM_T384 (3 * (16384 + 384 * 64 * 2))   // 196608

// ---------------------------------------------------------------------------
extern "C" void kernel_launch(void* const* d_in, const int* in_sizes, int n_in,
                              void* d_out, int out_size)
{
    (void)in_sizes; (void)n_in; (void)out_size;
    const float* hid      = (const float*)d_in[0];
    const float* mf_in_w  = (const float*)d_in[1];
    const float* mf_in_b  = (const float*)d_in[2];
    const float* mf_out_w = (const float*)d_in[3];
    const float* mf_out_b = (const float*)d_in[4];
    const float* sf_in_w  = (const float*)d_in[5];
    const float* sf_in_b  = (const float*)d_in[6];
    const float* sf_out_w = (const float*)d_in[7];
    const float* sf_out_b = (const float*)d_in[8];
    const float* pos_enc  = (const float*)d_in[9];
    float* out = (float*)d_out;

    __half *hidA, *wmin, *wmout, *wsin, *wsout, *meanb, *seq, *att2;
    cudaGetSymbolAddress((void**)&hidA,  g_hidA);
    cudaGetSymbolAddress((void**)&wmin,  g_wmin);
    cudaGetSymbolAddress((void**)&wmout, g_wmout);
    cudaGetSymbolAddress((void**)&wsin,  g_wsin);
    cudaGetSymbolAddress((void**)&wsout, g_wsout);
    cudaGetSymbolAddress((void**)&meanb, g_mean);
    cudaGetSymbolAddress((void**)&seq,   g_seq);
    cudaGetSymbolAddress((void**)&att2,  g_att2);

    cudaFuncSetAttribute(conv_all,
        cudaFuncAttributeMaxDynamicSharedMemorySize, CONV_SMEM);
    cudaFuncSetAttribute((tgemm2<3, 384, 384>),
        cudaFuncAttributeMaxDynamicSharedMemorySize, GSMEM_T384);
    cudaFuncSetAttribute((tgemm2<4, 384, 384>),
        cudaFuncAttributeMaxDynamicSharedMemorySize, GSMEM_T384);
    cudaFuncSetAttribute((tgemm2<1, 256, 256>),
        cudaFuncAttributeMaxDynamicSharedMemorySize, GSMEM_T256);
    cudaFuncSetAttribute((tgemm2<2, 256, 256>),
        cudaFuncAttributeMaxDynamicSharedMemorySize, GSMEM_T256);

    // ---- unified prepass: gather + fragment-order + fp16-round everything
    conv_all<<<2560, 256, CONV_SMEM>>>(hid, hidA,
                                       mf_in_w, mf_out_w, sf_in_w, sf_out_w,
                                       wmin, wmout, wsin, wsout);

    // Stage A: fused qkv GEMM + L=4 attention + model-mean -> meanb (A-frag)
    tgemm2<3, 384, 384><<<dim3(8, 256), 384, GSMEM_T384>>>(
        hidA, wmin, mf_in_b, nullptr, meanb, 384);
    // Stage A out-proj + transpose to [B,S,H] + pos_enc   -> seq (A-frag)
    tgemm2<1, 256, 256><<<dim3(4, 64), 256, GSMEM_T256>>>(
        meanb, wmout, mf_out_b, pos_enc, seq, 1024);
    // Stage B: fused qkv GEMM + TENSORIZED L=64 attention -> att2 (A-frag)
    tgemm2<4, 384, 384><<<dim3(8, 64), 384, GSMEM_T384>>>(
        seq, wsin, sf_in_b, nullptr, att2, 384);
    // Stage B out-proj + transpose to [S,B,1,H]           -> d_out (float)
    tgemm2<2, 256, 256><<<dim3(4, 64), 256, GSMEM_T256>>>(
        att2, wsout, sf_out_b, nullptr, out, 1024);
}